// round 2
// baseline (speedup 1.0000x reference)
#include <cuda_runtime.h>

namespace {
constexpr int B = 8;
constexpr int N = 2048;
constexpr int D = 128;
constexpr float NEGV = -9.0e15f;
}

// Scratch (static device globals; no runtime allocation).
__device__ float g_Wt[D * D];                 // W^T
__device__ float g_h[B * N * D];              // h = xW^T + b
__device__ float g_hA[B * N * D];             // hA = h A
__device__ float g_hp[B * N * D];             // relu(att @ h)
__device__ float g_E[(size_t)B * N * N];      // E = hA h^T
__device__ float g_T[(size_t)B * N * N];      // masked transposed logits -> probs

// ---------------------------------------------------------------------------
// 128x128 transpose of W_w (once, tiny).
__global__ void transpose_k(const float* __restrict__ W, float* __restrict__ Wt) {
    __shared__ float t[32][33];
    const int bx = blockIdx.x, by = blockIdx.y;
    const int x = bx * 32 + threadIdx.x;
    const int y0 = by * 32;
    for (int i = threadIdx.y; i < 32; i += 8)
        t[i][threadIdx.x] = W[(y0 + i) * D + x];
    __syncthreads();
    const int xo = by * 32 + threadIdx.x;
    const int yo0 = bx * 32;
    for (int i = threadIdx.y; i < 32; i += 8)
        Wt[(yo0 + i) * D + xo] = t[threadIdx.x][i];
}

// ---------------------------------------------------------------------------
// C[r][c] = sum_k X[r][k] * M[k][c] (+ bias[c]).  X: [B*N, D], M: [D, D].
// Block: 32 rows x 128 cols, 256 threads, K-step 32.
__global__ void __launch_bounds__(256) gemm_rows_k(
    const float* __restrict__ X, const float* __restrict__ M,
    const float* __restrict__ bias, float* __restrict__ C) {
    __shared__ float sM[32][D + 1];
    __shared__ float sX[32][33];
    const int row0 = blockIdx.x * 32;
    const int tid = threadIdx.x;
    const int tc = tid & 15;
    const int tr = tid >> 4;
    float acc[2][8];
#pragma unroll
    for (int a = 0; a < 2; a++)
#pragma unroll
        for (int c = 0; c < 8; c++) acc[a][c] = 0.0f;

    for (int k0 = 0; k0 < D; k0 += 32) {
#pragma unroll
        for (int i = tid; i < 32 * D; i += 256) {
            int kk = i >> 7, cc = i & 127;
            sM[kk][cc] = M[(k0 + kk) * D + cc];
        }
#pragma unroll
        for (int i = tid; i < 32 * 32; i += 256) {
            int r = i >> 5, kk = i & 31;
            sX[r][kk] = X[(size_t)(row0 + r) * D + k0 + kk];
        }
        __syncthreads();
#pragma unroll 8
        for (int kk = 0; kk < 32; kk++) {
            float x0 = sX[tr][kk];
            float x1 = sX[tr + 16][kk];
#pragma unroll
            for (int c = 0; c < 8; c++) {
                float mv = sM[kk][tc + c * 16];
                acc[0][c] += x0 * mv;
                acc[1][c] += x1 * mv;
            }
        }
        __syncthreads();
    }
#pragma unroll
    for (int a = 0; a < 2; a++) {
        int r = row0 + tr + a * 16;
#pragma unroll
        for (int c = 0; c < 8; c++) {
            int col = tc + c * 16;
            float v = acc[a][c];
            if (bias) v += bias[col];
            C[(size_t)r * D + col] = v;
        }
    }
}

// ---------------------------------------------------------------------------
// E[b][j][k] = sum_l hA[b][j][l] * h[b][k][l].  Tile 128(j) x 64(k), K-step 32.
__global__ void __launch_bounds__(256) e_gemm_k(
    const float* __restrict__ hA, const float* __restrict__ h,
    float* __restrict__ E) {
    __shared__ float sA[128][33];
    __shared__ float sB[64][33];
    const int b = blockIdx.z;
    const int j0 = blockIdx.y * 128;
    const int k0 = blockIdx.x * 64;
    const int tid = threadIdx.x;
    const int tj = tid >> 4, tk = tid & 15;
    const float* Ab = hA + (size_t)b * N * D;
    const float* Hb = h + (size_t)b * N * D;
    float acc[8][4];
#pragma unroll
    for (int a = 0; a < 8; a++)
#pragma unroll
        for (int c = 0; c < 4; c++) acc[a][c] = 0.0f;

    for (int l0 = 0; l0 < D; l0 += 32) {
#pragma unroll
        for (int i = tid; i < 128 * 32; i += 256) {
            int r = i >> 5, ll = i & 31;
            sA[r][ll] = Ab[(size_t)(j0 + r) * D + l0 + ll];
        }
#pragma unroll
        for (int i = tid; i < 64 * 32; i += 256) {
            int r = i >> 5, ll = i & 31;
            sB[r][ll] = Hb[(size_t)(k0 + r) * D + l0 + ll];
        }
        __syncthreads();
#pragma unroll 8
        for (int ll = 0; ll < 32; ll++) {
            float ra[8], rb[4];
#pragma unroll
            for (int a = 0; a < 8; a++) ra[a] = sA[tj + a * 16][ll];
#pragma unroll
            for (int c = 0; c < 4; c++) rb[c] = sB[tk + c * 16][ll];
#pragma unroll
            for (int a = 0; a < 8; a++)
#pragma unroll
                for (int c = 0; c < 4; c++) acc[a][c] += ra[a] * rb[c];
        }
        __syncthreads();
    }
    float* Eb = E + (size_t)b * N * N;
#pragma unroll
    for (int a = 0; a < 8; a++) {
        size_t ro = (size_t)(j0 + tj + a * 16) * N;
#pragma unroll
        for (int c = 0; c < 4; c++)
            Eb[ro + k0 + tk + c * 16] = acc[a][c];
    }
}

// ---------------------------------------------------------------------------
// T[b][k][j] = adj[b][j][k] > 0 ? E[b][j][k] + E[b][k][j] : NEG
// (transposed layout so the axis=1 softmax is a contiguous row softmax)
__global__ void __launch_bounds__(256) symmask_k(
    const float* __restrict__ E, const float* __restrict__ adj,
    float* __restrict__ T) {
    __shared__ float sE2[32][33];    // E[k][j]
    __shared__ float sE1t[32][33];   // E[j][k] transposed -> [k][j]
    __shared__ float sAdjt[32][33];  // adj[j][k] transposed -> [k][j]
    const int b = blockIdx.z;
    const int j0 = blockIdx.x * 32;
    const int k0 = blockIdx.y * 32;
    const float* Eb = E + (size_t)b * N * N;
    const float* Ab = adj + (size_t)b * N * N;
    float* Tb = T + (size_t)b * N * N;
    const int tid = threadIdx.x;
#pragma unroll
    for (int i = tid; i < 1024; i += 256) {
        int r = i >> 5, c = i & 31;
        sE2[r][c] = Eb[(size_t)(k0 + r) * N + j0 + c];
        sE1t[c][r] = Eb[(size_t)(j0 + r) * N + k0 + c];
        sAdjt[c][r] = Ab[(size_t)(j0 + r) * N + k0 + c];
    }
    __syncthreads();
#pragma unroll
    for (int i = tid; i < 1024; i += 256) {
        int kk = i >> 5, jj = i & 31;
        float v = (sAdjt[kk][jj] > 0.0f) ? (sE1t[kk][jj] + sE2[kk][jj]) : NEGV;
        Tb[(size_t)(k0 + kk) * N + j0 + jj] = v;
    }
}

// ---------------------------------------------------------------------------
// In-place row softmax over T rows (each row is one original column k).
__global__ void __launch_bounds__(256) softmax_k(float* __restrict__ T) {
    __shared__ float row[N];
    __shared__ float redm[8];
    __shared__ float reds[8];
    const int tid = threadIdx.x;
    const int lane = tid & 31, wid = tid >> 5;
    float* Tr = T + (size_t)blockIdx.x * N;

    float m = -3.4e38f;
    for (int i = tid; i < N; i += 256) {
        float v = Tr[i];
        row[i] = v;
        m = fmaxf(m, v);
    }
#pragma unroll
    for (int o = 16; o > 0; o >>= 1) m = fmaxf(m, __shfl_xor_sync(0xffffffffu, m, o));
    if (lane == 0) redm[wid] = m;
    __syncthreads();
    if (tid == 0) {
        float t = redm[0];
#pragma unroll
        for (int i = 1; i < 8; i++) t = fmaxf(t, redm[i]);
        redm[0] = t;
    }
    __syncthreads();
    m = redm[0];

    float s = 0.0f;
    for (int i = tid; i < N; i += 256) {
        float e = __expf(row[i] - m);   // masked (NEG) entries -> exactly 0
        row[i] = e;
        s += e;
    }
#pragma unroll
    for (int o = 16; o > 0; o >>= 1) s += __shfl_xor_sync(0xffffffffu, s, o);
    if (lane == 0) reds[wid] = s;
    __syncthreads();
    if (tid == 0) {
        float t = 0.0f;
#pragma unroll
        for (int i = 0; i < 8; i++) t += reds[i];
        reds[0] = t;
    }
    __syncthreads();
    const float inv = 1.0f / reds[0];
    for (int i = tid; i < N; i += 256) Tr[i] = row[i] * inv;
}

// ---------------------------------------------------------------------------
// hp[b][i][d] = relu( sum_j T[b][j][i] * h[b][j][d] )   (A^T * B GEMM)
// Tile: 64(i) x 128(d), K-step 32 over j.
__global__ void __launch_bounds__(256) hprime_k(
    const float* __restrict__ T, const float* __restrict__ h,
    float* __restrict__ hp) {
    __shared__ float sT[32][65];
    __shared__ float sH[32][129];
    const int b = blockIdx.y;
    const int i0 = blockIdx.x * 64;
    const int tid = threadIdx.x;
    const int ti = tid >> 4, td = tid & 15;
    const float* Tb = T + (size_t)b * N * N;
    const float* Hb = h + (size_t)b * N * D;
    float acc[4][8];
#pragma unroll
    for (int a = 0; a < 4; a++)
#pragma unroll
        for (int c = 0; c < 8; c++) acc[a][c] = 0.0f;

    for (int j0 = 0; j0 < N; j0 += 32) {
#pragma unroll
        for (int i = tid; i < 32 * 64; i += 256) {
            int jj = i >> 6, ii = i & 63;
            sT[jj][ii] = Tb[(size_t)(j0 + jj) * N + i0 + ii];
        }
#pragma unroll
        for (int i = tid; i < 32 * 128; i += 256) {
            int jj = i >> 7, dd = i & 127;
            sH[jj][dd] = Hb[(size_t)(j0 + jj) * D + dd];
        }
        __syncthreads();
#pragma unroll 8
        for (int jj = 0; jj < 32; jj++) {
            float ra[4], rb[8];
#pragma unroll
            for (int a = 0; a < 4; a++) ra[a] = sT[jj][ti + a * 16];
#pragma unroll
            for (int c = 0; c < 8; c++) rb[c] = sH[jj][td + c * 16];
#pragma unroll
            for (int a = 0; a < 4; a++)
#pragma unroll
                for (int c = 0; c < 8; c++) acc[a][c] += ra[a] * rb[c];
        }
        __syncthreads();
    }
#pragma unroll
    for (int a = 0; a < 4; a++) {
        size_t ro = ((size_t)b * N + i0 + ti + a * 16) * D;
#pragma unroll
        for (int c = 0; c < 8; c++)
            hp[ro + td + c * 16] = fmaxf(acc[a][c], 0.0f);
    }
}

// ---------------------------------------------------------------------------
// Gate + output.  One warp per row.
__global__ void __launch_bounds__(256) gate_k(
    const float* __restrict__ x, const float* __restrict__ hp,
    const float* __restrict__ gw, const float* __restrict__ gb,
    float* __restrict__ out) {
    const int lane = threadIdx.x & 31;
    const size_t row = (size_t)blockIdx.x * 8 + (threadIdx.x >> 5);
    const float4 xv = reinterpret_cast<const float4*>(x + row * D)[lane];
    const float4 hv = reinterpret_cast<const float4*>(hp + row * D)[lane];
    const float4 g1 = reinterpret_cast<const float4*>(gw)[lane];
    const float4 g2 = reinterpret_cast<const float4*>(gw + D)[lane];
    float p = xv.x * g1.x + xv.y * g1.y + xv.z * g1.z + xv.w * g1.w
            + hv.x * g2.x + hv.y * g2.y + hv.z * g2.z + hv.w * g2.w;
#pragma unroll
    for (int o = 16; o > 0; o >>= 1) p += __shfl_xor_sync(0xffffffffu, p, o);
    const float c = 1.0f / (1.0f + __expf(-(p + gb[0])));
    const float d1 = 1.0f - c;
    float4 o4;
    o4.x = c * xv.x + d1 * hv.x;
    o4.y = c * xv.y + d1 * hv.y;
    o4.z = c * xv.z + d1 * hv.z;
    o4.w = c * xv.w + d1 * hv.w;
    reinterpret_cast<float4*>(out + row * D)[lane] = o4;
}

// ---------------------------------------------------------------------------
extern "C" void kernel_launch(void* const* d_in, const int* in_sizes, int n_in,
                              void* d_out, int out_size) {
    const float* x   = (const float*)d_in[0];
    const float* adj = (const float*)d_in[1];
    const float* W_w = (const float*)d_in[2];
    const float* W_b = (const float*)d_in[3];
    const float* A   = (const float*)d_in[4];
    const float* gw  = (const float*)d_in[5];
    const float* gb  = (const float*)d_in[6];
    float* out = (float*)d_out;

    float *pWt, *ph, *phA, *php, *pE, *pT;
    cudaGetSymbolAddress((void**)&pWt, g_Wt);
    cudaGetSymbolAddress((void**)&ph,  g_h);
    cudaGetSymbolAddress((void**)&phA, g_hA);
    cudaGetSymbolAddress((void**)&php, g_hp);
    cudaGetSymbolAddress((void**)&pE,  g_E);
    cudaGetSymbolAddress((void**)&pT,  g_T);

    transpose_k<<<dim3(4, 4), dim3(32, 8)>>>(W_w, pWt);
    gemm_rows_k<<<(B * N) / 32, 256>>>(x, pWt, W_b, ph);
    gemm_rows_k<<<(B * N) / 32, 256>>>(ph, A, nullptr, phA);
    e_gemm_k<<<dim3(N / 64, N / 128, B), 256>>>(phA, ph, pE);
    symmask_k<<<dim3(N / 32, N / 32, B), 256>>>(pE, adj, pT);
    softmax_k<<<B * N, 256>>>(pT);
    hprime_k<<<dim3(N / 64, B), 256>>>(pT, ph, php);
    gate_k<<<(B * N) / 8, 256>>>(x, php, gw, gb, out);
}

// round 4
// speedup vs baseline: 1.4474x; 1.4474x over previous
#include <cuda_runtime.h>
#include <cuda_bf16.h>
#include <cstdint>

namespace {
constexpr int B = 8;
constexpr int N = 2048;
constexpr int D = 128;
constexpr float NEGV = -9.0e15f;
constexpr int LDS = 72;                    // padded smem row (bf16 elems)
constexpr int TILE_E = 128 * LDS;          // 9216 elems = 18432 B
constexpr int SMEM_GEMM = 4 * TILE_E * 2;  // 73728 B (double buffer, A+B)
constexpr int SMEM_ESYM = 3 * 128 * 129 * 4;  // 198144 B epilogue (sD, sA1, sA2)
}

// ---------------------------------------------------------------------------
// Scratch (static device globals; no runtime allocation).
__device__ float g_Wt[D * D];
__device__ float g_h[B * N * D];
__device__ float g_hA[B * N * D];
__device__ float g_hp[B * N * D];
__device__ float g_m[B * N];
__device__ float g_is[B * N];
__device__ float g_T[(size_t)B * N * N];
__device__ __nv_bfloat16 g_hh[B * N * D];    // split of h, row-major
__device__ __nv_bfloat16 g_hl[B * N * D];
__device__ __nv_bfloat16 g_hAh[B * N * D];   // split of hA, row-major
__device__ __nv_bfloat16 g_hAl[B * N * D];
__device__ __nv_bfloat16 g_hTh[B * D * N];   // split of h, d-major (transposed)
__device__ __nv_bfloat16 g_hTl[B * D * N];
__device__ __nv_bfloat16 g_Ph[(size_t)B * N * N];
__device__ __nv_bfloat16 g_Pl[(size_t)B * N * N];

// ---------------------------------------------------------------------------
__device__ __forceinline__ uint32_t smem_u32(const void* p) {
    uint32_t a;
    asm("{ .reg .u64 t; cvta.to.shared.u64 t, %1; cvt.u32.u64 %0, t; }" : "=r"(a) : "l"(p));
    return a;
}

// Load one 128x64 bf16 tile into registers (4 x uint4 per thread, coalesced).
__device__ __forceinline__ void load4(const __nv_bfloat16* __restrict__ base,
                                      size_t row0, int stride, int koff,
                                      int tid, uint4* r) {
#pragma unroll
    for (int t = 0; t < 4; t++) {
        const int i = t * 256 + tid;
        const int rr = i >> 3, c16 = i & 7;
        const uint4* p = (const uint4*)(base + (row0 + rr) * (size_t)stride + koff);
        r[t] = p[c16];
    }
}
__device__ __forceinline__ void store4(__nv_bfloat16* sA, int tid, const uint4* r) {
#pragma unroll
    for (int t = 0; t < 4; t++) {
        const int i = t * 256 + tid;
        const int rr = i >> 3, c16 = i & 7;
        *(uint4*)(sA + rr * LDS + c16 * 8) = r[t];
    }
}

// One 64-wide K block of m16n8k16 bf16 MMAs. Warp tile: 64(m) x 32(n).
__device__ __forceinline__ void mma_kblock(uint32_t sAb, uint32_t sBb,
                                           int wr, int wc, int lane,
                                           float (&acc)[4][4][4]) {
#pragma unroll
    for (int kk = 0; kk < 4; kk++) {
        uint32_t a[4][4], bb[4][2];
#pragma unroll
        for (int mi = 0; mi < 4; mi++) {
            const uint32_t addr = sAb +
                ((wr * 64 + mi * 16 + (lane & 15)) * LDS + kk * 16 + ((lane >> 4) << 3)) * 2;
            asm volatile("ldmatrix.sync.aligned.m8n8.x4.shared.b16 {%0,%1,%2,%3}, [%4];"
                         : "=r"(a[mi][0]), "=r"(a[mi][1]), "=r"(a[mi][2]), "=r"(a[mi][3])
                         : "r"(addr));
        }
#pragma unroll
        for (int ni = 0; ni < 4; ni++) {
            const uint32_t addr = sBb +
                ((wc * 32 + ni * 8 + (lane & 7)) * LDS + kk * 16 + (((lane >> 3) & 1) << 3)) * 2;
            asm volatile("ldmatrix.sync.aligned.m8n8.x2.shared.b16 {%0,%1}, [%2];"
                         : "=r"(bb[ni][0]), "=r"(bb[ni][1]) : "r"(addr));
        }
#pragma unroll
        for (int mi = 0; mi < 4; mi++)
#pragma unroll
            for (int ni = 0; ni < 4; ni++)
                asm volatile(
                    "mma.sync.aligned.m16n8k16.row.col.f32.bf16.bf16.f32 "
                    "{%0,%1,%2,%3}, {%4,%5,%6,%7}, {%8,%9}, {%0,%1,%2,%3};"
                    : "+f"(acc[mi][ni][0]), "+f"(acc[mi][ni][1]),
                      "+f"(acc[mi][ni][2]), "+f"(acc[mi][ni][3])
                    : "r"(a[mi][0]), "r"(a[mi][1]), "r"(a[mi][2]), "r"(a[mi][3]),
                      "r"(bb[ni][0]), "r"(bb[ni][1]));
    }
}

// Write warp accumulators into a 128x129 fp32 smem tile.
__device__ __forceinline__ void acc_to_smem(float* sD, int wr, int wc, int lane,
                                            const float (&acc)[4][4][4]) {
#pragma unroll
    for (int mi = 0; mi < 4; mi++)
#pragma unroll
        for (int ni = 0; ni < 4; ni++) {
            const int row = wr * 64 + mi * 16 + (lane >> 2);
            const int col = wc * 32 + ni * 8 + (lane & 3) * 2;
            sD[row * 129 + col]       = acc[mi][ni][0];
            sD[row * 129 + col + 1]   = acc[mi][ni][1];
            sD[(row + 8) * 129 + col]     = acc[mi][ni][2];
            sD[(row + 8) * 129 + col + 1] = acc[mi][ni][3];
        }
}

// ---------------------------------------------------------------------------
__global__ void transpose_k(const float* __restrict__ W, float* __restrict__ Wt) {
    __shared__ float t[32][33];
    const int x = blockIdx.x * 32 + threadIdx.x;
    const int y0 = blockIdx.y * 32;
    for (int i = threadIdx.y; i < 32; i += 8) t[i][threadIdx.x] = W[(y0 + i) * D + x];
    __syncthreads();
    const int xo = blockIdx.y * 32 + threadIdx.x;
    const int yo0 = blockIdx.x * 32;
    for (int i = threadIdx.y; i < 32; i += 8) Wt[(yo0 + i) * D + xo] = t[threadIdx.x][i];
}

// C[r][c] = sum_k X[r][k] * M[k][c] (+ bias[c]).
__global__ void __launch_bounds__(256) gemm_rows_k(
    const float* __restrict__ X, const float* __restrict__ M,
    const float* __restrict__ bias, float* __restrict__ C) {
    __shared__ float sM[32][D + 1];
    __shared__ float sX[32][33];
    const int row0 = blockIdx.x * 32;
    const int tid = threadIdx.x;
    const int tc = tid & 15, tr = tid >> 4;
    float acc[2][8];
#pragma unroll
    for (int a = 0; a < 2; a++)
#pragma unroll
        for (int c = 0; c < 8; c++) acc[a][c] = 0.0f;
    for (int k0 = 0; k0 < D; k0 += 32) {
#pragma unroll
        for (int i = tid; i < 32 * D; i += 256)
            sM[i >> 7][i & 127] = M[(k0 + (i >> 7)) * D + (i & 127)];
#pragma unroll
        for (int i = tid; i < 1024; i += 256)
            sX[i >> 5][i & 31] = X[(size_t)(row0 + (i >> 5)) * D + k0 + (i & 31)];
        __syncthreads();
#pragma unroll 8
        for (int kk = 0; kk < 32; kk++) {
            float x0 = sX[tr][kk], x1 = sX[tr + 16][kk];
#pragma unroll
            for (int c = 0; c < 8; c++) {
                float mv = sM[kk][tc + c * 16];
                acc[0][c] += x0 * mv;
                acc[1][c] += x1 * mv;
            }
        }
        __syncthreads();
    }
#pragma unroll
    for (int a = 0; a < 2; a++)
#pragma unroll
        for (int c = 0; c < 8; c++) {
            float v = acc[a][c];
            if (bias) v += bias[tc + c * 16];
            C[(size_t)(row0 + tr + a * 16) * D + tc + c * 16] = v;
        }
}

// ---------------------------------------------------------------------------
// bf16 hi/lo split of h and hA (row-major).
__global__ void __launch_bounds__(256) prep_split_k() {
    const int i = blockIdx.x * 256 + threadIdx.x;  // over B*N*D
    float v = g_h[i];
    __nv_bfloat16 hi = __float2bfloat16_rn(v);
    g_hh[i] = hi;
    g_hl[i] = __float2bfloat16_rn(v - __bfloat162float(hi));
    v = g_hA[i];
    hi = __float2bfloat16_rn(v);
    g_hAh[i] = hi;
    g_hAl[i] = __float2bfloat16_rn(v - __bfloat162float(hi));
}

// hT_hi/lo[b][d][n] = split(h[b][n][d])
__global__ void __launch_bounds__(256) htr_split_k() {
    __shared__ float t[32][33];
    const int b = blockIdx.z;
    const int n0 = blockIdx.x * 32, d0 = blockIdx.y * 32;
    const int tx = threadIdx.x & 31, ty = threadIdx.x >> 5;
    for (int r = ty; r < 32; r += 8)
        t[r][tx] = g_h[((size_t)b * N + n0 + r) * D + d0 + tx];
    __syncthreads();
    for (int r = ty; r < 32; r += 8) {
        const float v = t[tx][r];
        const __nv_bfloat16 hi = __float2bfloat16_rn(v);
        const size_t o = ((size_t)b * D + d0 + r) * N + n0 + tx;
        g_hTh[o] = hi;
        g_hTl[o] = __float2bfloat16_rn(v - __bfloat162float(hi));
    }
}

// ---------------------------------------------------------------------------
// Esym = u.v^T over upper-triangle 128x128 tile pairs; bf16 3-pass split.
// u = [hA, h], v = [h, hA]. Epilogue: mask with adj, write both T orientations.
__global__ void __launch_bounds__(256) esym_k(const float* __restrict__ adj,
                                              float* __restrict__ T) {
    extern __shared__ char sm[];
    const uint32_t sbase = smem_u32(sm);
    __nv_bfloat16* sb = (__nv_bfloat16*)sm;
    const int tid = threadIdx.x, wid = tid >> 5, lane = tid & 31;
    const int wr = wid >> 2, wc = wid & 3;

    int t = blockIdx.x % 136;
    const int b = blockIdx.x / 136;
    int tj = 0;
    while (t >= 16 - tj) { t -= 16 - tj; tj++; }
    const int tk = tj + t;
    const int j0 = tj * 128, k0 = tk * 128;
    const size_t arow = (size_t)b * N + j0, brow = (size_t)b * N + k0;

    float acc[4][4][4];
#pragma unroll
    for (int mi = 0; mi < 4; mi++)
#pragma unroll
        for (int ni = 0; ni < 4; ni++)
#pragma unroll
            for (int q = 0; q < 4; q++) acc[mi][ni][q] = 0.0f;

    // 12 chunks of K=64: seg = c>>2 (pass 0: uh*vh, 1: ul*vh, 2: uh*vl);
    // kin = (c&3)*64: half 0 -> first operand block, half 1 -> second.
    uint4 ra[4], rb[4];
#pragma unroll 1
    for (int c = 0; c < 12; c++) {
        if (c == 0) {
            const __nv_bfloat16* ap = g_hAh;  // seg0, half0: u = hA (hi)
            const __nv_bfloat16* bp = g_hh;   // seg0, half0: v = h  (hi)
            load4(ap, arow, D, 0, tid, ra);
            load4(bp, brow, D, 0, tid, rb);
        }
        const int buf = c & 1;
        __nv_bfloat16* sA = sb + buf * 2 * TILE_E;
        __nv_bfloat16* sB = sA + TILE_E;
        store4(sA, tid, ra);
        store4(sB, tid, rb);
        __syncthreads();
        if (c + 1 < 12) {
            const int cn = c + 1;
            const int seg = cn >> 2;
            const int kin = (cn & 3) * 64;
            const int half = kin >> 7;
            const int koff = kin & 127;
            const __nv_bfloat16* ap =
                (seg == 1) ? (half ? g_hl : g_hAl) : (half ? g_hh : g_hAh);
            const __nv_bfloat16* bp =
                (seg == 2) ? (half ? g_hAl : g_hl) : (half ? g_hAh : g_hh);
            load4(ap, arow, D, koff, tid, ra);
            load4(bp, brow, D, koff, tid, rb);
        }
        mma_kblock(sbase + buf * 2 * TILE_E * 2, sbase + (buf * 2 + 1) * TILE_E * 2,
                   wr, wc, lane, acc);
    }
    __syncthreads();

    // Epilogue: Esym tile -> smem, adj tiles -> smem, masked dual writes.
    float* sD  = (float*)sm;
    float* sA1 = (float*)(sm + 66048);
    float* sA2 = (float*)(sm + 132096);
    acc_to_smem(sD, wr, wc, lane, acc);
    const float* adjb = adj + (size_t)b * N * N;
#pragma unroll 4
    for (int i = tid; i < 16384; i += 256)
        sA1[(i >> 7) * 129 + (i & 127)] = adjb[(size_t)(j0 + (i >> 7)) * N + k0 + (i & 127)];
    if (tj != tk) {
#pragma unroll 4
        for (int i = tid; i < 16384; i += 256)
            sA2[(i >> 7) * 129 + (i & 127)] = adjb[(size_t)(k0 + (i >> 7)) * N + j0 + (i & 127)];
    }
    __syncthreads();

    float* Tb = T + (size_t)b * N * N;
    // T[k0+r][j0+c] = adj[j0+c][k0+r]>0 ? Esym[j0+c][k0+r] : NEG
#pragma unroll 4
    for (int kq = 0; kq < 16; kq++) {
        const int r = wid + 8 * kq;
#pragma unroll
        for (int s = 0; s < 4; s++) {
            const int cc = s * 32 + lane;
            const float v = (sA1[cc * 129 + r] > 0.0f) ? sD[cc * 129 + r] : NEGV;
            Tb[(size_t)(k0 + r) * N + j0 + cc] = v;
        }
    }
    if (tj != tk) {
        // T[j0+r][k0+c] = adj[k0+c][j0+r]>0 ? Esym[j0+r][k0+c] : NEG
#pragma unroll 4
        for (int kq = 0; kq < 16; kq++) {
            const int r = wid + 8 * kq;
#pragma unroll
            for (int s = 0; s < 4; s++) {
                const int cc = s * 32 + lane;
                const float v = (sA2[cc * 129 + r] > 0.0f) ? sD[r * 129 + cc] : NEGV;
                Tb[(size_t)(j0 + r) * N + k0 + cc] = v;
            }
        }
    }
}

// ---------------------------------------------------------------------------
// Row stats of T: m[row], is[row] = 1/sum(exp(v-m)).
__global__ void __launch_bounds__(256) stats_k(const float* __restrict__ T) {
    __shared__ float row[N];
    __shared__ float red[8];
    const int tid = threadIdx.x;
    const int lane = tid & 31, wid = tid >> 5;
    const float* Tr = T + (size_t)blockIdx.x * N;
    float m = -3.4e38f;
    for (int i = tid; i < N; i += 256) {
        const float v = Tr[i];
        row[i] = v;
        m = fmaxf(m, v);
    }
#pragma unroll
    for (int o = 16; o > 0; o >>= 1) m = fmaxf(m, __shfl_xor_sync(0xffffffffu, m, o));
    if (lane == 0) red[wid] = m;
    __syncthreads();
    if (tid == 0) {
        float tt = red[0];
#pragma unroll
        for (int i = 1; i < 8; i++) tt = fmaxf(tt, red[i]);
        red[0] = tt;
    }
    __syncthreads();
    m = red[0];
    __syncthreads();
    float s = 0.0f;
    for (int i = tid; i < N; i += 256) s += __expf(row[i] - m);
#pragma unroll
    for (int o = 16; o > 0; o >>= 1) s += __shfl_xor_sync(0xffffffffu, s, o);
    if (lane == 0) red[wid] = s;
    __syncthreads();
    if (tid == 0) {
        float tt = 0.0f;
#pragma unroll
        for (int i = 0; i < 8; i++) tt += red[i];
        g_m[blockIdx.x] = m;
        g_is[blockIdx.x] = 1.0f / tt;
    }
}

// P[i][j] = exp(T[j][i] - m[j]) * is[j], bf16 split, 32x32 transpose tiles.
__global__ void __launch_bounds__(256) pbuild_k(const float* __restrict__ T) {
    __shared__ float sT[32][33];
    __shared__ float sm_[32], si_[32];
    const int b = blockIdx.z;
    const int i0 = blockIdx.x * 32, j0 = blockIdx.y * 32;
    const int tid = threadIdx.x;
    const float* Tb = T + (size_t)b * N * N;
#pragma unroll
    for (int i = tid; i < 1024; i += 256)
        sT[i >> 5][i & 31] = Tb[(size_t)(j0 + (i >> 5)) * N + i0 + (i & 31)];
    if (tid < 32) {
        sm_[tid] = g_m[b * N + j0 + tid];
        si_[tid] = g_is[b * N + j0 + tid];
    }
    __syncthreads();
    const size_t base = (size_t)b * N * N;
#pragma unroll
    for (int i = tid; i < 1024; i += 256) {
        const int r = i >> 5, c = i & 31;
        const float v = __expf(sT[c][r] - sm_[c]) * si_[c];
        const __nv_bfloat16 hi = __float2bfloat16_rn(v);
        const size_t o = base + (size_t)(i0 + r) * N + j0 + c;
        g_Ph[o] = hi;
        g_Pl[o] = __float2bfloat16_rn(v - __bfloat162float(hi));
    }
}

// ---------------------------------------------------------------------------
// hp = relu(P @ h): M=128(i) x N=128(d), K=6144 = 3 passes of 2048.
__global__ void __launch_bounds__(256) hp_k() {
    extern __shared__ char sm[];
    const uint32_t sbase = smem_u32(sm);
    __nv_bfloat16* sb = (__nv_bfloat16*)sm;
    const int tid = threadIdx.x, wid = tid >> 5, lane = tid & 31;
    const int wr = wid >> 2, wc = wid & 3;
    const int b = blockIdx.y;
    const int i0 = blockIdx.x * 128;
    const size_t arow = (size_t)b * N + i0;
    const size_t brow = (size_t)b * D;

    float acc[4][4][4];
#pragma unroll
    for (int mi = 0; mi < 4; mi++)
#pragma unroll
        for (int ni = 0; ni < 4; ni++)
#pragma unroll
            for (int q = 0; q < 4; q++) acc[mi][ni][q] = 0.0f;

    uint4 ra[4], rb[4];
#pragma unroll 1
    for (int c = 0; c < 96; c++) {
        if (c == 0) {
            load4(g_Ph, arow, N, 0, tid, ra);
            load4(g_hTh, brow, N, 0, tid, rb);
        }
        const int buf = c & 1;
        __nv_bfloat16* sA = sb + buf * 2 * TILE_E;
        __nv_bfloat16* sB = sA + TILE_E;
        store4(sA, tid, ra);
        store4(sB, tid, rb);
        __syncthreads();
        if (c + 1 < 96) {
            const int cn = c + 1;
            const int seg = cn >> 5;
            const int koff = (cn & 31) * 64;
            const __nv_bfloat16* ap = (seg == 1) ? g_Pl : g_Ph;
            const __nv_bfloat16* bp = (seg == 2) ? g_hTl : g_hTh;
            load4(ap, arow, N, koff, tid, ra);
            load4(bp, brow, N, koff, tid, rb);
        }
        mma_kblock(sbase + buf * 2 * TILE_E * 2, sbase + (buf * 2 + 1) * TILE_E * 2,
                   wr, wc, lane, acc);
    }
    __syncthreads();

    float* sD = (float*)sm;
    acc_to_smem(sD, wr, wc, lane, acc);
    __syncthreads();
#pragma unroll 4
    for (int i = tid; i < 16384; i += 256) {
        const int r = i >> 7, cd = i & 127;
        g_hp[((size_t)b * N + i0 + r) * D + cd] = fmaxf(sD[r * 129 + cd], 0.0f);
    }
}

// ---------------------------------------------------------------------------
__global__ void __launch_bounds__(256) gate_k(
    const float* __restrict__ x, const float* __restrict__ hp,
    const float* __restrict__ gw, const float* __restrict__ gb,
    float* __restrict__ out) {
    const int lane = threadIdx.x & 31;
    const size_t row = (size_t)blockIdx.x * 8 + (threadIdx.x >> 5);
    const float4 xv = reinterpret_cast<const float4*>(x + row * D)[lane];
    const float4 hv = reinterpret_cast<const float4*>(hp + row * D)[lane];
    const float4 g1 = reinterpret_cast<const float4*>(gw)[lane];
    const float4 g2 = reinterpret_cast<const float4*>(gw + D)[lane];
    float p = xv.x * g1.x + xv.y * g1.y + xv.z * g1.z + xv.w * g1.w
            + hv.x * g2.x + hv.y * g2.y + hv.z * g2.z + hv.w * g2.w;
#pragma unroll
    for (int o = 16; o > 0; o >>= 1) p += __shfl_xor_sync(0xffffffffu, p, o);
    const float c = 1.0f / (1.0f + __expf(-(p + gb[0])));
    const float d1 = 1.0f - c;
    float4 o4;
    o4.x = c * xv.x + d1 * hv.x;
    o4.y = c * xv.y + d1 * hv.y;
    o4.z = c * xv.z + d1 * hv.z;
    o4.w = c * xv.w + d1 * hv.w;
    reinterpret_cast<float4*>(out + row * D)[lane] = o4;
}

// ---------------------------------------------------------------------------
extern "C" void kernel_launch(void* const* d_in, const int* in_sizes, int n_in,
                              void* d_out, int out_size) {
    const float* x   = (const float*)d_in[0];
    const float* adj = (const float*)d_in[1];
    const float* W_w = (const float*)d_in[2];
    const float* W_b = (const float*)d_in[3];
    const float* A   = (const float*)d_in[4];
    const float* gw  = (const float*)d_in[5];
    const float* gb  = (const float*)d_in[6];
    float* out = (float*)d_out;

    float *pWt, *ph, *phA, *php, *pT;
    cudaGetSymbolAddress((void**)&pWt, g_Wt);
    cudaGetSymbolAddress((void**)&ph,  g_h);
    cudaGetSymbolAddress((void**)&phA, g_hA);
    cudaGetSymbolAddress((void**)&php, g_hp);
    cudaGetSymbolAddress((void**)&pT,  g_T);

    static bool attr_done = false;
    if (!attr_done) {
        cudaFuncSetAttribute(esym_k, cudaFuncAttributeMaxDynamicSharedMemorySize, SMEM_ESYM);
        cudaFuncSetAttribute(hp_k,   cudaFuncAttributeMaxDynamicSharedMemorySize, SMEM_GEMM);
        attr_done = true;
    }

    transpose_k<<<dim3(4, 4), dim3(32, 8)>>>(W_w, pWt);
    gemm_rows_k<<<(B * N) / 32, 256>>>(x, pWt, W_b, ph);
    gemm_rows_k<<<(B * N) / 32, 256>>>(ph, A, nullptr, phA);
    prep_split_k<<<(B * N * D) / 256, 256>>>();
    htr_split_k<<<dim3(N / 32, D / 32, B), 256>>>();
    esym_k<<<B * 136, 256, SMEM_ESYM>>>(adj, pT);
    stats_k<<<B * N, 256>>>(pT);
    pbuild_k<<<dim3(N / 32, N / 32, B), 256>>>(pT);
    hp_k<<<dim3(N / 128, B), 256, SMEM_GEMM>>>();
    gate_k<<<(B * N) / 8, 256>>>(x, php, gw, gb, out);
}

// round 5
// speedup vs baseline: 1.5977x; 1.1038x over previous
#include <cuda_runtime.h>
#include <cuda_bf16.h>
#include <cstdint>

namespace {
constexpr int B = 8;
constexpr int N = 2048;
constexpr int D = 128;
constexpr float NEGV = -9.0e15f;
constexpr int LDS = 72;                      // padded smem row (bf16 elems)
constexpr int TILE_B = 128 * LDS * 2;        // 18432 bytes per operand tile
constexpr int SMEM_ESYM = 3 * 128 * 129 * 4; // 198144 epilogue (>= 4-stage 147456)
constexpr int SMEM_HP = 4 * 2 * TILE_B;      // 147456 (epilogue 66048 reuses)
}

// ---------------------------------------------------------------------------
// Scratch (static device globals; no runtime allocation).
__device__ float g_Wt[D * D];
__device__ float g_h[B * N * D];
__device__ float g_hA[B * N * D];
__device__ float g_hp[B * N * D];
__device__ float g_m[B * N];
__device__ float g_is[B * N];
__device__ float g_T[(size_t)B * N * N];
__device__ __nv_bfloat16 g_hh[B * N * D];
__device__ __nv_bfloat16 g_hl[B * N * D];
__device__ __nv_bfloat16 g_hAh[B * N * D];
__device__ __nv_bfloat16 g_hAl[B * N * D];
__device__ __nv_bfloat16 g_hTh[B * D * N];
__device__ __nv_bfloat16 g_hTl[B * D * N];
__device__ __nv_bfloat16 g_Ph[(size_t)B * N * N];
__device__ __nv_bfloat16 g_Pl[(size_t)B * N * N];

// ---------------------------------------------------------------------------
__device__ __forceinline__ uint32_t smem_u32(const void* p) {
    uint32_t a;
    asm("{ .reg .u64 t; cvta.to.shared.u64 t, %1; cvt.u32.u64 %0, t; }" : "=r"(a) : "l"(p));
    return a;
}
__device__ __forceinline__ void cp16(uint32_t dst, const void* src) {
    asm volatile("cp.async.cg.shared.global [%0], [%1], 16;" :: "r"(dst), "l"(src));
}
#define CP_COMMIT() asm volatile("cp.async.commit_group;" ::: "memory")
#define CP_WAIT(n)  asm volatile("cp.async.wait_group %0;" :: "n"(n) : "memory")

// Issue one 128x64 bf16 operand tile via cp.async (4 x 16B per thread).
__device__ __forceinline__ void issue_tile(uint32_t sdst,
                                           const __nv_bfloat16* __restrict__ base,
                                           size_t row0, int stride, int koff, int tid) {
#pragma unroll
    for (int t = 0; t < 4; t++) {
        const int i = t * 256 + tid;
        const int rr = i >> 3, c16 = i & 7;
        cp16(sdst + (uint32_t)(rr * LDS + c16 * 8) * 2,
             base + (row0 + rr) * (size_t)stride + koff + c16 * 8);
    }
}

// One 64-wide K block of m16n8k16 bf16 MMAs. Warp tile: 64(m) x 32(n).
__device__ __forceinline__ void mma_kblock(uint32_t sAb, uint32_t sBb,
                                           int wr, int wc, int lane,
                                           float (&acc)[4][4][4]) {
#pragma unroll
    for (int kk = 0; kk < 4; kk++) {
        uint32_t a[4][4], bb[4][2];
#pragma unroll
        for (int mi = 0; mi < 4; mi++) {
            const uint32_t addr = sAb +
                ((wr * 64 + mi * 16 + (lane & 15)) * LDS + kk * 16 + ((lane >> 4) << 3)) * 2;
            asm volatile("ldmatrix.sync.aligned.m8n8.x4.shared.b16 {%0,%1,%2,%3}, [%4];"
                         : "=r"(a[mi][0]), "=r"(a[mi][1]), "=r"(a[mi][2]), "=r"(a[mi][3])
                         : "r"(addr));
        }
#pragma unroll
        for (int ni = 0; ni < 4; ni++) {
            const uint32_t addr = sBb +
                ((wc * 32 + ni * 8 + (lane & 7)) * LDS + kk * 16 + (((lane >> 3) & 1) << 3)) * 2;
            asm volatile("ldmatrix.sync.aligned.m8n8.x2.shared.b16 {%0,%1}, [%2];"
                         : "=r"(bb[ni][0]), "=r"(bb[ni][1]) : "r"(addr));
        }
#pragma unroll
        for (int mi = 0; mi < 4; mi++)
#pragma unroll
            for (int ni = 0; ni < 4; ni++)
                asm volatile(
                    "mma.sync.aligned.m16n8k16.row.col.f32.bf16.bf16.f32 "
                    "{%0,%1,%2,%3}, {%4,%5,%6,%7}, {%8,%9}, {%0,%1,%2,%3};"
                    : "+f"(acc[mi][ni][0]), "+f"(acc[mi][ni][1]),
                      "+f"(acc[mi][ni][2]), "+f"(acc[mi][ni][3])
                    : "r"(a[mi][0]), "r"(a[mi][1]), "r"(a[mi][2]), "r"(a[mi][3]),
                      "r"(bb[ni][0]), "r"(bb[ni][1]));
    }
}

__device__ __forceinline__ void acc_to_smem(float* sD, int wr, int wc, int lane,
                                            const float (&acc)[4][4][4]) {
#pragma unroll
    for (int mi = 0; mi < 4; mi++)
#pragma unroll
        for (int ni = 0; ni < 4; ni++) {
            const int row = wr * 64 + mi * 16 + (lane >> 2);
            const int col = wc * 32 + ni * 8 + (lane & 3) * 2;
            sD[row * 129 + col]           = acc[mi][ni][0];
            sD[row * 129 + col + 1]       = acc[mi][ni][1];
            sD[(row + 8) * 129 + col]     = acc[mi][ni][2];
            sD[(row + 8) * 129 + col + 1] = acc[mi][ni][3];
        }
}

// ---------------------------------------------------------------------------
__global__ void transpose_k(const float* __restrict__ W, float* __restrict__ Wt) {
    __shared__ float t[32][33];
    const int x = blockIdx.x * 32 + threadIdx.x;
    const int y0 = blockIdx.y * 32;
    for (int i = threadIdx.y; i < 32; i += 8) t[i][threadIdx.x] = W[(y0 + i) * D + x];
    __syncthreads();
    const int xo = blockIdx.y * 32 + threadIdx.x;
    const int yo0 = blockIdx.x * 32;
    for (int i = threadIdx.y; i < 32; i += 8) Wt[(yo0 + i) * D + xo] = t[threadIdx.x][i];
}

__global__ void __launch_bounds__(256) gemm_rows_k(
    const float* __restrict__ X, const float* __restrict__ M,
    const float* __restrict__ bias, float* __restrict__ C) {
    __shared__ float sM[32][D + 1];
    __shared__ float sX[32][33];
    const int row0 = blockIdx.x * 32;
    const int tid = threadIdx.x;
    const int tc = tid & 15, tr = tid >> 4;
    float acc[2][8];
#pragma unroll
    for (int a = 0; a < 2; a++)
#pragma unroll
        for (int c = 0; c < 8; c++) acc[a][c] = 0.0f;
    for (int k0 = 0; k0 < D; k0 += 32) {
#pragma unroll
        for (int i = tid; i < 32 * D; i += 256)
            sM[i >> 7][i & 127] = M[(k0 + (i >> 7)) * D + (i & 127)];
#pragma unroll
        for (int i = tid; i < 1024; i += 256)
            sX[i >> 5][i & 31] = X[(size_t)(row0 + (i >> 5)) * D + k0 + (i & 31)];
        __syncthreads();
#pragma unroll 8
        for (int kk = 0; kk < 32; kk++) {
            float x0 = sX[tr][kk], x1 = sX[tr + 16][kk];
#pragma unroll
            for (int c = 0; c < 8; c++) {
                float mv = sM[kk][tc + c * 16];
                acc[0][c] += x0 * mv;
                acc[1][c] += x1 * mv;
            }
        }
        __syncthreads();
    }
#pragma unroll
    for (int a = 0; a < 2; a++)
#pragma unroll
        for (int c = 0; c < 8; c++) {
            float v = acc[a][c];
            if (bias) v += bias[tc + c * 16];
            C[(size_t)(row0 + tr + a * 16) * D + tc + c * 16] = v;
        }
}

// ---------------------------------------------------------------------------
__global__ void __launch_bounds__(256) prep_split_k() {
    const int i = blockIdx.x * 256 + threadIdx.x;
    float v = g_h[i];
    __nv_bfloat16 hi = __float2bfloat16_rn(v);
    g_hh[i] = hi;
    g_hl[i] = __float2bfloat16_rn(v - __bfloat162float(hi));
    v = g_hA[i];
    hi = __float2bfloat16_rn(v);
    g_hAh[i] = hi;
    g_hAl[i] = __float2bfloat16_rn(v - __bfloat162float(hi));
}

__global__ void __launch_bounds__(256) htr_split_k() {
    __shared__ float t[32][33];
    const int b = blockIdx.z;
    const int n0 = blockIdx.x * 32, d0 = blockIdx.y * 32;
    const int tx = threadIdx.x & 31, ty = threadIdx.x >> 5;
    for (int r = ty; r < 32; r += 8)
        t[r][tx] = g_h[((size_t)b * N + n0 + r) * D + d0 + tx];
    __syncthreads();
    for (int r = ty; r < 32; r += 8) {
        const float v = t[tx][r];
        const __nv_bfloat16 hi = __float2bfloat16_rn(v);
        const size_t o = ((size_t)b * D + d0 + r) * N + n0 + tx;
        g_hTh[o] = hi;
        g_hTl[o] = __float2bfloat16_rn(v - __bfloat162float(hi));
    }
}

// ---------------------------------------------------------------------------
// Esym = u.v^T over upper-triangle 128x128 tile pairs; 4-stage cp.async.
__device__ __forceinline__ void esym_issue(int c, int stage, uint32_t sbase,
                                           size_t arow, size_t brow, int tid) {
    const int seg = c >> 2;
    const int kin = (c & 3) * 64;
    const int half = kin >> 7;
    const int koff = kin & 127;
    const __nv_bfloat16* ap = (seg == 1) ? (half ? g_hl : g_hAl) : (half ? g_hh : g_hAh);
    const __nv_bfloat16* bp = (seg == 2) ? (half ? g_hAl : g_hl) : (half ? g_hAh : g_hh);
    const uint32_t sA = sbase + (uint32_t)stage * 2 * TILE_B;
    issue_tile(sA, ap, arow, D, koff, tid);
    issue_tile(sA + TILE_B, bp, brow, D, koff, tid);
    CP_COMMIT();
}

__global__ void __launch_bounds__(256) esym_k(const float* __restrict__ adj,
                                              float* __restrict__ T) {
    extern __shared__ char sm[];
    const uint32_t sbase = smem_u32(sm);
    const int tid = threadIdx.x, wid = tid >> 5, lane = tid & 31;
    const int wr = wid >> 2, wc = wid & 3;

    int t = blockIdx.x % 136;
    const int b = blockIdx.x / 136;
    int tj = 0;
    while (t >= 16 - tj) { t -= 16 - tj; tj++; }
    const int tk = tj + t;
    const int j0 = tj * 128, k0 = tk * 128;
    const size_t arow = (size_t)b * N + j0, brow = (size_t)b * N + k0;

    float acc[4][4][4];
#pragma unroll
    for (int mi = 0; mi < 4; mi++)
#pragma unroll
        for (int ni = 0; ni < 4; ni++)
#pragma unroll
            for (int q = 0; q < 4; q++) acc[mi][ni][q] = 0.0f;

    esym_issue(0, 0, sbase, arow, brow, tid);
    esym_issue(1, 1, sbase, arow, brow, tid);
    esym_issue(2, 2, sbase, arow, brow, tid);
#pragma unroll 1
    for (int c = 0; c < 12; c++) {
        if (c <= 9) CP_WAIT(2);
        else if (c == 10) CP_WAIT(1);
        else CP_WAIT(0);
        __syncthreads();
        if (c + 3 < 12) esym_issue(c + 3, (c + 3) & 3, sbase, arow, brow, tid);
        const uint32_t sA = sbase + (uint32_t)(c & 3) * 2 * TILE_B;
        mma_kblock(sA, sA + TILE_B, wr, wc, lane, acc);
    }
    __syncthreads();

    float* sD  = (float*)sm;
    float* sA1 = (float*)(sm + 66048);
    float* sA2 = (float*)(sm + 132096);
    acc_to_smem(sD, wr, wc, lane, acc);
    const float* adjb = adj + (size_t)b * N * N;
#pragma unroll 4
    for (int i = tid; i < 16384; i += 256)
        sA1[(i >> 7) * 129 + (i & 127)] = adjb[(size_t)(j0 + (i >> 7)) * N + k0 + (i & 127)];
    if (tj != tk) {
#pragma unroll 4
        for (int i = tid; i < 16384; i += 256)
            sA2[(i >> 7) * 129 + (i & 127)] = adjb[(size_t)(k0 + (i >> 7)) * N + j0 + (i & 127)];
    }
    __syncthreads();

    float* Tb = T + (size_t)b * N * N;
#pragma unroll 4
    for (int kq = 0; kq < 16; kq++) {
        const int r = wid + 8 * kq;
#pragma unroll
        for (int s = 0; s < 4; s++) {
            const int cc = s * 32 + lane;
            const float v = (sA1[cc * 129 + r] > 0.0f) ? sD[cc * 129 + r] : NEGV;
            Tb[(size_t)(k0 + r) * N + j0 + cc] = v;
        }
    }
    if (tj != tk) {
#pragma unroll 4
        for (int kq = 0; kq < 16; kq++) {
            const int r = wid + 8 * kq;
#pragma unroll
            for (int s = 0; s < 4; s++) {
                const int cc = s * 32 + lane;
                const float v = (sA2[cc * 129 + r] > 0.0f) ? sD[r * 129 + cc] : NEGV;
                Tb[(size_t)(j0 + r) * N + k0 + cc] = v;
            }
        }
    }
}

// ---------------------------------------------------------------------------
__global__ void __launch_bounds__(256) stats_k(const float* __restrict__ T) {
    __shared__ float row[N];
    __shared__ float red[8];
    const int tid = threadIdx.x;
    const int lane = tid & 31, wid = tid >> 5;
    const float4* Tr4 = (const float4*)(T + (size_t)blockIdx.x * N);
    float4* row4 = (float4*)row;
    float m = -3.4e38f;
#pragma unroll
    for (int i = tid; i < N / 4; i += 256) {
        const float4 v = Tr4[i];
        row4[i] = v;
        m = fmaxf(m, fmaxf(fmaxf(v.x, v.y), fmaxf(v.z, v.w)));
    }
#pragma unroll
    for (int o = 16; o > 0; o >>= 1) m = fmaxf(m, __shfl_xor_sync(0xffffffffu, m, o));
    if (lane == 0) red[wid] = m;
    __syncthreads();
    if (tid == 0) {
        float tt = red[0];
#pragma unroll
        for (int i = 1; i < 8; i++) tt = fmaxf(tt, red[i]);
        red[0] = tt;
    }
    __syncthreads();
    m = red[0];
    __syncthreads();
    float s = 0.0f;
#pragma unroll
    for (int i = tid; i < N / 4; i += 256) {
        const float4 v = row4[i];
        s += __expf(v.x - m) + __expf(v.y - m) + __expf(v.z - m) + __expf(v.w - m);
    }
#pragma unroll
    for (int o = 16; o > 0; o >>= 1) s += __shfl_xor_sync(0xffffffffu, s, o);
    if (lane == 0) red[wid] = s;
    __syncthreads();
    if (tid == 0) {
        float tt = 0.0f;
#pragma unroll
        for (int i = 0; i < 8; i++) tt += red[i];
        g_m[blockIdx.x] = m;
        g_is[blockIdx.x] = 1.0f / tt;
    }
}

// P[i][j] = exp(T[j][i]-m[j])*is[j], bf16 split. 64(i)x64(j) tiles, coalesced
// packed-u32 writes (warp per row).
__global__ void __launch_bounds__(256) pbuild_k(const float* __restrict__ T) {
    __shared__ float sT[64][69];
    __shared__ float sm_[64], si_[64];
    const int b = blockIdx.z;
    const int i0 = blockIdx.x * 64, j0 = blockIdx.y * 64;
    const int tid = threadIdx.x, wid = tid >> 5, lane = tid & 31;
    const float* Tb = T + (size_t)b * N * N;
#pragma unroll
    for (int i = tid; i < 4096; i += 256)
        sT[i >> 6][i & 63] = Tb[(size_t)(j0 + (i >> 6)) * N + i0 + (i & 63)];
    if (tid < 64) {
        sm_[tid] = g_m[b * N + j0 + tid];
        si_[tid] = g_is[b * N + j0 + tid];
    }
    __syncthreads();
    const size_t base = (size_t)b * N * N;
#pragma unroll
    for (int ir = 0; ir < 8; ir++) {
        const int i = wid * 8 + ir;
        const int j = lane * 2;
        const float v0 = __expf(sT[j][i] - sm_[j]) * si_[j];
        const float v1 = __expf(sT[j + 1][i] - sm_[j + 1]) * si_[j + 1];
        const __nv_bfloat16 h0 = __float2bfloat16_rn(v0);
        const __nv_bfloat16 h1 = __float2bfloat16_rn(v1);
        const __nv_bfloat16 l0 = __float2bfloat16_rn(v0 - __bfloat162float(h0));
        const __nv_bfloat16 l1 = __float2bfloat16_rn(v1 - __bfloat162float(h1));
        const size_t o = (base + (size_t)(i0 + i) * N + j0) >> 1;
        uint32_t ph, pl;
        asm("mov.b32 %0, {%1, %2};" : "=r"(ph) : "h"(*(const uint16_t*)&h0), "h"(*(const uint16_t*)&h1));
        asm("mov.b32 %0, {%1, %2};" : "=r"(pl) : "h"(*(const uint16_t*)&l0), "h"(*(const uint16_t*)&l1));
        ((uint32_t*)g_Ph)[o + lane] = ph;
        ((uint32_t*)g_Pl)[o + lane] = pl;
    }
}

// ---------------------------------------------------------------------------
// hp = relu(P @ h): 128(i) x 128(d), K = 96 chunks of 64; 4-stage cp.async.
__device__ __forceinline__ void hp_issue(int c, int stage, uint32_t sbase,
                                         size_t arow, size_t brow, int tid) {
    const int seg = c >> 5;
    const int koff = (c & 31) * 64;
    const __nv_bfloat16* ap = (seg == 1) ? g_Pl : g_Ph;
    const __nv_bfloat16* bp = (seg == 2) ? g_hTl : g_hTh;
    const uint32_t sA = sbase + (uint32_t)stage * 2 * TILE_B;
    issue_tile(sA, ap, arow, N, koff, tid);
    issue_tile(sA + TILE_B, bp, brow, N, koff, tid);
    CP_COMMIT();
}

__global__ void __launch_bounds__(256) hp_k() {
    extern __shared__ char sm[];
    const uint32_t sbase = smem_u32(sm);
    const int tid = threadIdx.x, wid = tid >> 5, lane = tid & 31;
    const int wr = wid >> 2, wc = wid & 3;
    const int b = blockIdx.y;
    const int i0 = blockIdx.x * 128;
    const size_t arow = (size_t)b * N + i0;
    const size_t brow = (size_t)b * D;

    float acc[4][4][4];
#pragma unroll
    for (int mi = 0; mi < 4; mi++)
#pragma unroll
        for (int ni = 0; ni < 4; ni++)
#pragma unroll
            for (int q = 0; q < 4; q++) acc[mi][ni][q] = 0.0f;

    hp_issue(0, 0, sbase, arow, brow, tid);
    hp_issue(1, 1, sbase, arow, brow, tid);
    hp_issue(2, 2, sbase, arow, brow, tid);
#pragma unroll 1
    for (int c = 0; c < 96; c++) {
        if (c <= 93) CP_WAIT(2);
        else if (c == 94) CP_WAIT(1);
        else CP_WAIT(0);
        __syncthreads();
        if (c + 3 < 96) hp_issue(c + 3, (c + 3) & 3, sbase, arow, brow, tid);
        const uint32_t sA = sbase + (uint32_t)(c & 3) * 2 * TILE_B;
        mma_kblock(sA, sA + TILE_B, wr, wc, lane, acc);
    }
    __syncthreads();

    float* sD = (float*)sm;
    acc_to_smem(sD, wr, wc, lane, acc);
    __syncthreads();
#pragma unroll 4
    for (int i = tid; i < 16384; i += 256) {
        const int r = i >> 7, cd = i & 127;
        g_hp[((size_t)b * N + i0 + r) * D + cd] = fmaxf(sD[r * 129 + cd], 0.0f);
    }
}

// ---------------------------------------------------------------------------
__global__ void __launch_bounds__(256) gate_k(
    const float* __restrict__ x, const float* __restrict__ hp,
    const float* __restrict__ gw, const float* __restrict__ gb,
    float* __restrict__ out) {
    const int lane = threadIdx.x & 31;
    const size_t row = (size_t)blockIdx.x * 8 + (threadIdx.x >> 5);
    const float4 xv = reinterpret_cast<const float4*>(x + row * D)[lane];
    const float4 hv = reinterpret_cast<const float4*>(hp + row * D)[lane];
    const float4 g1 = reinterpret_cast<const float4*>(gw)[lane];
    const float4 g2 = reinterpret_cast<const float4*>(gw + D)[lane];
    float p = xv.x * g1.x + xv.y * g1.y + xv.z * g1.z + xv.w * g1.w
            + hv.x * g2.x + hv.y * g2.y + hv.z * g2.z + hv.w * g2.w;
#pragma unroll
    for (int o = 16; o > 0; o >>= 1) p += __shfl_xor_sync(0xffffffffu, p, o);
    const float c = 1.0f / (1.0f + __expf(-(p + gb[0])));
    const float d1 = 1.0f - c;
    float4 o4;
    o4.x = c * xv.x + d1 * hv.x;
    o4.y = c * xv.y + d1 * hv.y;
    o4.z = c * xv.z + d1 * hv.z;
    o4.w = c * xv.w + d1 * hv.w;
    reinterpret_cast<float4*>(out + row * D)[lane] = o4;
}

// ---------------------------------------------------------------------------
extern "C" void kernel_launch(void* const* d_in, const int* in_sizes, int n_in,
                              void* d_out, int out_size) {
    const float* x   = (const float*)d_in[0];
    const float* adj = (const float*)d_in[1];
    const float* W_w = (const float*)d_in[2];
    const float* W_b = (const float*)d_in[3];
    const float* A   = (const float*)d_in[4];
    const float* gw  = (const float*)d_in[5];
    const float* gb  = (const float*)d_in[6];
    float* out = (float*)d_out;

    float *pWt, *ph, *phA, *php, *pT;
    cudaGetSymbolAddress((void**)&pWt, g_Wt);
    cudaGetSymbolAddress((void**)&ph,  g_h);
    cudaGetSymbolAddress((void**)&phA, g_hA);
    cudaGetSymbolAddress((void**)&php, g_hp);
    cudaGetSymbolAddress((void**)&pT,  g_T);

    static bool attr_done = false;
    if (!attr_done) {
        cudaFuncSetAttribute(esym_k, cudaFuncAttributeMaxDynamicSharedMemorySize, SMEM_ESYM);
        cudaFuncSetAttribute(hp_k,   cudaFuncAttributeMaxDynamicSharedMemorySize, SMEM_HP);
        attr_done = true;
    }

    transpose_k<<<dim3(4, 4), dim3(32, 8)>>>(W_w, pWt);
    gemm_rows_k<<<(B * N) / 32, 256>>>(x, pWt, W_b, ph);
    gemm_rows_k<<<(B * N) / 32, 256>>>(ph, A, nullptr, phA);
    prep_split_k<<<(B * N * D) / 256, 256>>>();
    htr_split_k<<<dim3(N / 32, D / 32, B), 256>>>();
    esym_k<<<B * 136, 256, SMEM_ESYM>>>(adj, pT);
    stats_k<<<B * N, 256>>>(pT);
    pbuild_k<<<dim3(N / 64, N / 64, B), 256>>>(pT);
    hp_k<<<dim3(N / 128, B), 256, SMEM_HP>>>();
    gate_k<<<(B * N) / 8, 256>>>(x, php, gw, gb, out);
}

// round 6
// speedup vs baseline: 1.6262x; 1.0179x over previous
#include <cuda_runtime.h>
#include <cuda_bf16.h>
#include <cstdint>

namespace {
constexpr int B = 8;
constexpr int N = 2048;
constexpr int D = 128;
constexpr int LDS = 72;                      // padded smem row (bf16 elems)
constexpr int TILE_B = 128 * LDS * 2;        // 18432 bytes per operand tile
constexpr int SMEM_ESYM = 3 * 128 * 129 * 4; // 198144 epilogue (>= 4-stage 147456)
constexpr int SMEM_HP = 4 * 2 * TILE_B;      // 147456 (epilogue 66048 reuses)
}

// ---------------------------------------------------------------------------
// Scratch (static device globals; no runtime allocation).
__device__ float g_Wt[D * D];
__device__ float g_h[B * N * D];
__device__ float g_hA[B * N * D];
__device__ float g_hp[B * N * D];
__device__ float g_is[B * N];
__device__ float g_part[(size_t)B * N * 32];   // per-(column, row-tile, half) partial sums
__device__ float g_U[(size_t)B * N * N];       // masked exp(e_sym), P-orientation [i][j]
__device__ __nv_bfloat16 g_hh[B * N * D];
__device__ __nv_bfloat16 g_hl[B * N * D];
__device__ __nv_bfloat16 g_hAh[B * N * D];
__device__ __nv_bfloat16 g_hAl[B * N * D];
__device__ __nv_bfloat16 g_hTh[B * D * N];
__device__ __nv_bfloat16 g_hTl[B * D * N];
__device__ __nv_bfloat16 g_Ph[(size_t)B * N * N];
__device__ __nv_bfloat16 g_Pl[(size_t)B * N * N];

// ---------------------------------------------------------------------------
__device__ __forceinline__ uint32_t smem_u32(const void* p) {
    uint32_t a;
    asm("{ .reg .u64 t; cvta.to.shared.u64 t, %1; cvt.u32.u64 %0, t; }" : "=r"(a) : "l"(p));
    return a;
}
__device__ __forceinline__ void cp16(uint32_t dst, const void* src) {
    asm volatile("cp.async.cg.shared.global [%0], [%1], 16;" :: "r"(dst), "l"(src));
}
#define CP_COMMIT() asm volatile("cp.async.commit_group;" ::: "memory")
#define CP_WAIT(n)  asm volatile("cp.async.wait_group %0;" :: "n"(n) : "memory")

// Issue one 128x64 bf16 operand tile via cp.async (4 x 16B per thread).
__device__ __forceinline__ void issue_tile(uint32_t sdst,
                                           const __nv_bfloat16* __restrict__ base,
                                           size_t row0, int stride, int koff, int tid) {
#pragma unroll
    for (int t = 0; t < 4; t++) {
        const int i = t * 256 + tid;
        const int rr = i >> 3, c16 = i & 7;
        cp16(sdst + (uint32_t)(rr * LDS + c16 * 8) * 2,
             base + (row0 + rr) * (size_t)stride + koff + c16 * 8);
    }
}

// One 64-wide K block of m16n8k16 bf16 MMAs. Warp tile: 64(m) x 32(n).
__device__ __forceinline__ void mma_kblock(uint32_t sAb, uint32_t sBb,
                                           int wr, int wc, int lane,
                                           float (&acc)[4][4][4]) {
#pragma unroll
    for (int kk = 0; kk < 4; kk++) {
        uint32_t a[4][4], bb[4][2];
#pragma unroll
        for (int mi = 0; mi < 4; mi++) {
            const uint32_t addr = sAb +
                ((wr * 64 + mi * 16 + (lane & 15)) * LDS + kk * 16 + ((lane >> 4) << 3)) * 2;
            asm volatile("ldmatrix.sync.aligned.m8n8.x4.shared.b16 {%0,%1,%2,%3}, [%4];"
                         : "=r"(a[mi][0]), "=r"(a[mi][1]), "=r"(a[mi][2]), "=r"(a[mi][3])
                         : "r"(addr));
        }
#pragma unroll
        for (int ni = 0; ni < 4; ni++) {
            const uint32_t addr = sBb +
                ((wc * 32 + ni * 8 + (lane & 7)) * LDS + kk * 16 + (((lane >> 3) & 1) << 3)) * 2;
            asm volatile("ldmatrix.sync.aligned.m8n8.x2.shared.b16 {%0,%1}, [%2];"
                         : "=r"(bb[ni][0]), "=r"(bb[ni][1]) : "r"(addr));
        }
#pragma unroll
        for (int mi = 0; mi < 4; mi++)
#pragma unroll
            for (int ni = 0; ni < 4; ni++)
                asm volatile(
                    "mma.sync.aligned.m16n8k16.row.col.f32.bf16.bf16.f32 "
                    "{%0,%1,%2,%3}, {%4,%5,%6,%7}, {%8,%9}, {%0,%1,%2,%3};"
                    : "+f"(acc[mi][ni][0]), "+f"(acc[mi][ni][1]),
                      "+f"(acc[mi][ni][2]), "+f"(acc[mi][ni][3])
                    : "r"(a[mi][0]), "r"(a[mi][1]), "r"(a[mi][2]), "r"(a[mi][3]),
                      "r"(bb[ni][0]), "r"(bb[ni][1]));
    }
}

__device__ __forceinline__ void acc_to_smem(float* sD, int wr, int wc, int lane,
                                            const float (&acc)[4][4][4]) {
#pragma unroll
    for (int mi = 0; mi < 4; mi++)
#pragma unroll
        for (int ni = 0; ni < 4; ni++) {
            const int row = wr * 64 + mi * 16 + (lane >> 2);
            const int col = wc * 32 + ni * 8 + (lane & 3) * 2;
            sD[row * 129 + col]           = acc[mi][ni][0];
            sD[row * 129 + col + 1]       = acc[mi][ni][1];
            sD[(row + 8) * 129 + col]     = acc[mi][ni][2];
            sD[(row + 8) * 129 + col + 1] = acc[mi][ni][3];
        }
}

// ---------------------------------------------------------------------------
__global__ void transpose_k(const float* __restrict__ W, float* __restrict__ Wt) {
    __shared__ float t[32][33];
    const int x = blockIdx.x * 32 + threadIdx.x;
    const int y0 = blockIdx.y * 32;
    for (int i = threadIdx.y; i < 32; i += 8) t[i][threadIdx.x] = W[(y0 + i) * D + x];
    __syncthreads();
    const int xo = blockIdx.y * 32 + threadIdx.x;
    const int yo0 = blockIdx.x * 32;
    for (int i = threadIdx.y; i < 32; i += 8) Wt[(yo0 + i) * D + xo] = t[threadIdx.x][i];
}

__global__ void __launch_bounds__(256) gemm_rows_k(
    const float* __restrict__ X, const float* __restrict__ M,
    const float* __restrict__ bias, float* __restrict__ C) {
    __shared__ float sM[32][D + 1];
    __shared__ float sX[32][33];
    const int row0 = blockIdx.x * 32;
    const int tid = threadIdx.x;
    const int tc = tid & 15, tr = tid >> 4;
    float acc[2][8];
#pragma unroll
    for (int a = 0; a < 2; a++)
#pragma unroll
        for (int c = 0; c < 8; c++) acc[a][c] = 0.0f;
    for (int k0 = 0; k0 < D; k0 += 32) {
#pragma unroll
        for (int i = tid; i < 32 * D; i += 256)
            sM[i >> 7][i & 127] = M[(k0 + (i >> 7)) * D + (i & 127)];
#pragma unroll
        for (int i = tid; i < 1024; i += 256)
            sX[i >> 5][i & 31] = X[(size_t)(row0 + (i >> 5)) * D + k0 + (i & 31)];
        __syncthreads();
#pragma unroll 8
        for (int kk = 0; kk < 32; kk++) {
            float x0 = sX[tr][kk], x1 = sX[tr + 16][kk];
#pragma unroll
            for (int c = 0; c < 8; c++) {
                float mv = sM[kk][tc + c * 16];
                acc[0][c] += x0 * mv;
                acc[1][c] += x1 * mv;
            }
        }
        __syncthreads();
    }
#pragma unroll
    for (int a = 0; a < 2; a++)
#pragma unroll
        for (int c = 0; c < 8; c++) {
            float v = acc[a][c];
            if (bias) v += bias[tc + c * 16];
            C[(size_t)(row0 + tr + a * 16) * D + tc + c * 16] = v;
        }
}

// ---------------------------------------------------------------------------
__global__ void __launch_bounds__(256) prep_split_k() {
    const int i = blockIdx.x * 256 + threadIdx.x;
    float v = g_h[i];
    __nv_bfloat16 hi = __float2bfloat16_rn(v);
    g_hh[i] = hi;
    g_hl[i] = __float2bfloat16_rn(v - __bfloat162float(hi));
    v = g_hA[i];
    hi = __float2bfloat16_rn(v);
    g_hAh[i] = hi;
    g_hAl[i] = __float2bfloat16_rn(v - __bfloat162float(hi));
}

__global__ void __launch_bounds__(256) htr_split_k() {
    __shared__ float t[32][33];
    const int b = blockIdx.z;
    const int n0 = blockIdx.x * 32, d0 = blockIdx.y * 32;
    const int tx = threadIdx.x & 31, ty = threadIdx.x >> 5;
    for (int r = ty; r < 32; r += 8)
        t[r][tx] = g_h[((size_t)b * N + n0 + r) * D + d0 + tx];
    __syncthreads();
    for (int r = ty; r < 32; r += 8) {
        const float v = t[tx][r];
        const __nv_bfloat16 hi = __float2bfloat16_rn(v);
        const size_t o = ((size_t)b * D + d0 + r) * N + n0 + tx;
        g_hTh[o] = hi;
        g_hTl[o] = __float2bfloat16_rn(v - __bfloat162float(hi));
    }
}

// ---------------------------------------------------------------------------
// Esym over upper-triangle 128x128 tile pairs; 4-stage cp.async.
// Epilogue: U = adj ? exp(Esym) : 0 (both orientations) + column partial sums.
__device__ __forceinline__ void esym_issue(int c, int stage, uint32_t sbase,
                                           size_t arow, size_t brow, int tid) {
    const int seg = c >> 2;
    const int kin = (c & 3) * 64;
    const int half = kin >> 7;
    const int koff = kin & 127;
    const __nv_bfloat16* ap = (seg == 1) ? (half ? g_hl : g_hAl) : (half ? g_hh : g_hAh);
    const __nv_bfloat16* bp = (seg == 2) ? (half ? g_hAl : g_hl) : (half ? g_hAh : g_hh);
    const uint32_t sA = sbase + (uint32_t)stage * 2 * TILE_B;
    issue_tile(sA, ap, arow, D, koff, tid);
    issue_tile(sA + TILE_B, bp, brow, D, koff, tid);
    CP_COMMIT();
}

__global__ void __launch_bounds__(256) esym_k(const float* __restrict__ adj) {
    extern __shared__ char sm[];
    const uint32_t sbase = smem_u32(sm);
    const int tid = threadIdx.x, wid = tid >> 5, lane = tid & 31;
    const int wr = wid >> 2, wc = wid & 3;

    int t = blockIdx.x % 136;
    const int b = blockIdx.x / 136;
    int tj = 0;
    while (t >= 16 - tj) { t -= 16 - tj; tj++; }
    const int tk = tj + t;
    const int j0 = tj * 128, k0 = tk * 128;
    const size_t arow = (size_t)b * N + j0, brow = (size_t)b * N + k0;

    float acc[4][4][4];
#pragma unroll
    for (int mi = 0; mi < 4; mi++)
#pragma unroll
        for (int ni = 0; ni < 4; ni++)
#pragma unroll
            for (int q = 0; q < 4; q++) acc[mi][ni][q] = 0.0f;

    esym_issue(0, 0, sbase, arow, brow, tid);
    esym_issue(1, 1, sbase, arow, brow, tid);
    esym_issue(2, 2, sbase, arow, brow, tid);
#pragma unroll 1
    for (int c = 0; c < 12; c++) {
        if (c <= 9) CP_WAIT(2);
        else if (c == 10) CP_WAIT(1);
        else CP_WAIT(0);
        __syncthreads();
        if (c + 3 < 12) esym_issue(c + 3, (c + 3) & 3, sbase, arow, brow, tid);
        const uint32_t sA = sbase + (uint32_t)(c & 3) * 2 * TILE_B;
        mma_kblock(sA, sA + TILE_B, wr, wc, lane, acc);
    }
    __syncthreads();

    float* sD  = (float*)sm;                  // becomes exp(Esym) tile
    float* sA1 = (float*)(sm + 66048);        // adj[j0..][k0..]
    float* sA2 = (float*)(sm + 132096);       // adj[k0..][j0..]
    acc_to_smem(sD, wr, wc, lane, acc);
    const float* adjb = adj + (size_t)b * N * N;
#pragma unroll 4
    for (int i = tid; i < 16384; i += 256)
        sA1[(i >> 7) * 129 + (i & 127)] = adjb[(size_t)(j0 + (i >> 7)) * N + k0 + (i & 127)];
    if (tj != tk) {
#pragma unroll 4
        for (int i = tid; i < 16384; i += 256)
            sA2[(i >> 7) * 129 + (i & 127)] = adjb[(size_t)(k0 + (i >> 7)) * N + j0 + (i & 127)];
    }
    __syncthreads();

    // exp once per unique element, in place (no max shift: |Esym| small, fp32-safe)
#pragma unroll 4
    for (int i = tid; i < 16384; i += 256) {
        const int r = i >> 7, c = i & 127;
        sD[r * 129 + c] = __expf(sD[r * 129 + c]);
    }
    __syncthreads();

    const int c = tid & 127, p = tid >> 7;

    // Orientation 1: U[(j0+r)][k0+c] = adj1[r][c] ? sE[r][c] : 0
    {
        float csum = 0.0f;
        const size_t ub = (size_t)b * N * N + (size_t)j0 * N + k0;
#pragma unroll 8
        for (int it = 0; it < 64; it++) {
            const int r = it * 2 + p;
            const float v = (sA1[r * 129 + c] > 0.0f) ? sD[r * 129 + c] : 0.0f;
            g_U[ub + (size_t)r * N + c] = v;
            csum += v;
        }
        g_part[((size_t)b * N + k0 + c) * 32 + tj * 2 + p] = csum;
    }
    // Orientation 2 (off-diagonal): U[(k0+r)][j0+c] = adj2[r][c] ? sE[c][r] : 0
    if (tj != tk) {
        float csum = 0.0f;
        const size_t ub = (size_t)b * N * N + (size_t)k0 * N + j0;
#pragma unroll 8
        for (int it = 0; it < 64; it++) {
            const int r = it * 2 + p;
            const float v = (sA2[r * 129 + c] > 0.0f) ? sD[c * 129 + r] : 0.0f;
            g_U[ub + (size_t)r * N + c] = v;
            csum += v;
        }
        g_part[((size_t)b * N + j0 + c) * 32 + tk * 2 + p] = csum;
    }
}

// ---------------------------------------------------------------------------
// g_is[col] = 1 / sum of 32 deterministic partial slots.
__global__ void __launch_bounds__(256) reduce_is_k() {
    const int i = blockIdx.x * 256 + threadIdx.x;  // over B*N
    const float4* p = (const float4*)(g_part + (size_t)i * 32);
    float s = 0.0f;
#pragma unroll
    for (int q = 0; q < 8; q++) {
        const float4 v = p[q];
        s += (v.x + v.y) + (v.z + v.w);
    }
    g_is[i] = 1.0f / s;
}

// ---------------------------------------------------------------------------
// P[i][j] = U[i][j] * is[j]; bf16 split; pure streaming (no transpose, no exp).
__global__ void __launch_bounds__(256) pbuild_k() {
    const size_t idx = (size_t)blockIdx.x * 256 + threadIdx.x;  // float4 units
    const int j4 = (int)(idx & (N / 4 - 1));
    const int b = (int)(idx >> 20);                              // idx / (N*N/4)
    const float4 u = ((const float4*)g_U)[idx];
    const float4 s = ((const float4*)g_is)[(size_t)b * (N / 4) + j4];
    const float v0 = u.x * s.x, v1 = u.y * s.y, v2 = u.z * s.z, v3 = u.w * s.w;
    const __nv_bfloat16 h0 = __float2bfloat16_rn(v0);
    const __nv_bfloat16 h1 = __float2bfloat16_rn(v1);
    const __nv_bfloat16 h2 = __float2bfloat16_rn(v2);
    const __nv_bfloat16 h3 = __float2bfloat16_rn(v3);
    const __nv_bfloat16 l0 = __float2bfloat16_rn(v0 - __bfloat162float(h0));
    const __nv_bfloat16 l1 = __float2bfloat16_rn(v1 - __bfloat162float(h1));
    const __nv_bfloat16 l2 = __float2bfloat16_rn(v2 - __bfloat162float(h2));
    const __nv_bfloat16 l3 = __float2bfloat16_rn(v3 - __bfloat162float(h3));
    uint2 ph, pl;
    asm("mov.b32 %0, {%1, %2};" : "=r"(ph.x) : "h"(*(const uint16_t*)&h0), "h"(*(const uint16_t*)&h1));
    asm("mov.b32 %0, {%1, %2};" : "=r"(ph.y) : "h"(*(const uint16_t*)&h2), "h"(*(const uint16_t*)&h3));
    asm("mov.b32 %0, {%1, %2};" : "=r"(pl.x) : "h"(*(const uint16_t*)&l0), "h"(*(const uint16_t*)&l1));
    asm("mov.b32 %0, {%1, %2};" : "=r"(pl.y) : "h"(*(const uint16_t*)&l2), "h"(*(const uint16_t*)&l3));
    ((uint2*)g_Ph)[idx] = ph;
    ((uint2*)g_Pl)[idx] = pl;
}

// ---------------------------------------------------------------------------
// hp = relu(P @ h): 128(i) x 128(d), K = 96 chunks of 64; 4-stage cp.async.
__device__ __forceinline__ void hp_issue(int c, int stage, uint32_t sbase,
                                         size_t arow, size_t brow, int tid) {
    const int seg = c >> 5;
    const int koff = (c & 31) * 64;
    const __nv_bfloat16* ap = (seg == 1) ? g_Pl : g_Ph;
    const __nv_bfloat16* bp = (seg == 2) ? g_hTl : g_hTh;
    const uint32_t sA = sbase + (uint32_t)stage * 2 * TILE_B;
    issue_tile(sA, ap, arow, N, koff, tid);
    issue_tile(sA + TILE_B, bp, brow, N, koff, tid);
    CP_COMMIT();
}

__global__ void __launch_bounds__(256) hp_k() {
    extern __shared__ char sm[];
    const uint32_t sbase = smem_u32(sm);
    const int tid = threadIdx.x, wid = tid >> 5, lane = tid & 31;
    const int wr = wid >> 2, wc = wid & 3;
    const int b = blockIdx.y;
    const int i0 = blockIdx.x * 128;
    const size_t arow = (size_t)b * N + i0;
    const size_t brow = (size_t)b * D;

    float acc[4][4][4];
#pragma unroll
    for (int mi = 0; mi < 4; mi++)
#pragma unroll
        for (int ni = 0; ni < 4; ni++)
#pragma unroll
            for (int q = 0; q < 4; q++) acc[mi][ni][q] = 0.0f;

    hp_issue(0, 0, sbase, arow, brow, tid);
    hp_issue(1, 1, sbase, arow, brow, tid);
    hp_issue(2, 2, sbase, arow, brow, tid);
#pragma unroll 1
    for (int c = 0; c < 96; c++) {
        if (c <= 93) CP_WAIT(2);
        else if (c == 94) CP_WAIT(1);
        else CP_WAIT(0);
        __syncthreads();
        if (c + 3 < 96) hp_issue(c + 3, (c + 3) & 3, sbase, arow, brow, tid);
        const uint32_t sA = sbase + (uint32_t)(c & 3) * 2 * TILE_B;
        mma_kblock(sA, sA + TILE_B, wr, wc, lane, acc);
    }
    __syncthreads();

    float* sD = (float*)sm;
    acc_to_smem(sD, wr, wc, lane, acc);
    __syncthreads();
#pragma unroll 4
    for (int i = tid; i < 16384; i += 256) {
        const int r = i >> 7, cd = i & 127;
        g_hp[((size_t)b * N + i0 + r) * D + cd] = fmaxf(sD[r * 129 + cd], 0.0f);
    }
}

// ---------------------------------------------------------------------------
__global__ void __launch_bounds__(256) gate_k(
    const float* __restrict__ x, const float* __restrict__ hp,
    const float* __restrict__ gw, const float* __restrict__ gb,
    float* __restrict__ out) {
    const int lane = threadIdx.x & 31;
    const size_t row = (size_t)blockIdx.x * 8 + (threadIdx.x >> 5);
    const float4 xv = reinterpret_cast<const float4*>(x + row * D)[lane];
    const float4 hv = reinterpret_cast<const float4*>(hp + row * D)[lane];
    const float4 g1 = reinterpret_cast<const float4*>(gw)[lane];
    const float4 g2 = reinterpret_cast<const float4*>(gw + D)[lane];
    float p = xv.x * g1.x + xv.y * g1.y + xv.z * g1.z + xv.w * g1.w
            + hv.x * g2.x + hv.y * g2.y + hv.z * g2.z + hv.w * g2.w;
#pragma unroll
    for (int o = 16; o > 0; o >>= 1) p += __shfl_xor_sync(0xffffffffu, p, o);
    const float c = 1.0f / (1.0f + __expf(-(p + gb[0])));
    const float d1 = 1.0f - c;
    float4 o4;
    o4.x = c * xv.x + d1 * hv.x;
    o4.y = c * xv.y + d1 * hv.y;
    o4.z = c * xv.z + d1 * hv.z;
    o4.w = c * xv.w + d1 * hv.w;
    reinterpret_cast<float4*>(out + row * D)[lane] = o4;
}

// ---------------------------------------------------------------------------
extern "C" void kernel_launch(void* const* d_in, const int* in_sizes, int n_in,
                              void* d_out, int out_size) {
    const float* x   = (const float*)d_in[0];
    const float* adj = (const float*)d_in[1];
    const float* W_w = (const float*)d_in[2];
    const float* W_b = (const float*)d_in[3];
    const float* A   = (const float*)d_in[4];
    const float* gw  = (const float*)d_in[5];
    const float* gb  = (const float*)d_in[6];
    float* out = (float*)d_out;

    float *pWt, *ph, *phA, *php;
    cudaGetSymbolAddress((void**)&pWt, g_Wt);
    cudaGetSymbolAddress((void**)&ph,  g_h);
    cudaGetSymbolAddress((void**)&phA, g_hA);
    cudaGetSymbolAddress((void**)&php, g_hp);

    static bool attr_done = false;
    if (!attr_done) {
        cudaFuncSetAttribute(esym_k, cudaFuncAttributeMaxDynamicSharedMemorySize, SMEM_ESYM);
        cudaFuncSetAttribute(hp_k,   cudaFuncAttributeMaxDynamicSharedMemorySize, SMEM_HP);
        attr_done = true;
    }

    transpose_k<<<dim3(4, 4), dim3(32, 8)>>>(W_w, pWt);
    gemm_rows_k<<<(B * N) / 32, 256>>>(x, pWt, W_b, ph);
    gemm_rows_k<<<(B * N) / 32, 256>>>(ph, A, nullptr, phA);
    prep_split_k<<<(B * N * D) / 256, 256>>>();
    htr_split_k<<<dim3(N / 32, D / 32, B), 256>>>();
    esym_k<<<B * 136, 256, SMEM_ESYM>>>(adj);
    reduce_is_k<<<(B * N) / 256, 256>>>();
    pbuild_k<<<(int)(((size_t)B * N * N / 4) / 256), 256>>>();
    hp_k<<<dim3(N / 128, B), 256, SMEM_HP>>>();
    gate_k<<<(B * N) / 8, 256>>>(x, php, gw, gb, out);
}

// round 7
// speedup vs baseline: 1.7351x; 1.0669x over previous
#include <cuda_runtime.h>
#include <cuda_bf16.h>
#include <cstdint>

namespace {
constexpr int B = 8;
constexpr int N = 2048;
constexpr int D = 128;
constexpr int LDS = 72;                      // padded smem row (bf16 elems)
constexpr int TILE_B = 128 * LDS * 2;        // 18432 bytes per operand tile
constexpr int SMEM_ESYM = 3 * 128 * 129 * 4; // 198144 epilogue (>= pipeline 147456)
constexpr int SMEM_HP = 4 * 2 * TILE_B;      // 147456 (epilogue 66048 fits inside)
}

// ---------------------------------------------------------------------------
// Scratch (static device globals; no runtime allocation).
__device__ float g_Wt[D * D];
__device__ float g_hT[B * D * N];              // h transposed, fp32
__device__ float g_is[B * N];
__device__ float g_part[(size_t)B * N * 32];   // deterministic partial column sums
__device__ __nv_bfloat16 g_hh[B * N * D];      // splits of h (row-major)
__device__ __nv_bfloat16 g_hl[B * N * D];
__device__ __nv_bfloat16 g_hAh[B * N * D];     // splits of hA (row-major)
__device__ __nv_bfloat16 g_hAl[B * N * D];
__device__ __nv_bfloat16 g_sh[B * D * N];      // splits of is[j]*h[j][d], d-major
__device__ __nv_bfloat16 g_sl[B * D * N];
__device__ __nv_bfloat16 g_Uh[(size_t)B * N * N];  // splits of masked exp(e_sym)
__device__ __nv_bfloat16 g_Ul[(size_t)B * N * N];

// ---------------------------------------------------------------------------
__device__ __forceinline__ uint32_t smem_u32(const void* p) {
    uint32_t a;
    asm("{ .reg .u64 t; cvta.to.shared.u64 t, %1; cvt.u32.u64 %0, t; }" : "=r"(a) : "l"(p));
    return a;
}
__device__ __forceinline__ void cp16(uint32_t dst, const void* src) {
    asm volatile("cp.async.cg.shared.global [%0], [%1], 16;" :: "r"(dst), "l"(src));
}
#define CP_COMMIT() asm volatile("cp.async.commit_group;" ::: "memory")
#define CP_WAIT(n)  asm volatile("cp.async.wait_group %0;" :: "n"(n) : "memory")

__device__ __forceinline__ void issue_tile(uint32_t sdst,
                                           const __nv_bfloat16* __restrict__ base,
                                           size_t row0, int stride, int koff, int tid) {
#pragma unroll
    for (int t = 0; t < 4; t++) {
        const int i = t * 256 + tid;
        const int rr = i >> 3, c16 = i & 7;
        cp16(sdst + (uint32_t)(rr * LDS + c16 * 8) * 2,
             base + (row0 + rr) * (size_t)stride + koff + c16 * 8);
    }
}

// One 64-wide K block of m16n8k16 bf16 MMAs. Warp tile: 64(m) x 32(n).
__device__ __forceinline__ void mma_kblock(uint32_t sAb, uint32_t sBb,
                                           int wr, int wc, int lane,
                                           float (&acc)[4][4][4]) {
#pragma unroll
    for (int kk = 0; kk < 4; kk++) {
        uint32_t a[4][4], bb[4][2];
#pragma unroll
        for (int mi = 0; mi < 4; mi++) {
            const uint32_t addr = sAb +
                ((wr * 64 + mi * 16 + (lane & 15)) * LDS + kk * 16 + ((lane >> 4) << 3)) * 2;
            asm volatile("ldmatrix.sync.aligned.m8n8.x4.shared.b16 {%0,%1,%2,%3}, [%4];"
                         : "=r"(a[mi][0]), "=r"(a[mi][1]), "=r"(a[mi][2]), "=r"(a[mi][3])
                         : "r"(addr));
        }
#pragma unroll
        for (int ni = 0; ni < 4; ni++) {
            const uint32_t addr = sBb +
                ((wc * 32 + ni * 8 + (lane & 7)) * LDS + kk * 16 + (((lane >> 3) & 1) << 3)) * 2;
            asm volatile("ldmatrix.sync.aligned.m8n8.x2.shared.b16 {%0,%1}, [%2];"
                         : "=r"(bb[ni][0]), "=r"(bb[ni][1]) : "r"(addr));
        }
#pragma unroll
        for (int mi = 0; mi < 4; mi++)
#pragma unroll
            for (int ni = 0; ni < 4; ni++)
                asm volatile(
                    "mma.sync.aligned.m16n8k16.row.col.f32.bf16.bf16.f32 "
                    "{%0,%1,%2,%3}, {%4,%5,%6,%7}, {%8,%9}, {%0,%1,%2,%3};"
                    : "+f"(acc[mi][ni][0]), "+f"(acc[mi][ni][1]),
                      "+f"(acc[mi][ni][2]), "+f"(acc[mi][ni][3])
                    : "r"(a[mi][0]), "r"(a[mi][1]), "r"(a[mi][2]), "r"(a[mi][3]),
                      "r"(bb[ni][0]), "r"(bb[ni][1]));
    }
}

__device__ __forceinline__ void acc_to_smem(float* sD, int wr, int wc, int lane,
                                            const float (&acc)[4][4][4]) {
#pragma unroll
    for (int mi = 0; mi < 4; mi++)
#pragma unroll
        for (int ni = 0; ni < 4; ni++) {
            const int row = wr * 64 + mi * 16 + (lane >> 2);
            const int col = wc * 32 + ni * 8 + (lane & 3) * 2;
            sD[row * 129 + col]           = acc[mi][ni][0];
            sD[row * 129 + col + 1]       = acc[mi][ni][1];
            sD[(row + 8) * 129 + col]     = acc[mi][ni][2];
            sD[(row + 8) * 129 + col + 1] = acc[mi][ni][3];
        }
}

// ---------------------------------------------------------------------------
__global__ void transpose_k(const float* __restrict__ W, float* __restrict__ Wt) {
    __shared__ float t[32][33];
    const int x = blockIdx.x * 32 + threadIdx.x;
    const int y0 = blockIdx.y * 32;
    for (int i = threadIdx.y; i < 32; i += 8) t[i][threadIdx.x] = W[(y0 + i) * D + x];
    __syncthreads();
    const int xo = blockIdx.y * 32 + threadIdx.x;
    const int yo0 = blockIdx.x * 32;
    for (int i = threadIdx.y; i < 32; i += 8) Wt[(yo0 + i) * D + xo] = t[threadIdx.x][i];
}

// ---------------------------------------------------------------------------
// Fused front end: h = x.Wt + b; hA = h.A; bf16 splits of both; hT fp32.
// 32 rows per block, 256 threads.
__global__ void __launch_bounds__(256) fused_h_k(
    const float* __restrict__ x, const float* __restrict__ A,
    const float* __restrict__ bias) {
    __shared__ float sM[32][D + 1];
    __shared__ float sX[32][33];
    __shared__ float sH[32][D + 1];
    const int row0 = blockIdx.x * 32;
    const int b = row0 >> 11;          // row0 / N
    const int n0 = row0 & (N - 1);
    const int tid = threadIdx.x;
    const int tc = tid & 15, tr = tid >> 4;
    float acc[2][8];

    // Phase A: h = x . Wt + bias
#pragma unroll
    for (int a = 0; a < 2; a++)
#pragma unroll
        for (int c = 0; c < 8; c++) acc[a][c] = 0.0f;
    for (int k0 = 0; k0 < D; k0 += 32) {
#pragma unroll
        for (int i = tid; i < 32 * D; i += 256)
            sM[i >> 7][i & 127] = g_Wt[(k0 + (i >> 7)) * D + (i & 127)];
#pragma unroll
        for (int i = tid; i < 1024; i += 256)
            sX[i >> 5][i & 31] = x[(size_t)(row0 + (i >> 5)) * D + k0 + (i & 31)];
        __syncthreads();
#pragma unroll 8
        for (int kk = 0; kk < 32; kk++) {
            float x0 = sX[tr][kk], x1 = sX[tr + 16][kk];
#pragma unroll
            for (int c = 0; c < 8; c++) {
                float mv = sM[kk][tc + c * 16];
                acc[0][c] += x0 * mv;
                acc[1][c] += x1 * mv;
            }
        }
        __syncthreads();
    }
#pragma unroll
    for (int a = 0; a < 2; a++)
#pragma unroll
        for (int c = 0; c < 8; c++) {
            const int r = tr + a * 16, col = tc + c * 16;
            const float v = acc[a][c] + bias[col];
            sH[r][col] = v;
            const __nv_bfloat16 hi = __float2bfloat16_rn(v);
            const size_t o = (size_t)(row0 + r) * D + col;
            g_hh[o] = hi;
            g_hl[o] = __float2bfloat16_rn(v - __bfloat162float(hi));
        }
    __syncthreads();

    // Phase B: hA = h . A
#pragma unroll
    for (int a = 0; a < 2; a++)
#pragma unroll
        for (int c = 0; c < 8; c++) acc[a][c] = 0.0f;
    for (int k0 = 0; k0 < D; k0 += 32) {
#pragma unroll
        for (int i = tid; i < 32 * D; i += 256)
            sM[i >> 7][i & 127] = A[(k0 + (i >> 7)) * D + (i & 127)];
        __syncthreads();
#pragma unroll 8
        for (int kk = 0; kk < 32; kk++) {
            float x0 = sH[tr][k0 + kk], x1 = sH[tr + 16][k0 + kk];
#pragma unroll
            for (int c = 0; c < 8; c++) {
                float mv = sM[kk][tc + c * 16];
                acc[0][c] += x0 * mv;
                acc[1][c] += x1 * mv;
            }
        }
        __syncthreads();
    }
#pragma unroll
    for (int a = 0; a < 2; a++)
#pragma unroll
        for (int c = 0; c < 8; c++) {
            const int r = tr + a * 16, col = tc + c * 16;
            const float v = acc[a][c];
            const __nv_bfloat16 hi = __float2bfloat16_rn(v);
            const size_t o = (size_t)(row0 + r) * D + col;
            g_hAh[o] = hi;
            g_hAl[o] = __float2bfloat16_rn(v - __bfloat162float(hi));
        }

    // Phase C: hT fp32 (transposed write; sH stride 129 is conflict-free)
    const int nn = tid & 31, d0 = tid >> 5;
#pragma unroll
    for (int dp = 0; dp < 16; dp++) {
        const int d = dp * 8 + d0;
        g_hT[((size_t)b * D + d) * N + n0 + nn] = sH[nn][d];
    }
}

// ---------------------------------------------------------------------------
// Esym over upper-triangle 128x128 tile pairs; 4-stage cp.async.
// Epilogue: Uh/Ul = bf16 split of (adj ? exp(Esym) : 0), both orientations,
// plus deterministic column partial sums.
__device__ __forceinline__ void esym_issue(int c, int stage, uint32_t sbase,
                                           size_t arow, size_t brow, int tid) {
    const int seg = c >> 2;
    const int kin = (c & 3) * 64;
    const int half = kin >> 7;
    const int koff = kin & 127;
    const __nv_bfloat16* ap = (seg == 1) ? (half ? g_hl : g_hAl) : (half ? g_hh : g_hAh);
    const __nv_bfloat16* bp = (seg == 2) ? (half ? g_hAl : g_hl) : (half ? g_hAh : g_hh);
    const uint32_t sA = sbase + (uint32_t)stage * 2 * TILE_B;
    issue_tile(sA, ap, arow, D, koff, tid);
    issue_tile(sA + TILE_B, bp, brow, D, koff, tid);
    CP_COMMIT();
}

__global__ void __launch_bounds__(256) esym_k(const float* __restrict__ adj) {
    extern __shared__ char sm[];
    const uint32_t sbase = smem_u32(sm);
    const int tid = threadIdx.x, wid = tid >> 5, lane = tid & 31;
    const int wr = wid >> 2, wc = wid & 3;

    int t = blockIdx.x % 136;
    const int b = blockIdx.x / 136;
    int tj = 0;
    while (t >= 16 - tj) { t -= 16 - tj; tj++; }
    const int tk = tj + t;
    const int j0 = tj * 128, k0 = tk * 128;
    const size_t arow = (size_t)b * N + j0, brow = (size_t)b * N + k0;

    float acc[4][4][4];
#pragma unroll
    for (int mi = 0; mi < 4; mi++)
#pragma unroll
        for (int ni = 0; ni < 4; ni++)
#pragma unroll
            for (int q = 0; q < 4; q++) acc[mi][ni][q] = 0.0f;

    esym_issue(0, 0, sbase, arow, brow, tid);
    esym_issue(1, 1, sbase, arow, brow, tid);
    esym_issue(2, 2, sbase, arow, brow, tid);
#pragma unroll 1
    for (int c = 0; c < 12; c++) {
        if (c <= 9) CP_WAIT(2);
        else if (c == 10) CP_WAIT(1);
        else CP_WAIT(0);
        __syncthreads();
        if (c + 3 < 12) esym_issue(c + 3, (c + 3) & 3, sbase, arow, brow, tid);
        const uint32_t sA = sbase + (uint32_t)(c & 3) * 2 * TILE_B;
        mma_kblock(sA, sA + TILE_B, wr, wc, lane, acc);
    }
    __syncthreads();

    float* sD  = (float*)sm;                  // exp(Esym) tile
    float* sA1 = (float*)(sm + 66048);        // adj[j0..][k0..]
    float* sA2 = (float*)(sm + 132096);       // adj[k0..][j0..]
    acc_to_smem(sD, wr, wc, lane, acc);
    const float* adjb = adj + (size_t)b * N * N;
#pragma unroll 4
    for (int i = tid; i < 16384; i += 256)
        sA1[(i >> 7) * 129 + (i & 127)] = adjb[(size_t)(j0 + (i >> 7)) * N + k0 + (i & 127)];
    if (tj != tk) {
#pragma unroll 4
        for (int i = tid; i < 16384; i += 256)
            sA2[(i >> 7) * 129 + (i & 127)] = adjb[(size_t)(k0 + (i >> 7)) * N + j0 + (i & 127)];
    }
    __syncthreads();

    // exp once per unique element, in place (logits bounded; no max shift needed)
#pragma unroll 4
    for (int i = tid; i < 16384; i += 256) {
        const int r = i >> 7, c = i & 127;
        sD[r * 129 + c] = __expf(sD[r * 129 + c]);
    }
    __syncthreads();

    const int c = tid & 127, p = tid >> 7;

    // Orientation 1: U[(j0+r)][k0+c]
    {
        float csum = 0.0f;
        const size_t ub = (size_t)b * N * N + (size_t)j0 * N + k0;
#pragma unroll 8
        for (int it = 0; it < 64; it++) {
            const int r = it * 2 + p;
            const float v = (sA1[r * 129 + c] > 0.0f) ? sD[r * 129 + c] : 0.0f;
            const __nv_bfloat16 vh = __float2bfloat16_rn(v);
            g_Uh[ub + (size_t)r * N + c] = vh;
            g_Ul[ub + (size_t)r * N + c] = __float2bfloat16_rn(v - __bfloat162float(vh));
            csum += v;
        }
        g_part[((size_t)b * N + k0 + c) * 32 + tj * 2 + p] = csum;
    }
    // Orientation 2 (off-diagonal): U[(k0+r)][j0+c]
    if (tj != tk) {
        float csum = 0.0f;
        const size_t ub = (size_t)b * N * N + (size_t)k0 * N + j0;
#pragma unroll 8
        for (int it = 0; it < 64; it++) {
            const int r = it * 2 + p;
            const float v = (sA2[r * 129 + c] > 0.0f) ? sD[c * 129 + r] : 0.0f;
            const __nv_bfloat16 vh = __float2bfloat16_rn(v);
            g_Uh[ub + (size_t)r * N + c] = vh;
            g_Ul[ub + (size_t)r * N + c] = __float2bfloat16_rn(v - __bfloat162float(vh));
            csum += v;
        }
        g_part[((size_t)b * N + j0 + c) * 32 + tk * 2 + p] = csum;
    }
}

// ---------------------------------------------------------------------------
// g_is[col] = 1 / sum of the 32 deterministic partial slots.
__global__ void __launch_bounds__(256) reduce_is_k() {
    const int i = blockIdx.x * 256 + threadIdx.x;  // over B*N
    const float4* p = (const float4*)(g_part + (size_t)i * 32);
    float s = 0.0f;
#pragma unroll
    for (int q = 0; q < 8; q++) {
        const float4 v = p[q];
        s += (v.x + v.y) + (v.z + v.w);
    }
    g_is[i] = 1.0f / s;
}

// ---------------------------------------------------------------------------
// g_sh/g_sl = bf16 split of is[j] * hT[d][j]  (streaming over 8MB)
__global__ void __launch_bounds__(256) scale_ht_k() {
    const size_t idx = (size_t)blockIdx.x * 256 + threadIdx.x;  // float4 units
    const int j4 = (int)(idx & (N / 4 - 1));
    const int b = (int)(idx >> 16);                              // idx / (D*N/4)
    const float4 hv = ((const float4*)g_hT)[idx];
    const float4 s = ((const float4*)g_is)[(size_t)b * (N / 4) + j4];
    const float v0 = hv.x * s.x, v1 = hv.y * s.y, v2 = hv.z * s.z, v3 = hv.w * s.w;
    const __nv_bfloat16 h0 = __float2bfloat16_rn(v0);
    const __nv_bfloat16 h1 = __float2bfloat16_rn(v1);
    const __nv_bfloat16 h2 = __float2bfloat16_rn(v2);
    const __nv_bfloat16 h3 = __float2bfloat16_rn(v3);
    const __nv_bfloat16 l0 = __float2bfloat16_rn(v0 - __bfloat162float(h0));
    const __nv_bfloat16 l1 = __float2bfloat16_rn(v1 - __bfloat162float(h1));
    const __nv_bfloat16 l2 = __float2bfloat16_rn(v2 - __bfloat162float(h2));
    const __nv_bfloat16 l3 = __float2bfloat16_rn(v3 - __bfloat162float(h3));
    uint2 ph, pl;
    asm("mov.b32 %0, {%1, %2};" : "=r"(ph.x) : "h"(*(const uint16_t*)&h0), "h"(*(const uint16_t*)&h1));
    asm("mov.b32 %0, {%1, %2};" : "=r"(ph.y) : "h"(*(const uint16_t*)&h2), "h"(*(const uint16_t*)&h3));
    asm("mov.b32 %0, {%1, %2};" : "=r"(pl.x) : "h"(*(const uint16_t*)&l0), "h"(*(const uint16_t*)&l1));
    asm("mov.b32 %0, {%1, %2};" : "=r"(pl.y) : "h"(*(const uint16_t*)&l2), "h"(*(const uint16_t*)&l3));
    ((uint2*)g_sh)[idx] = ph;
    ((uint2*)g_sl)[idx] = pl;
}

// ---------------------------------------------------------------------------
// hp+gate fused: h' = relu(U @ s_h); out = c*x + (1-c)*h' with
// c = sigmoid(gate_w . [x, h'] + gate_b). 128(i) x 128(d), K = 96 chunks.
__device__ __forceinline__ void hp_issue(int c, int stage, uint32_t sbase,
                                         size_t arow, size_t brow, int tid) {
    const int seg = c >> 5;
    const int koff = (c & 31) * 64;
    const __nv_bfloat16* ap = (seg == 1) ? g_Ul : g_Uh;
    const __nv_bfloat16* bp = (seg == 2) ? g_sl : g_sh;
    const uint32_t sA = sbase + (uint32_t)stage * 2 * TILE_B;
    issue_tile(sA, ap, arow, N, koff, tid);
    issue_tile(sA + TILE_B, bp, brow, N, koff, tid);
    CP_COMMIT();
}

__global__ void __launch_bounds__(256) hp_k(
    const float* __restrict__ x, const float* __restrict__ gw,
    const float* __restrict__ gb, float* __restrict__ out) {
    extern __shared__ char sm[];
    const uint32_t sbase = smem_u32(sm);
    const int tid = threadIdx.x, wid = tid >> 5, lane = tid & 31;
    const int wr = wid >> 2, wc = wid & 3;
    const int b = blockIdx.y;
    const int i0 = blockIdx.x * 128;
    const size_t arow = (size_t)b * N + i0;
    const size_t brow = (size_t)b * D;

    float acc[4][4][4];
#pragma unroll
    for (int mi = 0; mi < 4; mi++)
#pragma unroll
        for (int ni = 0; ni < 4; ni++)
#pragma unroll
            for (int q = 0; q < 4; q++) acc[mi][ni][q] = 0.0f;

    hp_issue(0, 0, sbase, arow, brow, tid);
    hp_issue(1, 1, sbase, arow, brow, tid);
    hp_issue(2, 2, sbase, arow, brow, tid);
#pragma unroll 1
    for (int c = 0; c < 96; c++) {
        if (c <= 93) CP_WAIT(2);
        else if (c == 94) CP_WAIT(1);
        else CP_WAIT(0);
        __syncthreads();
        if (c + 3 < 96) hp_issue(c + 3, (c + 3) & 3, sbase, arow, brow, tid);
        const uint32_t sA = sbase + (uint32_t)(c & 3) * 2 * TILE_B;
        mma_kblock(sA, sA + TILE_B, wr, wc, lane, acc);
    }
    __syncthreads();

    float* sD = (float*)sm;
    acc_to_smem(sD, wr, wc, lane, acc);
    __syncthreads();

    // Gate epilogue: one warp per row (16 rows/warp).
    const float4 g1 = ((const float4*)gw)[lane];
    const float4 g2 = ((const float4*)(gw + D))[lane];
    const float gbv = gb[0];
#pragma unroll 1
    for (int rr = wid; rr < 128; rr += 8) {
        const size_t row = (size_t)b * N + i0 + rr;
        const float4 xv = ((const float4*)(x + row * D))[lane];
        float4 hv;
        hv.x = fmaxf(sD[rr * 129 + lane * 4 + 0], 0.0f);
        hv.y = fmaxf(sD[rr * 129 + lane * 4 + 1], 0.0f);
        hv.z = fmaxf(sD[rr * 129 + lane * 4 + 2], 0.0f);
        hv.w = fmaxf(sD[rr * 129 + lane * 4 + 3], 0.0f);
        float p = xv.x * g1.x + xv.y * g1.y + xv.z * g1.z + xv.w * g1.w
                + hv.x * g2.x + hv.y * g2.y + hv.z * g2.z + hv.w * g2.w;
#pragma unroll
        for (int o = 16; o > 0; o >>= 1) p += __shfl_xor_sync(0xffffffffu, p, o);
        const float cf = 1.0f / (1.0f + __expf(-(p + gbv)));
        const float df = 1.0f - cf;
        float4 o4;
        o4.x = cf * xv.x + df * hv.x;
        o4.y = cf * xv.y + df * hv.y;
        o4.z = cf * xv.z + df * hv.z;
        o4.w = cf * xv.w + df * hv.w;
        ((float4*)(out + row * D))[lane] = o4;
    }
}

// ---------------------------------------------------------------------------
extern "C" void kernel_launch(void* const* d_in, const int* in_sizes, int n_in,
                              void* d_out, int out_size) {
    const float* x   = (const float*)d_in[0];
    const float* adj = (const float*)d_in[1];
    const float* W_w = (const float*)d_in[2];
    const float* W_b = (const float*)d_in[3];
    const float* A   = (const float*)d_in[4];
    const float* gw  = (const float*)d_in[5];
    const float* gb  = (const float*)d_in[6];
    float* out = (float*)d_out;

    float* pWt;
    cudaGetSymbolAddress((void**)&pWt, g_Wt);

    static bool attr_done = false;
    if (!attr_done) {
        cudaFuncSetAttribute(esym_k, cudaFuncAttributeMaxDynamicSharedMemorySize, SMEM_ESYM);
        cudaFuncSetAttribute(hp_k,   cudaFuncAttributeMaxDynamicSharedMemorySize, SMEM_HP);
        attr_done = true;
    }

    transpose_k<<<dim3(4, 4), dim3(32, 8)>>>(W_w, pWt);
    fused_h_k<<<(B * N) / 32, 256>>>(x, A, W_b);
    esym_k<<<B * 136, 256, SMEM_ESYM>>>(adj);
    reduce_is_k<<<(B * N) / 256, 256>>>();
    scale_ht_k<<<(B * D * N / 4) / 256, 256>>>();
    hp_k<<<dim3(N / 128, B), 256, SMEM_HP>>>(x, gw, gb, out);
}

// round 9
// speedup vs baseline: 1.9025x; 1.0965x over previous
#include <cuda_runtime.h>
#include <cuda_bf16.h>
#include <cstdint>

namespace {
constexpr int B = 8;
constexpr int N = 2048;
constexpr int D = 128;
constexpr int LDS = 72;                    // padded smem row (bf16 elems)
constexpr int TILE_B = 128 * LDS * 2;      // 18432 bytes per operand tile
constexpr int STAGE_B = 4 * TILE_B;        // 73728: Ah, Al, Bh, Bl
constexpr int SMEM_MMA = 3 * STAGE_B;      // 221184 (3-stage; epilogue 198144 fits)
}

// ---------------------------------------------------------------------------
// Scratch (static device globals; no runtime allocation).
__device__ float g_Wt[D * D];
__device__ float g_hT[B * D * N];
__device__ float g_is[B * N];
__device__ float g_part[(size_t)B * N * 32];
__device__ __nv_bfloat16 g_hh[B * N * D];
__device__ __nv_bfloat16 g_hl[B * N * D];
__device__ __nv_bfloat16 g_hAh[B * N * D];
__device__ __nv_bfloat16 g_hAl[B * N * D];
__device__ __nv_bfloat16 g_sh[B * D * N];
__device__ __nv_bfloat16 g_sl[B * D * N];
__device__ __nv_bfloat16 g_Uh[(size_t)B * N * N];
__device__ __nv_bfloat16 g_Ul[(size_t)B * N * N];

// ---------------------------------------------------------------------------
__device__ __forceinline__ uint32_t smem_u32(const void* p) {
    uint32_t a;
    asm("{ .reg .u64 t; cvta.to.shared.u64 t, %1; cvt.u32.u64 %0, t; }" : "=r"(a) : "l"(p));
    return a;
}
__device__ __forceinline__ void cp16(uint32_t dst, const void* src) {
    asm volatile("cp.async.cg.shared.global [%0], [%1], 16;" :: "r"(dst), "l"(src));
}
#define CP_COMMIT() asm volatile("cp.async.commit_group;" ::: "memory")
#define CP_WAIT(n)  asm volatile("cp.async.wait_group %0;" :: "n"(n) : "memory")

__device__ __forceinline__ void issue_tile(uint32_t sdst,
                                           const __nv_bfloat16* __restrict__ base,
                                           size_t row0, int stride, int koff, int tid) {
#pragma unroll
    for (int t = 0; t < 4; t++) {
        const int i = t * 256 + tid;
        const int rr = i >> 3, c16 = i & 7;
        cp16(sdst + (uint32_t)(rr * LDS + c16 * 8) * 2,
             base + (row0 + rr) * (size_t)stride + koff + c16 * 8);
    }
}

// ---------------------------------------------------------------------------
// Fragment loaders for the m16n8k16 layout.
__device__ __forceinline__ void lda_frag(uint32_t sA, int wr, int mi, int kk, int lane,
                                         uint32_t (&a)[4]) {
    const uint32_t addr = sA +
        ((wr * 64 + mi * 16 + (lane & 15)) * LDS + kk * 16 + ((lane >> 4) << 3)) * 2;
    asm volatile("ldmatrix.sync.aligned.m8n8.x4.shared.b16 {%0,%1,%2,%3}, [%4];"
                 : "=r"(a[0]), "=r"(a[1]), "=r"(a[2]), "=r"(a[3]) : "r"(addr));
}
__device__ __forceinline__ void ldb_frag(uint32_t sB, int wc, int ni, int kk, int lane,
                                         uint32_t (&b)[2]) {
    const uint32_t addr = sB +
        ((wc * 32 + ni * 8 + (lane & 7)) * LDS + kk * 16 + (((lane >> 3) & 1) << 3)) * 2;
    asm volatile("ldmatrix.sync.aligned.m8n8.x2.shared.b16 {%0,%1}, [%2];"
                 : "=r"(b[0]), "=r"(b[1]) : "r"(addr));
}
__device__ __forceinline__ void mma16816(float (&d)[4], const uint32_t (&a)[4],
                                         const uint32_t (&b)[2]) {
    asm volatile(
        "mma.sync.aligned.m16n8k16.row.col.f32.bf16.bf16.f32 "
        "{%0,%1,%2,%3}, {%4,%5,%6,%7}, {%8,%9}, {%0,%1,%2,%3};"
        : "+f"(d[0]), "+f"(d[1]), "+f"(d[2]), "+f"(d[3])
        : "r"(a[0]), "r"(a[1]), "r"(a[2]), "r"(a[3]), "r"(b[0]), "r"(b[1]));
}

// Three-term split MMA over one 64-wide K chunk with fragment reuse:
// acc += Ah.Bh + Ah.Bl + Al.Bh
__device__ __forceinline__ void mma_tri(uint32_t sAh, uint32_t sAl,
                                        uint32_t sBh, uint32_t sBl,
                                        int wr, int wc, int lane,
                                        float (&acc)[4][4][4]) {
#pragma unroll
    for (int kk = 0; kk < 4; kk++) {
        uint32_t ah[4][4], al[4][4], bh[4][2], bl[4][2];
#pragma unroll
        for (int mi = 0; mi < 4; mi++) lda_frag(sAh, wr, mi, kk, lane, ah[mi]);
#pragma unroll
        for (int ni = 0; ni < 4; ni++) ldb_frag(sBh, wc, ni, kk, lane, bh[ni]);
#pragma unroll
        for (int mi = 0; mi < 4; mi++)
#pragma unroll
            for (int ni = 0; ni < 4; ni++) mma16816(acc[mi][ni], ah[mi], bh[ni]);
#pragma unroll
        for (int ni = 0; ni < 4; ni++) ldb_frag(sBl, wc, ni, kk, lane, bl[ni]);
#pragma unroll
        for (int mi = 0; mi < 4; mi++)
#pragma unroll
            for (int ni = 0; ni < 4; ni++) mma16816(acc[mi][ni], ah[mi], bl[ni]);
#pragma unroll
        for (int mi = 0; mi < 4; mi++) lda_frag(sAl, wr, mi, kk, lane, al[mi]);
#pragma unroll
        for (int mi = 0; mi < 4; mi++)
#pragma unroll
            for (int ni = 0; ni < 4; ni++) mma16816(acc[mi][ni], al[mi], bh[ni]);
    }
}

__device__ __forceinline__ void acc_to_smem(float* sD, int wr, int wc, int lane,
                                            const float (&acc)[4][4][4]) {
#pragma unroll
    for (int mi = 0; mi < 4; mi++)
#pragma unroll
        for (int ni = 0; ni < 4; ni++) {
            const int row = wr * 64 + mi * 16 + (lane >> 2);
            const int col = wc * 32 + ni * 8 + (lane & 3) * 2;
            sD[row * 129 + col]           = acc[mi][ni][0];
            sD[row * 129 + col + 1]       = acc[mi][ni][1];
            sD[(row + 8) * 129 + col]     = acc[mi][ni][2];
            sD[(row + 8) * 129 + col + 1] = acc[mi][ni][3];
        }
}

// ---------------------------------------------------------------------------
__global__ void transpose_k(const float* __restrict__ W, float* __restrict__ Wt) {
    __shared__ float t[32][33];
    const int x = blockIdx.x * 32 + threadIdx.x;
    const int y0 = blockIdx.y * 32;
    for (int i = threadIdx.y; i < 32; i += 8) t[i][threadIdx.x] = W[(y0 + i) * D + x];
    __syncthreads();
    const int xo = blockIdx.y * 32 + threadIdx.x;
    const int yo0 = blockIdx.x * 32;
    for (int i = threadIdx.y; i < 32; i += 8) Wt[(yo0 + i) * D + xo] = t[threadIdx.x][i];
}

// ---------------------------------------------------------------------------
// Fused front end: h = x.Wt + b; hA = h.A; bf16 splits; hT fp32.
__global__ void __launch_bounds__(256) fused_h_k(
    const float* __restrict__ x, const float* __restrict__ A,
    const float* __restrict__ bias) {
    __shared__ float sM[32][D + 1];
    __shared__ float sX[32][33];
    __shared__ float sH[32][D + 1];
    const int row0 = blockIdx.x * 32;
    const int b = row0 >> 11;
    const int n0 = row0 & (N - 1);
    const int tid = threadIdx.x;
    const int tc = tid & 15, tr = tid >> 4;
    float acc[2][8];

#pragma unroll
    for (int a = 0; a < 2; a++)
#pragma unroll
        for (int c = 0; c < 8; c++) acc[a][c] = 0.0f;
    for (int k0 = 0; k0 < D; k0 += 32) {
#pragma unroll
        for (int i = tid; i < 32 * D; i += 256)
            sM[i >> 7][i & 127] = g_Wt[(k0 + (i >> 7)) * D + (i & 127)];
#pragma unroll
        for (int i = tid; i < 1024; i += 256)
            sX[i >> 5][i & 31] = x[(size_t)(row0 + (i >> 5)) * D + k0 + (i & 31)];
        __syncthreads();
#pragma unroll 8
        for (int kk = 0; kk < 32; kk++) {
            float x0 = sX[tr][kk], x1 = sX[tr + 16][kk];
#pragma unroll
            for (int c = 0; c < 8; c++) {
                float mv = sM[kk][tc + c * 16];
                acc[0][c] += x0 * mv;
                acc[1][c] += x1 * mv;
            }
        }
        __syncthreads();
    }
#pragma unroll
    for (int a = 0; a < 2; a++)
#pragma unroll
        for (int c = 0; c < 8; c++) {
            const int r = tr + a * 16, col = tc + c * 16;
            const float v = acc[a][c] + bias[col];
            sH[r][col] = v;
            const __nv_bfloat16 hi = __float2bfloat16_rn(v);
            const size_t o = (size_t)(row0 + r) * D + col;
            g_hh[o] = hi;
            g_hl[o] = __float2bfloat16_rn(v - __bfloat162float(hi));
        }
    __syncthreads();

#pragma unroll
    for (int a = 0; a < 2; a++)
#pragma unroll
        for (int c = 0; c < 8; c++) acc[a][c] = 0.0f;
    for (int k0 = 0; k0 < D; k0 += 32) {
#pragma unroll
        for (int i = tid; i < 32 * D; i += 256)
            sM[i >> 7][i & 127] = A[(k0 + (i >> 7)) * D + (i & 127)];
        __syncthreads();
#pragma unroll 8
        for (int kk = 0; kk < 32; kk++) {
            float x0 = sH[tr][k0 + kk], x1 = sH[tr + 16][k0 + kk];
#pragma unroll
            for (int c = 0; c < 8; c++) {
                float mv = sM[kk][tc + c * 16];
                acc[0][c] += x0 * mv;
                acc[1][c] += x1 * mv;
            }
        }
        __syncthreads();
    }
#pragma unroll
    for (int a = 0; a < 2; a++)
#pragma unroll
        for (int c = 0; c < 8; c++) {
            const int r = tr + a * 16, col = tc + c * 16;
            const float v = acc[a][c];
            const __nv_bfloat16 hi = __float2bfloat16_rn(v);
            const size_t o = (size_t)(row0 + r) * D + col;
            g_hAh[o] = hi;
            g_hAl[o] = __float2bfloat16_rn(v - __bfloat162float(hi));
        }

    const int nn = tid & 31, d0 = tid >> 5;
#pragma unroll
    for (int dp = 0; dp < 16; dp++) {
        const int d = dp * 8 + d0;
        g_hT[((size_t)b * D + d) * N + n0 + nn] = sH[nn][d];
    }
}

// ---------------------------------------------------------------------------
// Esym over upper-triangle tile pairs. 4 physical chunks x 3 fused split terms.
// Depth-2 prefetch on 3 stages: chunk c+2 is issued into stage (c+2)%3 only
// after the __syncthreads() that proves chunk c-1 (its previous occupant) is
// fully consumed. Never touches the stage being read this iteration.
__device__ __forceinline__ void esym_issue(int q, int stage, uint32_t sbase,
                                           size_t arow, size_t brow, int tid) {
    const int half = q >> 1;
    const int koff = (q & 1) * 64;
    const __nv_bfloat16* uh = half ? g_hh : g_hAh;
    const __nv_bfloat16* ul = half ? g_hl : g_hAl;
    const __nv_bfloat16* vh = half ? g_hAh : g_hh;
    const __nv_bfloat16* vl = half ? g_hAl : g_hl;
    const uint32_t s = sbase + (uint32_t)stage * STAGE_B;
    issue_tile(s,              uh, arow, D, koff, tid);
    issue_tile(s + TILE_B,     ul, arow, D, koff, tid);
    issue_tile(s + 2 * TILE_B, vh, brow, D, koff, tid);
    issue_tile(s + 3 * TILE_B, vl, brow, D, koff, tid);
    CP_COMMIT();
}

__global__ void __launch_bounds__(256) esym_k(const float* __restrict__ adj) {
    extern __shared__ char sm[];
    const uint32_t sbase = smem_u32(sm);
    const int tid = threadIdx.x, wid = tid >> 5, lane = tid & 31;
    const int wr = wid >> 2, wc = wid & 3;

    int t = blockIdx.x % 136;
    const int b = blockIdx.x / 136;
    int tj = 0;
    while (t >= 16 - tj) { t -= 16 - tj; tj++; }
    const int tk = tj + t;
    const int j0 = tj * 128, k0 = tk * 128;
    const size_t arow = (size_t)b * N + j0, brow = (size_t)b * N + k0;

    float acc[4][4][4];
#pragma unroll
    for (int mi = 0; mi < 4; mi++)
#pragma unroll
        for (int ni = 0; ni < 4; ni++)
#pragma unroll
            for (int q = 0; q < 4; q++) acc[mi][ni][q] = 0.0f;

    esym_issue(0, 0, sbase, arow, brow, tid);
    esym_issue(1, 1, sbase, arow, brow, tid);
#pragma unroll 1
    for (int q = 0; q < 4; q++) {
        if (q < 3) CP_WAIT(1);
        else CP_WAIT(0);
        __syncthreads();
        if (q + 2 < 4) esym_issue(q + 2, (q + 2) % 3, sbase, arow, brow, tid);
        const uint32_t s = sbase + (uint32_t)(q % 3) * STAGE_B;
        mma_tri(s, s + TILE_B, s + 2 * TILE_B, s + 3 * TILE_B, wr, wc, lane, acc);
    }
    __syncthreads();

    float* sD  = (float*)sm;
    float* sA1 = (float*)(sm + 66048);
    float* sA2 = (float*)(sm + 132096);
    acc_to_smem(sD, wr, wc, lane, acc);
    const float* adjb = adj + (size_t)b * N * N;
#pragma unroll 4
    for (int i = tid; i < 16384; i += 256)
        sA1[(i >> 7) * 129 + (i & 127)] = adjb[(size_t)(j0 + (i >> 7)) * N + k0 + (i & 127)];
    if (tj != tk) {
#pragma unroll 4
        for (int i = tid; i < 16384; i += 256)
            sA2[(i >> 7) * 129 + (i & 127)] = adjb[(size_t)(k0 + (i >> 7)) * N + j0 + (i & 127)];
    }
    __syncthreads();

#pragma unroll 4
    for (int i = tid; i < 16384; i += 256) {
        const int r = i >> 7, c = i & 127;
        sD[r * 129 + c] = __expf(sD[r * 129 + c]);
    }
    __syncthreads();

    const int c = tid & 127, p = tid >> 7;
    {
        float csum = 0.0f;
        const size_t ub = (size_t)b * N * N + (size_t)j0 * N + k0;
#pragma unroll 8
        for (int it = 0; it < 64; it++) {
            const int r = it * 2 + p;
            const float v = (sA1[r * 129 + c] > 0.0f) ? sD[r * 129 + c] : 0.0f;
            const __nv_bfloat16 vh = __float2bfloat16_rn(v);
            g_Uh[ub + (size_t)r * N + c] = vh;
            g_Ul[ub + (size_t)r * N + c] = __float2bfloat16_rn(v - __bfloat162float(vh));
            csum += v;
        }
        g_part[((size_t)b * N + k0 + c) * 32 + tj * 2 + p] = csum;
    }
    if (tj != tk) {
        float csum = 0.0f;
        const size_t ub = (size_t)b * N * N + (size_t)k0 * N + j0;
#pragma unroll 8
        for (int it = 0; it < 64; it++) {
            const int r = it * 2 + p;
            const float v = (sA2[r * 129 + c] > 0.0f) ? sD[c * 129 + r] : 0.0f;
            const __nv_bfloat16 vh = __float2bfloat16_rn(v);
            g_Uh[ub + (size_t)r * N + c] = vh;
            g_Ul[ub + (size_t)r * N + c] = __float2bfloat16_rn(v - __bfloat162float(vh));
            csum += v;
        }
        g_part[((size_t)b * N + j0 + c) * 32 + tk * 2 + p] = csum;
    }
}

// ---------------------------------------------------------------------------
__global__ void __launch_bounds__(256) reduce_is_k() {
    const int i = blockIdx.x * 256 + threadIdx.x;
    const float4* p = (const float4*)(g_part + (size_t)i * 32);
    float s = 0.0f;
#pragma unroll
    for (int q = 0; q < 8; q++) {
        const float4 v = p[q];
        s += (v.x + v.y) + (v.z + v.w);
    }
    g_is[i] = 1.0f / s;
}

// ---------------------------------------------------------------------------
__global__ void __launch_bounds__(256) scale_ht_k() {
    const size_t idx = (size_t)blockIdx.x * 256 + threadIdx.x;
    const int j4 = (int)(idx & (N / 4 - 1));
    const int b = (int)(idx >> 16);
    const float4 hv = ((const float4*)g_hT)[idx];
    const float4 s = ((const float4*)g_is)[(size_t)b * (N / 4) + j4];
    const float v0 = hv.x * s.x, v1 = hv.y * s.y, v2 = hv.z * s.z, v3 = hv.w * s.w;
    const __nv_bfloat16 h0 = __float2bfloat16_rn(v0);
    const __nv_bfloat16 h1 = __float2bfloat16_rn(v1);
    const __nv_bfloat16 h2 = __float2bfloat16_rn(v2);
    const __nv_bfloat16 h3 = __float2bfloat16_rn(v3);
    const __nv_bfloat16 l0 = __float2bfloat16_rn(v0 - __bfloat162float(h0));
    const __nv_bfloat16 l1 = __float2bfloat16_rn(v1 - __bfloat162float(h1));
    const __nv_bfloat16 l2 = __float2bfloat16_rn(v2 - __bfloat162float(h2));
    const __nv_bfloat16 l3 = __float2bfloat16_rn(v3 - __bfloat162float(h3));
    uint2 ph, pl;
    asm("mov.b32 %0, {%1, %2};" : "=r"(ph.x) : "h"(*(const uint16_t*)&h0), "h"(*(const uint16_t*)&h1));
    asm("mov.b32 %0, {%1, %2};" : "=r"(ph.y) : "h"(*(const uint16_t*)&h2), "h"(*(const uint16_t*)&h3));
    asm("mov.b32 %0, {%1, %2};" : "=r"(pl.x) : "h"(*(const uint16_t*)&l0), "h"(*(const uint16_t*)&l1));
    asm("mov.b32 %0, {%1, %2};" : "=r"(pl.y) : "h"(*(const uint16_t*)&l2), "h"(*(const uint16_t*)&l3));
    ((uint2*)g_sh)[idx] = ph;
    ((uint2*)g_sl)[idx] = pl;
}

// ---------------------------------------------------------------------------
// hp+gate fused: 32 physical chunks x 3 fused split terms; depth-2 prefetch.
__device__ __forceinline__ void hp_issue(int c, int stage, uint32_t sbase,
                                         size_t arow, size_t brow, int tid) {
    const int koff = c * 64;
    const uint32_t s = sbase + (uint32_t)stage * STAGE_B;
    issue_tile(s,              g_Uh, arow, N, koff, tid);
    issue_tile(s + TILE_B,     g_Ul, arow, N, koff, tid);
    issue_tile(s + 2 * TILE_B, g_sh, brow, N, koff, tid);
    issue_tile(s + 3 * TILE_B, g_sl, brow, N, koff, tid);
    CP_COMMIT();
}

__global__ void __launch_bounds__(256) hp_k(
    const float* __restrict__ x, const float* __restrict__ gw,
    const float* __restrict__ gb, float* __restrict__ out) {
    extern __shared__ char sm[];
    const uint32_t sbase = smem_u32(sm);
    const int tid = threadIdx.x, wid = tid >> 5, lane = tid & 31;
    const int wr = wid >> 2, wc = wid & 3;
    const int b = blockIdx.y;
    const int i0 = blockIdx.x * 128;
    const size_t arow = (size_t)b * N + i0;
    const size_t brow = (size_t)b * D;

    float acc[4][4][4];
#pragma unroll
    for (int mi = 0; mi < 4; mi++)
#pragma unroll
        for (int ni = 0; ni < 4; ni++)
#pragma unroll
            for (int q = 0; q < 4; q++) acc[mi][ni][q] = 0.0f;

    hp_issue(0, 0, sbase, arow, brow, tid);
    hp_issue(1, 1, sbase, arow, brow, tid);
#pragma unroll 1
    for (int c = 0; c < 32; c++) {
        if (c < 31) CP_WAIT(1);
        else CP_WAIT(0);
        __syncthreads();
        if (c + 2 < 32) hp_issue(c + 2, (c + 2) % 3, sbase, arow, brow, tid);
        const uint32_t s = sbase + (uint32_t)(c % 3) * STAGE_B;
        mma_tri(s, s + TILE_B, s + 2 * TILE_B, s + 3 * TILE_B, wr, wc, lane, acc);
    }
    __syncthreads();

    float* sD = (float*)sm;
    acc_to_smem(sD, wr, wc, lane, acc);
    __syncthreads();

    const float4 g1 = ((const float4*)gw)[lane];
    const float4 g2 = ((const float4*)(gw + D))[lane];
    const float gbv = gb[0];
#pragma unroll 1
    for (int rr = wid; rr < 128; rr += 8) {
        const size_t row = (size_t)b * N + i0 + rr;
        const float4 xv = ((const float4*)(x + row * D))[lane];
        float4 hv;
        hv.x = fmaxf(sD[rr * 129 + lane * 4 + 0], 0.0f);
        hv.y = fmaxf(sD[rr * 129 + lane * 4 + 1], 0.0f);
        hv.z = fmaxf(sD[rr * 129 + lane * 4 + 2], 0.0f);
        hv.w = fmaxf(sD[rr * 129 + lane * 4 + 3], 0.0f);
        float p = xv.x * g1.x + xv.y * g1.y + xv.z * g1.z + xv.w * g1.w
                + hv.x * g2.x + hv.y * g2.y + hv.z * g2.z + hv.w * g2.w;
#pragma unroll
        for (int o = 16; o > 0; o >>= 1) p += __shfl_xor_sync(0xffffffffu, p, o);
        const float cf = 1.0f / (1.0f + __expf(-(p + gbv)));
        const float df = 1.0f - cf;
        float4 o4;
        o4.x = cf * xv.x + df * hv.x;
        o4.y = cf * xv.y + df * hv.y;
        o4.z = cf * xv.z + df * hv.z;
        o4.w = cf * xv.w + df * hv.w;
        ((float4*)(out + row * D))[lane] = o4;
    }
}

// ---------------------------------------------------------------------------
extern "C" void kernel_launch(void* const* d_in, const int* in_sizes, int n_in,
                              void* d_out, int out_size) {
    const float* x   = (const float*)d_in[0];
    const float* adj = (const float*)d_in[1];
    const float* W_w = (const float*)d_in[2];
    const float* W_b = (const float*)d_in[3];
    const float* A   = (const float*)d_in[4];
    const float* gw  = (const float*)d_in[5];
    const float* gb  = (const float*)d_in[6];
    float* out = (float*)d_out;

    float* pWt;
    cudaGetSymbolAddress((void**)&pWt, g_Wt);

    static bool attr_done = false;
    if (!attr_done) {
        cudaFuncSetAttribute(esym_k, cudaFuncAttributeMaxDynamicSharedMemorySize, SMEM_MMA);
        cudaFuncSetAttribute(hp_k,   cudaFuncAttributeMaxDynamicSharedMemorySize, SMEM_MMA);
        attr_done = true;
    }

    transpose_k<<<dim3(4, 4), dim3(32, 8)>>>(W_w, pWt);
    fused_h_k<<<(B * N) / 32, 256>>>(x, A, W_b);
    esym_k<<<B * 136, 256, SMEM_MMA>>>(adj);
    reduce_is_k<<<(B * N) / 256, 256>>>();
    scale_ht_k<<<(B * D * N / 4) / 256, 256>>>();
    hp_k<<<dim3(N / 128, B), 256, SMEM_MMA>>>(x, gw, gb, out);
}

// round 10
// speedup vs baseline: 2.7652x; 1.4535x over previous
#include <cuda_runtime.h>
#include <cuda_bf16.h>
#include <cstdint>

namespace {
constexpr int B = 8;
constexpr int N = 2048;
constexpr int D = 128;
constexpr int LDS = 72;                    // padded smem row (bf16 elems)
constexpr int TILE_B = 128 * LDS * 2;      // 18432 bytes per operand tile
constexpr int STAGE_B = 4 * TILE_B;        // 73728: Ah, Al, Bh, Bl
constexpr int SMEM_MMA = 3 * STAGE_B;      // 221184
constexpr int ADJ_LDS = 132;               // fp32 elems per adj smem row (528B, 16B-aligned)
}

// ---------------------------------------------------------------------------
// Scratch (static device globals; no runtime allocation).
__device__ float g_Wt[D * D];
__device__ float g_hT[B * D * N];
__device__ float g_part[(size_t)B * N * 32];
__device__ __nv_bfloat16 g_hh[B * N * D];
__device__ __nv_bfloat16 g_hl[B * N * D];
__device__ __nv_bfloat16 g_hAh[B * N * D];
__device__ __nv_bfloat16 g_hAl[B * N * D];
__device__ __nv_bfloat16 g_sh[B * D * N];
__device__ __nv_bfloat16 g_sl[B * D * N];
__device__ __nv_bfloat16 g_Uh[(size_t)B * N * N];
__device__ __nv_bfloat16 g_Ul[(size_t)B * N * N];

// ---------------------------------------------------------------------------
__device__ __forceinline__ uint32_t smem_u32(const void* p) {
    uint32_t a;
    asm("{ .reg .u64 t; cvta.to.shared.u64 t, %1; cvt.u32.u64 %0, t; }" : "=r"(a) : "l"(p));
    return a;
}
__device__ __forceinline__ void cp16(uint32_t dst, const void* src) {
    asm volatile("cp.async.cg.shared.global [%0], [%1], 16;" :: "r"(dst), "l"(src));
}
#define CP_COMMIT() asm volatile("cp.async.commit_group;" ::: "memory")
#define CP_WAIT(n)  asm volatile("cp.async.wait_group %0;" :: "n"(n) : "memory")

__device__ __forceinline__ void issue_tile(uint32_t sdst,
                                           const __nv_bfloat16* __restrict__ base,
                                           size_t row0, int stride, int koff, int tid) {
#pragma unroll
    for (int t = 0; t < 4; t++) {
        const int i = t * 256 + tid;
        const int rr = i >> 3, c16 = i & 7;
        cp16(sdst + (uint32_t)(rr * LDS + c16 * 8) * 2,
             base + (row0 + rr) * (size_t)stride + koff + c16 * 8);
    }
}

// Prefetch a 128x128 fp32 adj tile into smem (row stride ADJ_LDS floats).
__device__ __forceinline__ void adj_issue(uint32_t sdst, const float* __restrict__ adjb,
                                          int r0, int c0, int tid) {
#pragma unroll
    for (int t = 0; t < 16; t++) {
        const int i = t * 256 + tid;
        const int rr = i >> 5, cc = i & 31;
        cp16(sdst + (uint32_t)(rr * ADJ_LDS + cc * 4) * 4,
             adjb + (size_t)(r0 + rr) * N + c0 + cc * 4);
    }
    CP_COMMIT();
}

// ---------------------------------------------------------------------------
// Fragment loaders for the m16n8k16 layout.
__device__ __forceinline__ void lda_frag(uint32_t sA, int wr, int mi, int kk, int lane,
                                         uint32_t (&a)[4]) {
    const uint32_t addr = sA +
        ((wr * 64 + mi * 16 + (lane & 15)) * LDS + kk * 16 + ((lane >> 4) << 3)) * 2;
    asm volatile("ldmatrix.sync.aligned.m8n8.x4.shared.b16 {%0,%1,%2,%3}, [%4];"
                 : "=r"(a[0]), "=r"(a[1]), "=r"(a[2]), "=r"(a[3]) : "r"(addr));
}
__device__ __forceinline__ void ldb_frag(uint32_t sB, int wc, int ni, int kk, int lane,
                                         uint32_t (&b)[2]) {
    const uint32_t addr = sB +
        ((wc * 32 + ni * 8 + (lane & 7)) * LDS + kk * 16 + (((lane >> 3) & 1) << 3)) * 2;
    asm volatile("ldmatrix.sync.aligned.m8n8.x2.shared.b16 {%0,%1}, [%2];"
                 : "=r"(b[0]), "=r"(b[1]) : "r"(addr));
}
__device__ __forceinline__ void mma16816(float (&d)[4], const uint32_t (&a)[4],
                                         const uint32_t (&b)[2]) {
    asm volatile(
        "mma.sync.aligned.m16n8k16.row.col.f32.bf16.bf16.f32 "
        "{%0,%1,%2,%3}, {%4,%5,%6,%7}, {%8,%9}, {%0,%1,%2,%3};"
        : "+f"(d[0]), "+f"(d[1]), "+f"(d[2]), "+f"(d[3])
        : "r"(a[0]), "r"(a[1]), "r"(a[2]), "r"(a[3]), "r"(b[0]), "r"(b[1]));
}

// Three-term split MMA over one 64-wide K chunk with fragment reuse:
// acc += Ah.Bh + Ah.Bl + Al.Bh
__device__ __forceinline__ void mma_tri(uint32_t sAh, uint32_t sAl,
                                        uint32_t sBh, uint32_t sBl,
                                        int wr, int wc, int lane,
                                        float (&acc)[4][4][4]) {
#pragma unroll
    for (int kk = 0; kk < 4; kk++) {
        uint32_t ah[4][4], al[4][4], bh[4][2], bl[4][2];
#pragma unroll
        for (int mi = 0; mi < 4; mi++) lda_frag(sAh, wr, mi, kk, lane, ah[mi]);
#pragma unroll
        for (int ni = 0; ni < 4; ni++) ldb_frag(sBh, wc, ni, kk, lane, bh[ni]);
#pragma unroll
        for (int mi = 0; mi < 4; mi++)
#pragma unroll
            for (int ni = 0; ni < 4; ni++) mma16816(acc[mi][ni], ah[mi], bh[ni]);
#pragma unroll
        for (int ni = 0; ni < 4; ni++) ldb_frag(sBl, wc, ni, kk, lane, bl[ni]);
#pragma unroll
        for (int mi = 0; mi < 4; mi++)
#pragma unroll
            for (int ni = 0; ni < 4; ni++) mma16816(acc[mi][ni], ah[mi], bl[ni]);
#pragma unroll
        for (int mi = 0; mi < 4; mi++) lda_frag(sAl, wr, mi, kk, lane, al[mi]);
#pragma unroll
        for (int mi = 0; mi < 4; mi++)
#pragma unroll
            for (int ni = 0; ni < 4; ni++) mma16816(acc[mi][ni], al[mi], bh[ni]);
    }
}

__device__ __forceinline__ void acc_to_smem(float* sD, int wr, int wc, int lane,
                                            const float (&acc)[4][4][4], bool do_exp) {
#pragma unroll
    for (int mi = 0; mi < 4; mi++)
#pragma unroll
        for (int ni = 0; ni < 4; ni++) {
            const int row = wr * 64 + mi * 16 + (lane >> 2);
            const int col = wc * 32 + ni * 8 + (lane & 3) * 2;
            if (do_exp) {
                sD[row * 129 + col]           = __expf(acc[mi][ni][0]);
                sD[row * 129 + col + 1]       = __expf(acc[mi][ni][1]);
                sD[(row + 8) * 129 + col]     = __expf(acc[mi][ni][2]);
                sD[(row + 8) * 129 + col + 1] = __expf(acc[mi][ni][3]);
            } else {
                sD[row * 129 + col]           = acc[mi][ni][0];
                sD[row * 129 + col + 1]       = acc[mi][ni][1];
                sD[(row + 8) * 129 + col]     = acc[mi][ni][2];
                sD[(row + 8) * 129 + col + 1] = acc[mi][ni][3];
            }
        }
}

// ---------------------------------------------------------------------------
__global__ void transpose_k(const float* __restrict__ W, float* __restrict__ Wt) {
    __shared__ float t[32][33];
    const int x = blockIdx.x * 32 + threadIdx.x;
    const int y0 = blockIdx.y * 32;
    for (int i = threadIdx.y; i < 32; i += 8) t[i][threadIdx.x] = W[(y0 + i) * D + x];
    __syncthreads();
    const int xo = blockIdx.y * 32 + threadIdx.x;
    const int yo0 = blockIdx.x * 32;
    for (int i = threadIdx.y; i < 32; i += 8) Wt[(yo0 + i) * D + xo] = t[threadIdx.x][i];
}

// ---------------------------------------------------------------------------
// Fused front end: h = x.Wt + b; hA = h.A; bf16 splits; hT fp32.
__global__ void __launch_bounds__(256) fused_h_k(
    const float* __restrict__ x, const float* __restrict__ A,
    const float* __restrict__ bias) {
    __shared__ float sM[32][D + 1];
    __shared__ float sX[32][33];
    __shared__ float sH[32][D + 1];
    const int row0 = blockIdx.x * 32;
    const int b = row0 >> 11;
    const int n0 = row0 & (N - 1);
    const int tid = threadIdx.x;
    const int tc = tid & 15, tr = tid >> 4;
    float acc[2][8];

#pragma unroll
    for (int a = 0; a < 2; a++)
#pragma unroll
        for (int c = 0; c < 8; c++) acc[a][c] = 0.0f;
    for (int k0 = 0; k0 < D; k0 += 32) {
#pragma unroll
        for (int i = tid; i < 32 * D; i += 256)
            sM[i >> 7][i & 127] = g_Wt[(k0 + (i >> 7)) * D + (i & 127)];
#pragma unroll
        for (int i = tid; i < 1024; i += 256)
            sX[i >> 5][i & 31] = x[(size_t)(row0 + (i >> 5)) * D + k0 + (i & 31)];
        __syncthreads();
#pragma unroll 8
        for (int kk = 0; kk < 32; kk++) {
            float x0 = sX[tr][kk], x1 = sX[tr + 16][kk];
#pragma unroll
            for (int c = 0; c < 8; c++) {
                float mv = sM[kk][tc + c * 16];
                acc[0][c] += x0 * mv;
                acc[1][c] += x1 * mv;
            }
        }
        __syncthreads();
    }
#pragma unroll
    for (int a = 0; a < 2; a++)
#pragma unroll
        for (int c = 0; c < 8; c++) {
            const int r = tr + a * 16, col = tc + c * 16;
            const float v = acc[a][c] + bias[col];
            sH[r][col] = v;
            const __nv_bfloat16 hi = __float2bfloat16_rn(v);
            const size_t o = (size_t)(row0 + r) * D + col;
            g_hh[o] = hi;
            g_hl[o] = __float2bfloat16_rn(v - __bfloat162float(hi));
        }
    __syncthreads();

#pragma unroll
    for (int a = 0; a < 2; a++)
#pragma unroll
        for (int c = 0; c < 8; c++) acc[a][c] = 0.0f;
    for (int k0 = 0; k0 < D; k0 += 32) {
#pragma unroll
        for (int i = tid; i < 32 * D; i += 256)
            sM[i >> 7][i & 127] = A[(k0 + (i >> 7)) * D + (i & 127)];
        __syncthreads();
#pragma unroll 8
        for (int kk = 0; kk < 32; kk++) {
            float x0 = sH[tr][k0 + kk], x1 = sH[tr + 16][k0 + kk];
#pragma unroll
            for (int c = 0; c < 8; c++) {
                float mv = sM[kk][tc + c * 16];
                acc[0][c] += x0 * mv;
                acc[1][c] += x1 * mv;
            }
        }
        __syncthreads();
    }
#pragma unroll
    for (int a = 0; a < 2; a++)
#pragma unroll
        for (int c = 0; c < 8; c++) {
            const int r = tr + a * 16, col = tc + c * 16;
            const float v = acc[a][c];
            const __nv_bfloat16 hi = __float2bfloat16_rn(v);
            const size_t o = (size_t)(row0 + r) * D + col;
            g_hAh[o] = hi;
            g_hAl[o] = __float2bfloat16_rn(v - __bfloat162float(hi));
        }

    const int nn = tid & 31, d0 = tid >> 5;
#pragma unroll
    for (int dp = 0; dp < 16; dp++) {
        const int d = dp * 8 + d0;
        g_hT[((size_t)b * D + d) * N + n0 + nn] = sH[nn][d];
    }
}

// ---------------------------------------------------------------------------
// Esym over upper-triangle tile pairs: 4 chunks x 3 fused split terms,
// depth-2 prefetch on 3 stages; adj tiles prefetched into stages as they free;
// exp fused into the accumulator spill.
__device__ __forceinline__ void esym_issue(int q, int stage, uint32_t sbase,
                                           size_t arow, size_t brow, int tid) {
    const int half = q >> 1;
    const int koff = (q & 1) * 64;
    const __nv_bfloat16* uh = half ? g_hh : g_hAh;
    const __nv_bfloat16* ul = half ? g_hl : g_hAl;
    const __nv_bfloat16* vh = half ? g_hAh : g_hh;
    const __nv_bfloat16* vl = half ? g_hAl : g_hl;
    const uint32_t s = sbase + (uint32_t)stage * STAGE_B;
    issue_tile(s,              uh, arow, D, koff, tid);
    issue_tile(s + TILE_B,     ul, arow, D, koff, tid);
    issue_tile(s + 2 * TILE_B, vh, brow, D, koff, tid);
    issue_tile(s + 3 * TILE_B, vl, brow, D, koff, tid);
    CP_COMMIT();
}

__global__ void __launch_bounds__(256) esym_k(const float* __restrict__ adj) {
    extern __shared__ char sm[];
    const uint32_t sbase = smem_u32(sm);
    const int tid = threadIdx.x, wid = tid >> 5, lane = tid & 31;
    const int wr = wid >> 2, wc = wid & 3;

    int t = blockIdx.x % 136;
    const int b = blockIdx.x / 136;
    int tj = 0;
    while (t >= 16 - tj) { t -= 16 - tj; tj++; }
    const int tk = tj + t;
    const int j0 = tj * 128, k0 = tk * 128;
    const size_t arow = (size_t)b * N + j0, brow = (size_t)b * N + k0;
    const float* adjb = adj + (size_t)b * N * N;

    float acc[4][4][4];
#pragma unroll
    for (int mi = 0; mi < 4; mi++)
#pragma unroll
        for (int ni = 0; ni < 4; ni++)
#pragma unroll
            for (int q = 0; q < 4; q++) acc[mi][ni][q] = 0.0f;

    esym_issue(0, 0, sbase, arow, brow, tid);
    esym_issue(1, 1, sbase, arow, brow, tid);

    // q=0: consume st0, prefetch chunk2 -> st2
    CP_WAIT(1); __syncthreads();
    esym_issue(2, 2, sbase, arow, brow, tid);
    mma_tri(sbase, sbase + TILE_B, sbase + 2 * TILE_B, sbase + 3 * TILE_B,
            wr, wc, lane, acc);
    // q=1: consume st1, prefetch chunk3 -> st0
    CP_WAIT(1); __syncthreads();
    esym_issue(3, 0, sbase, arow, brow, tid);
    {
        const uint32_t s = sbase + STAGE_B;
        mma_tri(s, s + TILE_B, s + 2 * TILE_B, s + 3 * TILE_B, wr, wc, lane, acc);
    }
    // q=2: consume st2, prefetch adj1 -> st1 region (st1 consumed at q=1)
    CP_WAIT(1); __syncthreads();
    adj_issue(sbase + STAGE_B, adjb, j0, k0, tid);
    {
        const uint32_t s = sbase + 2 * STAGE_B;
        mma_tri(s, s + TILE_B, s + 2 * TILE_B, s + 3 * TILE_B, wr, wc, lane, acc);
    }
    // q=3: consume st0 (groups complete in order: wait(1) covers chunk3),
    // prefetch adj2 -> st2 region (st2 consumed at q=2)
    CP_WAIT(1); __syncthreads();
    if (tj != tk) adj_issue(sbase + 2 * STAGE_B, adjb, k0, j0, tid);
    mma_tri(sbase, sbase + TILE_B, sbase + 2 * TILE_B, sbase + 3 * TILE_B,
            wr, wc, lane, acc);

    CP_WAIT(0);
    __syncthreads();

    float* sD  = (float*)sm;                         // 128x129 fp32 in st0 region
    float* sA1 = (float*)(sm + STAGE_B);             // adj[j0..][k0..], stride 132
    float* sA2 = (float*)(sm + 2 * STAGE_B);         // adj[k0..][j0..], stride 132
    acc_to_smem(sD, wr, wc, lane, acc, true);        // exp fused
    __syncthreads();

    const int c = tid & 127, p = tid >> 7;
    {
        float csum = 0.0f;
        const size_t ub = (size_t)b * N * N + (size_t)j0 * N + k0;
#pragma unroll 8
        for (int it = 0; it < 64; it++) {
            const int r = it * 2 + p;
            const float v = (sA1[r * ADJ_LDS + c] > 0.0f) ? sD[r * 129 + c] : 0.0f;
            const __nv_bfloat16 vh = __float2bfloat16_rn(v);
            g_Uh[ub + (size_t)r * N + c] = vh;
            g_Ul[ub + (size_t)r * N + c] = __float2bfloat16_rn(v - __bfloat162float(vh));
            csum += v;
        }
        g_part[((size_t)b * N + k0 + c) * 32 + tj * 2 + p] = csum;
    }
    if (tj != tk) {
        float csum = 0.0f;
        const size_t ub = (size_t)b * N * N + (size_t)k0 * N + j0;
#pragma unroll 8
        for (int it = 0; it < 64; it++) {
            const int r = it * 2 + p;
            const float v = (sA2[r * ADJ_LDS + c] > 0.0f) ? sD[c * 129 + r] : 0.0f;
            const __nv_bfloat16 vh = __float2bfloat16_rn(v);
            g_Uh[ub + (size_t)r * N + c] = vh;
            g_Ul[ub + (size_t)r * N + c] = __float2bfloat16_rn(v - __bfloat162float(vh));
            csum += v;
        }
        g_part[((size_t)b * N + j0 + c) * 32 + tk * 2 + p] = csum;
    }
}

// ---------------------------------------------------------------------------
// Merged: per 256-column block, reduce partial sums -> is[]; then scale hT and
// emit bf16 splits. Grid: B*8 blocks.
__global__ void __launch_bounds__(256) scale_is_k() {
    __shared__ float s_is[256];
    const int b = blockIdx.x >> 3;
    const int j0 = (blockIdx.x & 7) * 256;
    const int tid = threadIdx.x;

    {
        const float4* p = (const float4*)(g_part + ((size_t)b * N + j0 + tid) * 32);
        float s = 0.0f;
#pragma unroll
        for (int q = 0; q < 8; q++) {
            const float4 v = p[q];
            s += (v.x + v.y) + (v.z + v.w);
        }
        s_is[tid] = 1.0f / s;
    }
    __syncthreads();

    const int jq = tid & 63, dr0 = tid >> 6;     // 4 d-rows per iteration
    const float4 sv = ((const float4*)s_is)[jq];
#pragma unroll 4
    for (int it = 0; it < 32; it++) {
        const int d = it * 4 + dr0;
        const size_t o4 = (((size_t)b * D + d) * N + j0) / 4 + jq;
        const float4 hv = ((const float4*)g_hT)[o4];
        const float v0 = hv.x * sv.x, v1 = hv.y * sv.y, v2 = hv.z * sv.z, v3 = hv.w * sv.w;
        const __nv_bfloat16 h0 = __float2bfloat16_rn(v0);
        const __nv_bfloat16 h1 = __float2bfloat16_rn(v1);
        const __nv_bfloat16 h2 = __float2bfloat16_rn(v2);
        const __nv_bfloat16 h3 = __float2bfloat16_rn(v3);
        const __nv_bfloat16 l0 = __float2bfloat16_rn(v0 - __bfloat162float(h0));
        const __nv_bfloat16 l1 = __float2bfloat16_rn(v1 - __bfloat162float(h1));
        const __nv_bfloat16 l2 = __float2bfloat16_rn(v2 - __bfloat162float(h2));
        const __nv_bfloat16 l3 = __float2bfloat16_rn(v3 - __bfloat162float(h3));
        uint2 ph, pl;
        asm("mov.b32 %0, {%1, %2};" : "=r"(ph.x) : "h"(*(const uint16_t*)&h0), "h"(*(const uint16_t*)&h1));
        asm("mov.b32 %0, {%1, %2};" : "=r"(ph.y) : "h"(*(const uint16_t*)&h2), "h"(*(const uint16_t*)&h3));
        asm("mov.b32 %0, {%1, %2};" : "=r"(pl.x) : "h"(*(const uint16_t*)&l0), "h"(*(const uint16_t*)&l1));
        asm("mov.b32 %0, {%1, %2};" : "=r"(pl.y) : "h"(*(const uint16_t*)&l2), "h"(*(const uint16_t*)&l3));
        ((uint2*)g_sh)[o4] = ph;
        ((uint2*)g_sl)[o4] = pl;
    }
}

// ---------------------------------------------------------------------------
// hp+gate fused: 32 chunks x 3 fused split terms; depth-2 prefetch on 3 stages.
__device__ __forceinline__ void hp_issue(int c, int stage, uint32_t sbase,
                                         size_t arow, size_t brow, int tid) {
    const int koff = c * 64;
    const uint32_t s = sbase + (uint32_t)stage * STAGE_B;
    issue_tile(s,              g_Uh, arow, N, koff, tid);
    issue_tile(s + TILE_B,     g_Ul, arow, N, koff, tid);
    issue_tile(s + 2 * TILE_B, g_sh, brow, N, koff, tid);
    issue_tile(s + 3 * TILE_B, g_sl, brow, N, koff, tid);
    CP_COMMIT();
}

__global__ void __launch_bounds__(256) hp_k(
    const float* __restrict__ x, const float* __restrict__ gw,
    const float* __restrict__ gb, float* __restrict__ out) {
    extern __shared__ char sm[];
    const uint32_t sbase = smem_u32(sm);
    const int tid = threadIdx.x, wid = tid >> 5, lane = tid & 31;
    const int wr = wid >> 2, wc = wid & 3;
    const int b = blockIdx.y;
    const int i0 = blockIdx.x * 128;
    const size_t arow = (size_t)b * N + i0;
    const size_t brow = (size_t)b * D;

    float acc[4][4][4];
#pragma unroll
    for (int mi = 0; mi < 4; mi++)
#pragma unroll
        for (int ni = 0; ni < 4; ni++)
#pragma unroll
            for (int q = 0; q < 4; q++) acc[mi][ni][q] = 0.0f;

    hp_issue(0, 0, sbase, arow, brow, tid);
    hp_issue(1, 1, sbase, arow, brow, tid);
#pragma unroll 1
    for (int c = 0; c < 32; c++) {
        if (c < 31) CP_WAIT(1);
        else CP_WAIT(0);
        __syncthreads();
        if (c + 2 < 32) hp_issue(c + 2, (c + 2) % 3, sbase, arow, brow, tid);
        const uint32_t s = sbase + (uint32_t)(c % 3) * STAGE_B;
        mma_tri(s, s + TILE_B, s + 2 * TILE_B, s + 3 * TILE_B, wr, wc, lane, acc);
    }
    __syncthreads();

    float* sD = (float*)sm;
    acc_to_smem(sD, wr, wc, lane, acc, false);
    __syncthreads();

    const float4 g1 = ((const float4*)gw)[lane];
    const float4 g2 = ((const float4*)(gw + D))[lane];
    const float gbv = gb[0];
#pragma unroll 1
    for (int rr = wid; rr < 128; rr += 8) {
        const size_t row = (size_t)b * N + i0 + rr;
        const float4 xv = ((const float4*)(x + row * D))[lane];
        float4 hv;
        hv.x = fmaxf(sD[rr * 129 + lane * 4 + 0], 0.0f);
        hv.y = fmaxf(sD[rr * 129 + lane * 4 + 1], 0.0f);
        hv.z = fmaxf(sD[rr * 129 + lane * 4 + 2], 0.0f);
        hv.w = fmaxf(sD[rr * 129 + lane * 4 + 3], 0.0f);
        float p = xv.x * g1.x + xv.y * g1.y + xv.z * g1.z + xv.w * g1.w
                + hv.x * g2.x + hv.y * g2.y + hv.z * g2.z + hv.w * g2.w;
#pragma unroll
        for (int o = 16; o > 0; o >>= 1) p += __shfl_xor_sync(0xffffffffu, p, o);
        const float cf = 1.0f / (1.0f + __expf(-(p + gbv)));
        const float df = 1.0f - cf;
        float4 o4;
        o4.x = cf * xv.x + df * hv.x;
        o4.y = cf * xv.y + df * hv.y;
        o4.z = cf * xv.z + df * hv.z;
        o4.w = cf * xv.w + df * hv.w;
        ((float4*)(out + row * D))[lane] = o4;
    }
}

// ---------------------------------------------------------------------------
extern "C" void kernel_launch(void* const* d_in, const int* in_sizes, int n_in,
                              void* d_out, int out_size) {
    const float* x   = (const float*)d_in[0];
    const float* adj = (const float*)d_in[1];
    const float* W_w = (const float*)d_in[2];
    const float* W_b = (const float*)d_in[3];
    const float* A   = (const float*)d_in[4];
    const float* gw  = (const float*)d_in[5];
    const float* gb  = (const float*)d_in[6];
    float* out = (float*)d_out;

    float* pWt;
    cudaGetSymbolAddress((void**)&pWt, g_Wt);

    static bool attr_done = false;
    if (!attr_done) {
        cudaFuncSetAttribute(esym_k, cudaFuncAttributeMaxDynamicSharedMemorySize, SMEM_MMA);
        cudaFuncSetAttribute(hp_k,   cudaFuncAttributeMaxDynamicSharedMemorySize, SMEM_MMA);
        attr_done = true;
    }

    transpose_k<<<dim3(4, 4), dim3(32, 8)>>>(W_w, pWt);
    fused_h_k<<<(B * N) / 32, 256>>>(x, A, W_b);
    esym_k<<<B * 136, 256, SMEM_MMA>>>(adj);
    scale_is_k<<<B * 8, 256>>>();
    hp_k<<<dim3(N / 128, B), 256, SMEM_MMA>>>(x, gw, gb, out);
}

// round 11
// speedup vs baseline: 2.8804x; 1.0416x over previous
#include <cuda_runtime.h>
#include <cuda_bf16.h>
#include <cstdint>

namespace {
constexpr int B = 8;
constexpr int N = 2048;
constexpr int D = 128;
constexpr int LDS = 72;                    // padded smem row (bf16 elems)
constexpr int TILE_B = 128 * LDS * 2;      // 18432 bytes per operand tile
constexpr int STAGE_B = 4 * TILE_B;        // 73728: Ah, Al, Bh, Bl
constexpr int SMEM_MMA = 3 * STAGE_B;      // 221184
constexpr int ADJ_LDS = 132;               // fp32 elems per adj smem row
}

// ---------------------------------------------------------------------------
// Scratch (static device globals; no runtime allocation).
__device__ float g_Wt[D * D];
__device__ float g_hT[B * D * N];
__device__ float g_part[(size_t)B * N * 32];
__device__ __nv_bfloat16 g_hh[B * N * D];
__device__ __nv_bfloat16 g_hl[B * N * D];
__device__ __nv_bfloat16 g_hAh[B * N * D];
__device__ __nv_bfloat16 g_hAl[B * N * D];
__device__ __nv_bfloat16 g_sh[B * D * N];
__device__ __nv_bfloat16 g_sl[B * D * N];
__device__ __nv_bfloat16 g_Uh[(size_t)B * N * N];
__device__ __nv_bfloat16 g_Ul[(size_t)B * N * N];

// ---------------------------------------------------------------------------
__device__ __forceinline__ uint32_t smem_u32(const void* p) {
    uint32_t a;
    asm("{ .reg .u64 t; cvta.to.shared.u64 t, %1; cvt.u32.u64 %0, t; }" : "=r"(a) : "l"(p));
    return a;
}
__device__ __forceinline__ void cp16(uint32_t dst, const void* src) {
    asm volatile("cp.async.cg.shared.global [%0], [%1], 16;" :: "r"(dst), "l"(src));
}
#define CP_COMMIT() asm volatile("cp.async.commit_group;" ::: "memory")
#define CP_WAIT(n)  asm volatile("cp.async.wait_group %0;" :: "n"(n) : "memory")

__device__ __forceinline__ void issue_tile(uint32_t sdst,
                                           const __nv_bfloat16* __restrict__ base,
                                           size_t row0, int stride, int koff, int tid) {
#pragma unroll
    for (int t = 0; t < 4; t++) {
        const int i = t * 256 + tid;
        const int rr = i >> 3, c16 = i & 7;
        cp16(sdst + (uint32_t)(rr * LDS + c16 * 8) * 2,
             base + (row0 + rr) * (size_t)stride + koff + c16 * 8);
    }
}

// Prefetch a 128x128 fp32 adj tile into smem (row stride ADJ_LDS floats).
__device__ __forceinline__ void adj_issue(uint32_t sdst, const float* __restrict__ adjb,
                                          int r0, int c0, int tid) {
#pragma unroll
    for (int t = 0; t < 16; t++) {
        const int i = t * 256 + tid;
        const int rr = i >> 5, cc = i & 31;
        cp16(sdst + (uint32_t)(rr * ADJ_LDS + cc * 4) * 4,
             adjb + (size_t)(r0 + rr) * N + c0 + cc * 4);
    }
    CP_COMMIT();
}

// ---------------------------------------------------------------------------
// Fragment loaders for the m16n8k16 layout.
__device__ __forceinline__ void lda_frag(uint32_t sA, int wr, int mi, int kk, int lane,
                                         uint32_t (&a)[4]) {
    const uint32_t addr = sA +
        ((wr * 64 + mi * 16 + (lane & 15)) * LDS + kk * 16 + ((lane >> 4) << 3)) * 2;
    asm volatile("ldmatrix.sync.aligned.m8n8.x4.shared.b16 {%0,%1,%2,%3}, [%4];"
                 : "=r"(a[0]), "=r"(a[1]), "=r"(a[2]), "=r"(a[3]) : "r"(addr));
}
// x4 B loader: two adjacent n8 fragments (ni = 2p, 2p+1) in one instruction.
// matrix m = lane>>3: m0=(2p,k0) m1=(2p,k8) m2=(2p+1,k0) m3=(2p+1,k8)
__device__ __forceinline__ void ldb_frag4(uint32_t sB, int wc, int p, int kk, int lane,
                                          uint32_t (&b0)[2], uint32_t (&b1)[2]) {
    const uint32_t addr = sB +
        ((wc * 32 + (2 * p + ((lane >> 4) & 1)) * 8 + (lane & 7)) * LDS +
         kk * 16 + (((lane >> 3) & 1) << 3)) * 2;
    asm volatile("ldmatrix.sync.aligned.m8n8.x4.shared.b16 {%0,%1,%2,%3}, [%4];"
                 : "=r"(b0[0]), "=r"(b0[1]), "=r"(b1[0]), "=r"(b1[1]) : "r"(addr));
}
__device__ __forceinline__ void mma16816(float (&d)[4], const uint32_t (&a)[4],
                                         const uint32_t (&b)[2]) {
    asm volatile(
        "mma.sync.aligned.m16n8k16.row.col.f32.bf16.bf16.f32 "
        "{%0,%1,%2,%3}, {%4,%5,%6,%7}, {%8,%9}, {%0,%1,%2,%3};"
        : "+f"(d[0]), "+f"(d[1]), "+f"(d[2]), "+f"(d[3])
        : "r"(a[0]), "r"(a[1]), "r"(a[2]), "r"(a[3]), "r"(b[0]), "r"(b[1]));
}

// Three-term split MMA over one 64-wide K chunk with fragment reuse:
// acc += Ah.Bh + Ah.Bl + Al.Bh
__device__ __forceinline__ void mma_tri(uint32_t sAh, uint32_t sAl,
                                        uint32_t sBh, uint32_t sBl,
                                        int wr, int wc, int lane,
                                        float (&acc)[4][4][4]) {
#pragma unroll
    for (int kk = 0; kk < 4; kk++) {
        uint32_t ah[4][4], al[4][4], bh[4][2], bl[4][2];
#pragma unroll
        for (int mi = 0; mi < 4; mi++) lda_frag(sAh, wr, mi, kk, lane, ah[mi]);
#pragma unroll
        for (int p = 0; p < 2; p++) ldb_frag4(sBh, wc, p, kk, lane, bh[2 * p], bh[2 * p + 1]);
#pragma unroll
        for (int mi = 0; mi < 4; mi++)
#pragma unroll
            for (int ni = 0; ni < 4; ni++) mma16816(acc[mi][ni], ah[mi], bh[ni]);
#pragma unroll
        for (int p = 0; p < 2; p++) ldb_frag4(sBl, wc, p, kk, lane, bl[2 * p], bl[2 * p + 1]);
#pragma unroll
        for (int mi = 0; mi < 4; mi++)
#pragma unroll
            for (int ni = 0; ni < 4; ni++) mma16816(acc[mi][ni], ah[mi], bl[ni]);
#pragma unroll
        for (int mi = 0; mi < 4; mi++) lda_frag(sAl, wr, mi, kk, lane, al[mi]);
#pragma unroll
        for (int mi = 0; mi < 4; mi++)
#pragma unroll
            for (int ni = 0; ni < 4; ni++) mma16816(acc[mi][ni], al[mi], bh[ni]);
    }
}

__device__ __forceinline__ void acc_to_smem(float* sD, int wr, int wc, int lane,
                                            const float (&acc)[4][4][4], bool do_exp) {
#pragma unroll
    for (int mi = 0; mi < 4; mi++)
#pragma unroll
        for (int ni = 0; ni < 4; ni++) {
            const int row = wr * 64 + mi * 16 + (lane >> 2);
            const int col = wc * 32 + ni * 8 + (lane & 3) * 2;
            if (do_exp) {
                sD[row * 129 + col]           = __expf(acc[mi][ni][0]);
                sD[row * 129 + col + 1]       = __expf(acc[mi][ni][1]);
                sD[(row + 8) * 129 + col]     = __expf(acc[mi][ni][2]);
                sD[(row + 8) * 129 + col + 1] = __expf(acc[mi][ni][3]);
            } else {
                sD[row * 129 + col]           = acc[mi][ni][0];
                sD[row * 129 + col + 1]       = acc[mi][ni][1];
                sD[(row + 8) * 129 + col]     = acc[mi][ni][2];
                sD[(row + 8) * 129 + col + 1] = acc[mi][ni][3];
            }
        }
}

// ---------------------------------------------------------------------------
__global__ void transpose_k(const float* __restrict__ W, float* __restrict__ Wt) {
    __shared__ float t[32][33];
    const int x = blockIdx.x * 32 + threadIdx.x;
    const int y0 = blockIdx.y * 32;
    for (int i = threadIdx.y; i < 32; i += 8) t[i][threadIdx.x] = W[(y0 + i) * D + x];
    __syncthreads();
    const int xo = blockIdx.y * 32 + threadIdx.x;
    const int yo0 = blockIdx.x * 32;
    for (int i = threadIdx.y; i < 32; i += 8) Wt[(yo0 + i) * D + xo] = t[threadIdx.x][i];
}

// ---------------------------------------------------------------------------
// Fused front end: h = x.Wt + b; hA = h.A; bf16 splits; hT fp32.
__global__ void __launch_bounds__(256) fused_h_k(
    const float* __restrict__ x, const float* __restrict__ A,
    const float* __restrict__ bias) {
    __shared__ float sM[32][D + 1];
    __shared__ float sX[32][33];
    __shared__ float sH[32][D + 1];
    const int row0 = blockIdx.x * 32;
    const int b = row0 >> 11;
    const int n0 = row0 & (N - 1);
    const int tid = threadIdx.x;
    const int tc = tid & 15, tr = tid >> 4;
    float acc[2][8];

#pragma unroll
    for (int a = 0; a < 2; a++)
#pragma unroll
        for (int c = 0; c < 8; c++) acc[a][c] = 0.0f;
    for (int k0 = 0; k0 < D; k0 += 32) {
#pragma unroll
        for (int i = tid; i < 32 * D; i += 256)
            sM[i >> 7][i & 127] = g_Wt[(k0 + (i >> 7)) * D + (i & 127)];
#pragma unroll
        for (int i = tid; i < 1024; i += 256)
            sX[i >> 5][i & 31] = x[(size_t)(row0 + (i >> 5)) * D + k0 + (i & 31)];
        __syncthreads();
#pragma unroll 8
        for (int kk = 0; kk < 32; kk++) {
            float x0 = sX[tr][kk], x1 = sX[tr + 16][kk];
#pragma unroll
            for (int c = 0; c < 8; c++) {
                float mv = sM[kk][tc + c * 16];
                acc[0][c] += x0 * mv;
                acc[1][c] += x1 * mv;
            }
        }
        __syncthreads();
    }
#pragma unroll
    for (int a = 0; a < 2; a++)
#pragma unroll
        for (int c = 0; c < 8; c++) {
            const int r = tr + a * 16, col = tc + c * 16;
            const float v = acc[a][c] + bias[col];
            sH[r][col] = v;
            const __nv_bfloat16 hi = __float2bfloat16_rn(v);
            const size_t o = (size_t)(row0 + r) * D + col;
            g_hh[o] = hi;
            g_hl[o] = __float2bfloat16_rn(v - __bfloat162float(hi));
        }
    __syncthreads();

#pragma unroll
    for (int a = 0; a < 2; a++)
#pragma unroll
        for (int c = 0; c < 8; c++) acc[a][c] = 0.0f;
    for (int k0 = 0; k0 < D; k0 += 32) {
#pragma unroll
        for (int i = tid; i < 32 * D; i += 256)
            sM[i >> 7][i & 127] = A[(k0 + (i >> 7)) * D + (i & 127)];
        __syncthreads();
#pragma unroll 8
        for (int kk = 0; kk < 32; kk++) {
            float x0 = sH[tr][k0 + kk], x1 = sH[tr + 16][k0 + kk];
#pragma unroll
            for (int c = 0; c < 8; c++) {
                float mv = sM[kk][tc + c * 16];
                acc[0][c] += x0 * mv;
                acc[1][c] += x1 * mv;
            }
        }
        __syncthreads();
    }
#pragma unroll
    for (int a = 0; a < 2; a++)
#pragma unroll
        for (int c = 0; c < 8; c++) {
            const int r = tr + a * 16, col = tc + c * 16;
            const float v = acc[a][c];
            const __nv_bfloat16 hi = __float2bfloat16_rn(v);
            const size_t o = (size_t)(row0 + r) * D + col;
            g_hAh[o] = hi;
            g_hAl[o] = __float2bfloat16_rn(v - __bfloat162float(hi));
        }

    const int nn = tid & 31, d0 = tid >> 5;
#pragma unroll
    for (int dp = 0; dp < 16; dp++) {
        const int d = dp * 8 + d0;
        g_hT[((size_t)b * D + d) * N + n0 + nn] = sH[nn][d];
    }
}

// ---------------------------------------------------------------------------
// Esym over upper-triangle tile pairs: 4 chunks x 3 fused split terms,
// depth-2 prefetch on 3 stages; adj prefetched into freed stages; exp fused.
__device__ __forceinline__ void esym_issue(int q, int stage, uint32_t sbase,
                                           size_t arow, size_t brow, int tid) {
    const int half = q >> 1;
    const int koff = (q & 1) * 64;
    const __nv_bfloat16* uh = half ? g_hh : g_hAh;
    const __nv_bfloat16* ul = half ? g_hl : g_hAl;
    const __nv_bfloat16* vh = half ? g_hAh : g_hh;
    const __nv_bfloat16* vl = half ? g_hAl : g_hl;
    const uint32_t s = sbase + (uint32_t)stage * STAGE_B;
    issue_tile(s,              uh, arow, D, koff, tid);
    issue_tile(s + TILE_B,     ul, arow, D, koff, tid);
    issue_tile(s + 2 * TILE_B, vh, brow, D, koff, tid);
    issue_tile(s + 3 * TILE_B, vl, brow, D, koff, tid);
    CP_COMMIT();
}

__global__ void __launch_bounds__(256) esym_k(const float* __restrict__ adj) {
    extern __shared__ char sm[];
    const uint32_t sbase = smem_u32(sm);
    const int tid = threadIdx.x, wid = tid >> 5, lane = tid & 31;
    const int wr = wid >> 2, wc = wid & 3;

    int t = blockIdx.x % 136;
    const int b = blockIdx.x / 136;
    int tj = 0;
    while (t >= 16 - tj) { t -= 16 - tj; tj++; }
    const int tk = tj + t;
    const int j0 = tj * 128, k0 = tk * 128;
    const size_t arow = (size_t)b * N + j0, brow = (size_t)b * N + k0;
    const float* adjb = adj + (size_t)b * N * N;

    float acc[4][4][4];
#pragma unroll
    for (int mi = 0; mi < 4; mi++)
#pragma unroll
        for (int ni = 0; ni < 4; ni++)
#pragma unroll
            for (int q = 0; q < 4; q++) acc[mi][ni][q] = 0.0f;

    esym_issue(0, 0, sbase, arow, brow, tid);
    esym_issue(1, 1, sbase, arow, brow, tid);

    CP_WAIT(1); __syncthreads();
    esym_issue(2, 2, sbase, arow, brow, tid);
    mma_tri(sbase, sbase + TILE_B, sbase + 2 * TILE_B, sbase + 3 * TILE_B,
            wr, wc, lane, acc);
    CP_WAIT(1); __syncthreads();
    esym_issue(3, 0, sbase, arow, brow, tid);
    {
        const uint32_t s = sbase + STAGE_B;
        mma_tri(s, s + TILE_B, s + 2 * TILE_B, s + 3 * TILE_B, wr, wc, lane, acc);
    }
    CP_WAIT(1); __syncthreads();
    adj_issue(sbase + STAGE_B, adjb, j0, k0, tid);
    {
        const uint32_t s = sbase + 2 * STAGE_B;
        mma_tri(s, s + TILE_B, s + 2 * TILE_B, s + 3 * TILE_B, wr, wc, lane, acc);
    }
    CP_WAIT(1); __syncthreads();
    if (tj != tk) adj_issue(sbase + 2 * STAGE_B, adjb, k0, j0, tid);
    mma_tri(sbase, sbase + TILE_B, sbase + 2 * TILE_B, sbase + 3 * TILE_B,
            wr, wc, lane, acc);

    CP_WAIT(0);
    __syncthreads();

    float* sD  = (float*)sm;
    float* sA1 = (float*)(sm + STAGE_B);
    float* sA2 = (float*)(sm + 2 * STAGE_B);
    acc_to_smem(sD, wr, wc, lane, acc, true);
    __syncthreads();

    const int c = tid & 127, p = tid >> 7;
    {
        float csum = 0.0f;
        const size_t ub = (size_t)b * N * N + (size_t)j0 * N + k0;
#pragma unroll 8
        for (int it = 0; it < 64; it++) {
            const int r = it * 2 + p;
            const float v = (sA1[r * ADJ_LDS + c] > 0.0f) ? sD[r * 129 + c] : 0.0f;
            const __nv_bfloat16 vh = __float2bfloat16_rn(v);
            g_Uh[ub + (size_t)r * N + c] = vh;
            g_Ul[ub + (size_t)r * N + c] = __float2bfloat16_rn(v - __bfloat162float(vh));
            csum += v;
        }
        g_part[((size_t)b * N + k0 + c) * 32 + tj * 2 + p] = csum;
    }
    if (tj != tk) {
        float csum = 0.0f;
        const size_t ub = (size_t)b * N * N + (size_t)k0 * N + j0;
#pragma unroll 8
        for (int it = 0; it < 64; it++) {
            const int r = it * 2 + p;
            const float v = (sA2[r * ADJ_LDS + c] > 0.0f) ? sD[c * 129 + r] : 0.0f;
            const __nv_bfloat16 vh = __float2bfloat16_rn(v);
            g_Uh[ub + (size_t)r * N + c] = vh;
            g_Ul[ub + (size_t)r * N + c] = __float2bfloat16_rn(v - __bfloat162float(vh));
            csum += v;
        }
        g_part[((size_t)b * N + j0 + c) * 32 + tk * 2 + p] = csum;
    }
}

// ---------------------------------------------------------------------------
// Per block: reduce is[] for 256 columns (redundant across d-chunks, cheap),
// then scale 32 d-rows of hT and emit bf16 splits. Grid: B*8*4 = 256 blocks.
__global__ void __launch_bounds__(256) scale_is_k() {
    __shared__ float s_is[256];
    const int bx = blockIdx.x;
    const int b = bx >> 5;
    const int rem = bx & 31;
    const int j0 = (rem & 7) * 256;
    const int d0 = (rem >> 3) * 32;
    const int tid = threadIdx.x;

    {
        const float4* p = (const float4*)(g_part + ((size_t)b * N + j0 + tid) * 32);
        float s = 0.0f;
#pragma unroll
        for (int q = 0; q < 8; q++) {
            const float4 v = p[q];
            s += (v.x + v.y) + (v.z + v.w);
        }
        s_is[tid] = 1.0f / s;
    }
    __syncthreads();

    const int jq = tid & 63, dr0 = tid >> 6;     // 4 d-rows per iteration
    const float4 sv = ((const float4*)s_is)[jq];
#pragma unroll
    for (int it = 0; it < 8; it++) {
        const int d = d0 + it * 4 + dr0;
        const size_t o4 = (((size_t)b * D + d) * N + j0) / 4 + jq;
        const float4 hv = ((const float4*)g_hT)[o4];
        const float v0 = hv.x * sv.x, v1 = hv.y * sv.y, v2 = hv.z * sv.z, v3 = hv.w * sv.w;
        const __nv_bfloat16 h0 = __float2bfloat16_rn(v0);
        const __nv_bfloat16 h1 = __float2bfloat16_rn(v1);
        const __nv_bfloat16 h2 = __float2bfloat16_rn(v2);
        const __nv_bfloat16 h3 = __float2bfloat16_rn(v3);
        const __nv_bfloat16 l0 = __float2bfloat16_rn(v0 - __bfloat162float(h0));
        const __nv_bfloat16 l1 = __float2bfloat16_rn(v1 - __bfloat162float(h1));
        const __nv_bfloat16 l2 = __float2bfloat16_rn(v2 - __bfloat162float(h2));
        const __nv_bfloat16 l3 = __float2bfloat16_rn(v3 - __bfloat162float(h3));
        uint2 ph, pl;
        asm("mov.b32 %0, {%1, %2};" : "=r"(ph.x) : "h"(*(const uint16_t*)&h0), "h"(*(const uint16_t*)&h1));
        asm("mov.b32 %0, {%1, %2};" : "=r"(ph.y) : "h"(*(const uint16_t*)&h2), "h"(*(const uint16_t*)&h3));
        asm("mov.b32 %0, {%1, %2};" : "=r"(pl.x) : "h"(*(const uint16_t*)&l0), "h"(*(const uint16_t*)&l1));
        asm("mov.b32 %0, {%1, %2};" : "=r"(pl.y) : "h"(*(const uint16_t*)&l2), "h"(*(const uint16_t*)&l3));
        ((uint2*)g_sh)[o4] = ph;
        ((uint2*)g_sl)[o4] = pl;
    }
}

// ---------------------------------------------------------------------------
// hp+gate fused: 32 chunks x 3 fused split terms; depth-2 prefetch on 3 stages.
__device__ __forceinline__ void hp_issue(int c, int stage, uint32_t sbase,
                                         size_t arow, size_t brow, int tid) {
    const int koff = c * 64;
    const uint32_t s = sbase + (uint32_t)stage * STAGE_B;
    issue_tile(s,              g_Uh, arow, N, koff, tid);
    issue_tile(s + TILE_B,     g_Ul, arow, N, koff, tid);
    issue_tile(s + 2 * TILE_B, g_sh, brow, N, koff, tid);
    issue_tile(s + 3 * TILE_B, g_sl, brow, N, koff, tid);
    CP_COMMIT();
}

__global__ void __launch_bounds__(256) hp_k(
    const float* __restrict__ x, const float* __restrict__ gw,
    const float* __restrict__ gb, float* __restrict__ out) {
    extern __shared__ char sm[];
    const uint32_t sbase = smem_u32(sm);
    const int tid = threadIdx.x, wid = tid >> 5, lane = tid & 31;
    const int wr = wid >> 2, wc = wid & 3;
    const int b = blockIdx.y;
    const int i0 = blockIdx.x * 128;
    const size_t arow = (size_t)b * N + i0;
    const size_t brow = (size_t)b * D;

    float acc[4][4][4];
#pragma unroll
    for (int mi = 0; mi < 4; mi++)
#pragma unroll
        for (int ni = 0; ni < 4; ni++)
#pragma unroll
            for (int q = 0; q < 4; q++) acc[mi][ni][q] = 0.0f;

    hp_issue(0, 0, sbase, arow, brow, tid);
    hp_issue(1, 1, sbase, arow, brow, tid);
#pragma unroll 1
    for (int c = 0; c < 32; c++) {
        if (c < 31) CP_WAIT(1);
        else CP_WAIT(0);
        __syncthreads();
        if (c + 2 < 32) hp_issue(c + 2, (c + 2) % 3, sbase, arow, brow, tid);
        const uint32_t s = sbase + (uint32_t)(c % 3) * STAGE_B;
        mma_tri(s, s + TILE_B, s + 2 * TILE_B, s + 3 * TILE_B, wr, wc, lane, acc);
    }
    __syncthreads();

    float* sD = (float*)sm;
    acc_to_smem(sD, wr, wc, lane, acc, false);
    __syncthreads();

    const float4 g1 = ((const float4*)gw)[lane];
    const float4 g2 = ((const float4*)(gw + D))[lane];
    const float gbv = gb[0];
#pragma unroll 1
    for (int rr = wid; rr < 128; rr += 8) {
        const size_t row = (size_t)b * N + i0 + rr;
        const float4 xv = ((const float4*)(x + row * D))[lane];
        float4 hv;
        hv.x = fmaxf(sD[rr * 129 + lane * 4 + 0], 0.0f);
        hv.y = fmaxf(sD[rr * 129 + lane * 4 + 1], 0.0f);
        hv.z = fmaxf(sD[rr * 129 + lane * 4 + 2], 0.0f);
        hv.w = fmaxf(sD[rr * 129 + lane * 4 + 3], 0.0f);
        float p = xv.x * g1.x + xv.y * g1.y + xv.z * g1.z + xv.w * g1.w
                + hv.x * g2.x + hv.y * g2.y + hv.z * g2.z + hv.w * g2.w;
#pragma unroll
        for (int o = 16; o > 0; o >>= 1) p += __shfl_xor_sync(0xffffffffu, p, o);
        const float cf = 1.0f / (1.0f + __expf(-(p + gbv)));
        const float df = 1.0f - cf;
        float4 o4;
        o4.x = cf * xv.x + df * hv.x;
        o4.y = cf * xv.y + df * hv.y;
        o4.z = cf * xv.z + df * hv.z;
        o4.w = cf * xv.w + df * hv.w;
        ((float4*)(out + row * D))[lane] = o4;
    }
}

// ---------------------------------------------------------------------------
extern "C" void kernel_launch(void* const* d_in, const int* in_sizes, int n_in,
                              void* d_out, int out_size) {
    const float* x   = (const float*)d_in[0];
    const float* adj = (const float*)d_in[1];
    const float* W_w = (const float*)d_in[2];
    const float* W_b = (const float*)d_in[3];
    const float* A   = (const float*)d_in[4];
    const float* gw  = (const float*)d_in[5];
    const float* gb  = (const float*)d_in[6];
    float* out = (float*)d_out;

    float* pWt;
    cudaGetSymbolAddress((void**)&pWt, g_Wt);

    static bool attr_done = false;
    if (!attr_done) {
        cudaFuncSetAttribute(esym_k, cudaFuncAttributeMaxDynamicSharedMemorySize, SMEM_MMA);
        cudaFuncSetAttribute(hp_k,   cudaFuncAttributeMaxDynamicSharedMemorySize, SMEM_MMA);
        attr_done = true;
    }

    transpose_k<<<dim3(4, 4), dim3(32, 8)>>>(W_w, pWt);
    fused_h_k<<<(B * N) / 32, 256>>>(x, A, W_b);
    esym_k<<<B * 136, 256, SMEM_MMA>>>(adj);
    scale_is_k<<<B * 32, 256>>>();
    hp_k<<<dim3(N / 128, B), 256, SMEM_MMA>>>(x, gw, gb, out);
}

// round 12
// speedup vs baseline: 3.2020x; 1.1117x over previous
#include <cuda_runtime.h>
#include <cuda_bf16.h>
#include <cstdint>

namespace {
constexpr int B = 8;
constexpr int N = 2048;
constexpr int D = 128;
constexpr int LDS = 72;                    // padded smem row (bf16 elems)
constexpr int TILE_B = 128 * LDS * 2;      // 18432 bytes per operand tile
constexpr int STAGE_B = 4 * TILE_B;        // 73728: Ah, Al, Bh, Bl
constexpr int SMEM_MMA = 3 * STAGE_B;      // 221184
constexpr int ADJ_LDS = 132;               // fp32 elems per adj smem row
}

// ---------------------------------------------------------------------------
// Scratch (static device globals; no runtime allocation).
__device__ float g_Wt[D * D];
__device__ float g_M[D * D];               // A + A^T
__device__ float g_hT[B * D * N];
__device__ float g_part[(size_t)B * N * 32];
__device__ __nv_bfloat16 g_hh[B * N * D];
__device__ __nv_bfloat16 g_hl[B * N * D];
__device__ __nv_bfloat16 g_Gh[B * N * D];  // splits of G = h.(A+A^T)
__device__ __nv_bfloat16 g_Gl[B * N * D];
__device__ __nv_bfloat16 g_sh[B * D * N];
__device__ __nv_bfloat16 g_sl[B * D * N];
__device__ __nv_bfloat16 g_Uh[(size_t)B * N * N];
__device__ __nv_bfloat16 g_Ul[(size_t)B * N * N];

// ---------------------------------------------------------------------------
__device__ __forceinline__ uint32_t smem_u32(const void* p) {
    uint32_t a;
    asm("{ .reg .u64 t; cvta.to.shared.u64 t, %1; cvt.u32.u64 %0, t; }" : "=r"(a) : "l"(p));
    return a;
}
__device__ __forceinline__ void cp16(uint32_t dst, const void* src) {
    asm volatile("cp.async.cg.shared.global [%0], [%1], 16;" :: "r"(dst), "l"(src));
}
#define CP_COMMIT() asm volatile("cp.async.commit_group;" ::: "memory")
#define CP_WAIT(n)  asm volatile("cp.async.wait_group %0;" :: "n"(n) : "memory")

__device__ __forceinline__ void issue_tile(uint32_t sdst,
                                           const __nv_bfloat16* __restrict__ base,
                                           size_t row0, int stride, int koff, int tid) {
#pragma unroll
    for (int t = 0; t < 4; t++) {
        const int i = t * 256 + tid;
        const int rr = i >> 3, c16 = i & 7;
        cp16(sdst + (uint32_t)(rr * LDS + c16 * 8) * 2,
             base + (row0 + rr) * (size_t)stride + koff + c16 * 8);
    }
}

// Prefetch a 128x128 fp32 adj tile into smem (row stride ADJ_LDS floats).
__device__ __forceinline__ void adj_issue(uint32_t sdst, const float* __restrict__ adjb,
                                          int r0, int c0, int tid) {
#pragma unroll
    for (int t = 0; t < 16; t++) {
        const int i = t * 256 + tid;
        const int rr = i >> 5, cc = i & 31;
        cp16(sdst + (uint32_t)(rr * ADJ_LDS + cc * 4) * 4,
             adjb + (size_t)(r0 + rr) * N + c0 + cc * 4);
    }
    CP_COMMIT();
}

// ---------------------------------------------------------------------------
// Fragment loaders for the m16n8k16 layout.
__device__ __forceinline__ void lda_frag(uint32_t sA, int wr, int mi, int kk, int lane,
                                         uint32_t (&a)[4]) {
    const uint32_t addr = sA +
        ((wr * 64 + mi * 16 + (lane & 15)) * LDS + kk * 16 + ((lane >> 4) << 3)) * 2;
    asm volatile("ldmatrix.sync.aligned.m8n8.x4.shared.b16 {%0,%1,%2,%3}, [%4];"
                 : "=r"(a[0]), "=r"(a[1]), "=r"(a[2]), "=r"(a[3]) : "r"(addr));
}
// x4 B loader: two adjacent n8 fragments in one instruction.
__device__ __forceinline__ void ldb_frag4(uint32_t sB, int wc, int p, int kk, int lane,
                                          uint32_t (&b0)[2], uint32_t (&b1)[2]) {
    const uint32_t addr = sB +
        ((wc * 32 + (2 * p + ((lane >> 4) & 1)) * 8 + (lane & 7)) * LDS +
         kk * 16 + (((lane >> 3) & 1) << 3)) * 2;
    asm volatile("ldmatrix.sync.aligned.m8n8.x4.shared.b16 {%0,%1,%2,%3}, [%4];"
                 : "=r"(b0[0]), "=r"(b0[1]), "=r"(b1[0]), "=r"(b1[1]) : "r"(addr));
}
__device__ __forceinline__ void mma16816(float (&d)[4], const uint32_t (&a)[4],
                                         const uint32_t (&b)[2]) {
    asm volatile(
        "mma.sync.aligned.m16n8k16.row.col.f32.bf16.bf16.f32 "
        "{%0,%1,%2,%3}, {%4,%5,%6,%7}, {%8,%9}, {%0,%1,%2,%3};"
        : "+f"(d[0]), "+f"(d[1]), "+f"(d[2]), "+f"(d[3])
        : "r"(a[0]), "r"(a[1]), "r"(a[2]), "r"(a[3]), "r"(b[0]), "r"(b[1]));
}

// Three-term split MMA over one 64-wide K chunk with fragment reuse:
// acc += Ah.Bh + Ah.Bl + Al.Bh
__device__ __forceinline__ void mma_tri(uint32_t sAh, uint32_t sAl,
                                        uint32_t sBh, uint32_t sBl,
                                        int wr, int wc, int lane,
                                        float (&acc)[4][4][4]) {
#pragma unroll
    for (int kk = 0; kk < 4; kk++) {
        uint32_t ah[4][4], al[4][4], bh[4][2], bl[4][2];
#pragma unroll
        for (int mi = 0; mi < 4; mi++) lda_frag(sAh, wr, mi, kk, lane, ah[mi]);
#pragma unroll
        for (int p = 0; p < 2; p++) ldb_frag4(sBh, wc, p, kk, lane, bh[2 * p], bh[2 * p + 1]);
#pragma unroll
        for (int mi = 0; mi < 4; mi++)
#pragma unroll
            for (int ni = 0; ni < 4; ni++) mma16816(acc[mi][ni], ah[mi], bh[ni]);
#pragma unroll
        for (int p = 0; p < 2; p++) ldb_frag4(sBl, wc, p, kk, lane, bl[2 * p], bl[2 * p + 1]);
#pragma unroll
        for (int mi = 0; mi < 4; mi++)
#pragma unroll
            for (int ni = 0; ni < 4; ni++) mma16816(acc[mi][ni], ah[mi], bl[ni]);
#pragma unroll
        for (int mi = 0; mi < 4; mi++) lda_frag(sAl, wr, mi, kk, lane, al[mi]);
#pragma unroll
        for (int mi = 0; mi < 4; mi++)
#pragma unroll
            for (int ni = 0; ni < 4; ni++) mma16816(acc[mi][ni], al[mi], bh[ni]);
    }
}

__device__ __forceinline__ void acc_to_smem(float* sD, int wr, int wc, int lane,
                                            const float (&acc)[4][4][4], bool do_exp) {
#pragma unroll
    for (int mi = 0; mi < 4; mi++)
#pragma unroll
        for (int ni = 0; ni < 4; ni++) {
            const int row = wr * 64 + mi * 16 + (lane >> 2);
            const int col = wc * 32 + ni * 8 + (lane & 3) * 2;
            if (do_exp) {
                sD[row * 129 + col]           = __expf(acc[mi][ni][0]);
                sD[row * 129 + col + 1]       = __expf(acc[mi][ni][1]);
                sD[(row + 8) * 129 + col]     = __expf(acc[mi][ni][2]);
                sD[(row + 8) * 129 + col + 1] = __expf(acc[mi][ni][3]);
            } else {
                sD[row * 129 + col]           = acc[mi][ni][0];
                sD[row * 129 + col + 1]       = acc[mi][ni][1];
                sD[(row + 8) * 129 + col]     = acc[mi][ni][2];
                sD[(row + 8) * 129 + col + 1] = acc[mi][ni][3];
            }
        }
}

// ---------------------------------------------------------------------------
// Wt = W^T and M = A + A^T (both 128x128, tiny).
__global__ void prep_wm_k(const float* __restrict__ W, const float* __restrict__ A) {
    __shared__ float tw[32][33];
    __shared__ float ta[32][33];
    const int bx = blockIdx.x, by = blockIdx.y;
    const int x = bx * 32 + threadIdx.x;
    const int y0 = by * 32;
    for (int i = threadIdx.y; i < 32; i += 8) {
        tw[i][threadIdx.x] = W[(y0 + i) * D + x];
        ta[i][threadIdx.x] = A[(bx * 32 + i) * D + by * 32 + threadIdx.x];
    }
    __syncthreads();
    const int xo = by * 32 + threadIdx.x;
    const int yo0 = bx * 32;
    for (int i = threadIdx.y; i < 32; i += 8) {
        g_Wt[(yo0 + i) * D + xo] = tw[threadIdx.x][i];
        // M[y0+i][x] = A[y0+i][x] + A[x][y0+i]
        g_M[(y0 + i) * D + x] = A[(y0 + i) * D + x] + ta[threadIdx.x][i];
    }
}

// ---------------------------------------------------------------------------
// Fused front end: h = x.Wt + b; G = h.M; bf16 splits of both; hT fp32.
__global__ void __launch_bounds__(256) fused_h_k(const float* __restrict__ x,
                                                 const float* __restrict__ bias) {
    __shared__ float sM[32][D + 1];
    __shared__ float sX[32][33];
    __shared__ float sH[32][D + 1];
    const int row0 = blockIdx.x * 32;
    const int b = row0 >> 11;
    const int n0 = row0 & (N - 1);
    const int tid = threadIdx.x;
    const int tc = tid & 15, tr = tid >> 4;
    float acc[2][8];

#pragma unroll
    for (int a = 0; a < 2; a++)
#pragma unroll
        for (int c = 0; c < 8; c++) acc[a][c] = 0.0f;
    for (int k0 = 0; k0 < D; k0 += 32) {
#pragma unroll
        for (int i = tid; i < 32 * D; i += 256)
            sM[i >> 7][i & 127] = g_Wt[(k0 + (i >> 7)) * D + (i & 127)];
#pragma unroll
        for (int i = tid; i < 1024; i += 256)
            sX[i >> 5][i & 31] = x[(size_t)(row0 + (i >> 5)) * D + k0 + (i & 31)];
        __syncthreads();
#pragma unroll 8
        for (int kk = 0; kk < 32; kk++) {
            float x0 = sX[tr][kk], x1 = sX[tr + 16][kk];
#pragma unroll
            for (int c = 0; c < 8; c++) {
                float mv = sM[kk][tc + c * 16];
                acc[0][c] += x0 * mv;
                acc[1][c] += x1 * mv;
            }
        }
        __syncthreads();
    }
#pragma unroll
    for (int a = 0; a < 2; a++)
#pragma unroll
        for (int c = 0; c < 8; c++) {
            const int r = tr + a * 16, col = tc + c * 16;
            const float v = acc[a][c] + bias[col];
            sH[r][col] = v;
            const __nv_bfloat16 hi = __float2bfloat16_rn(v);
            const size_t o = (size_t)(row0 + r) * D + col;
            g_hh[o] = hi;
            g_hl[o] = __float2bfloat16_rn(v - __bfloat162float(hi));
        }
    __syncthreads();

#pragma unroll
    for (int a = 0; a < 2; a++)
#pragma unroll
        for (int c = 0; c < 8; c++) acc[a][c] = 0.0f;
    for (int k0 = 0; k0 < D; k0 += 32) {
#pragma unroll
        for (int i = tid; i < 32 * D; i += 256)
            sM[i >> 7][i & 127] = g_M[(k0 + (i >> 7)) * D + (i & 127)];
        __syncthreads();
#pragma unroll 8
        for (int kk = 0; kk < 32; kk++) {
            float x0 = sH[tr][k0 + kk], x1 = sH[tr + 16][k0 + kk];
#pragma unroll
            for (int c = 0; c < 8; c++) {
                float mv = sM[kk][tc + c * 16];
                acc[0][c] += x0 * mv;
                acc[1][c] += x1 * mv;
            }
        }
        __syncthreads();
    }
#pragma unroll
    for (int a = 0; a < 2; a++)
#pragma unroll
        for (int c = 0; c < 8; c++) {
            const int r = tr + a * 16, col = tc + c * 16;
            const float v = acc[a][c];
            const __nv_bfloat16 hi = __float2bfloat16_rn(v);
            const size_t o = (size_t)(row0 + r) * D + col;
            g_Gh[o] = hi;
            g_Gl[o] = __float2bfloat16_rn(v - __bfloat162float(hi));
        }

    const int nn = tid & 31, d0 = tid >> 5;
#pragma unroll
    for (int dp = 0; dp < 16; dp++) {
        const int d = dp * 8 + d0;
        g_hT[((size_t)b * D + d) * N + n0 + nn] = sH[nn][d];
    }
}

// ---------------------------------------------------------------------------
// Esym = G.h^T (K=128, 2 chunks) over upper-triangle tile pairs.
// adj tiles prefetched concurrently; exp fused into the accumulator spill.
__device__ __forceinline__ void esym_issue(int q, int stage, uint32_t sbase,
                                           size_t arow, size_t brow, int tid) {
    const int koff = q * 64;
    const uint32_t s = sbase + (uint32_t)stage * STAGE_B;
    issue_tile(s,              g_Gh, arow, D, koff, tid);
    issue_tile(s + TILE_B,     g_Gl, arow, D, koff, tid);
    issue_tile(s + 2 * TILE_B, g_hh, brow, D, koff, tid);
    issue_tile(s + 3 * TILE_B, g_hl, brow, D, koff, tid);
    CP_COMMIT();
}

__global__ void __launch_bounds__(256) esym_k(const float* __restrict__ adj) {
    extern __shared__ char sm[];
    const uint32_t sbase = smem_u32(sm);
    const int tid = threadIdx.x, wid = tid >> 5, lane = tid & 31;
    const int wr = wid >> 2, wc = wid & 3;

    int t = blockIdx.x % 136;
    const int b = blockIdx.x / 136;
    int tj = 0;
    while (t >= 16 - tj) { t -= 16 - tj; tj++; }
    const int tk = tj + t;
    const int j0 = tj * 128, k0 = tk * 128;
    const size_t arow = (size_t)b * N + j0, brow = (size_t)b * N + k0;
    const float* adjb = adj + (size_t)b * N * N;

    float acc[4][4][4];
#pragma unroll
    for (int mi = 0; mi < 4; mi++)
#pragma unroll
        for (int ni = 0; ni < 4; ni++)
#pragma unroll
            for (int q = 0; q < 4; q++) acc[mi][ni][q] = 0.0f;

    esym_issue(0, 0, sbase, arow, brow, tid);      // group 1 -> st0
    esym_issue(1, 1, sbase, arow, brow, tid);      // group 2 -> st1
    adj_issue(sbase + 2 * STAGE_B, adjb, j0, k0, tid);  // group 3 (adj1) -> st2

    CP_WAIT(2); __syncthreads();                   // chunk0 ready
    mma_tri(sbase, sbase + TILE_B, sbase + 2 * TILE_B, sbase + 3 * TILE_B,
            wr, wc, lane, acc);
    __syncthreads();                               // st0 fully consumed
    if (tj != tk) {
        adj_issue(sbase, adjb, k0, j0, tid);       // group 4 (adj2) -> st0
        CP_WAIT(2);                                // chunk1 done (adj1, adj2 pending)
    } else {
        CP_WAIT(1);                                // chunk1 done (adj1 pending)
    }
    __syncthreads();
    {
        const uint32_t s = sbase + STAGE_B;
        mma_tri(s, s + TILE_B, s + 2 * TILE_B, s + 3 * TILE_B, wr, wc, lane, acc);
    }
    CP_WAIT(0);
    __syncthreads();

    float* sD  = (float*)(sm + STAGE_B);           // st1 (chunk1 consumed)
    float* sA1 = (float*)(sm + 2 * STAGE_B);       // adj[j0..][k0..]
    float* sA2 = (float*)sm;                       // adj[k0..][j0..]
    acc_to_smem(sD, wr, wc, lane, acc, true);
    __syncthreads();

    const int c = tid & 127, p = tid >> 7;
    {
        float csum = 0.0f;
        const size_t ub = (size_t)b * N * N + (size_t)j0 * N + k0;
#pragma unroll 8
        for (int it = 0; it < 64; it++) {
            const int r = it * 2 + p;
            const float v = (sA1[r * ADJ_LDS + c] > 0.0f) ? sD[r * 129 + c] : 0.0f;
            const __nv_bfloat16 vh = __float2bfloat16_rn(v);
            g_Uh[ub + (size_t)r * N + c] = vh;
            g_Ul[ub + (size_t)r * N + c] = __float2bfloat16_rn(v - __bfloat162float(vh));
            csum += v;
        }
        g_part[((size_t)b * N + k0 + c) * 32 + tj * 2 + p] = csum;
    }
    if (tj != tk) {
        float csum = 0.0f;
        const size_t ub = (size_t)b * N * N + (size_t)k0 * N + j0;
#pragma unroll 8
        for (int it = 0; it < 64; it++) {
            const int r = it * 2 + p;
            const float v = (sA2[r * ADJ_LDS + c] > 0.0f) ? sD[c * 129 + r] : 0.0f;
            const __nv_bfloat16 vh = __float2bfloat16_rn(v);
            g_Uh[ub + (size_t)r * N + c] = vh;
            g_Ul[ub + (size_t)r * N + c] = __float2bfloat16_rn(v - __bfloat162float(vh));
            csum += v;
        }
        g_part[((size_t)b * N + j0 + c) * 32 + tk * 2 + p] = csum;
    }
}

// ---------------------------------------------------------------------------
// Per block: reduce is[] for 256 columns, then scale 32 d-rows of hT; splits.
__global__ void __launch_bounds__(256) scale_is_k() {
    __shared__ float s_is[256];
    const int bx = blockIdx.x;
    const int b = bx >> 5;
    const int rem = bx & 31;
    const int j0 = (rem & 7) * 256;
    const int d0 = (rem >> 3) * 32;
    const int tid = threadIdx.x;

    {
        const float4* p = (const float4*)(g_part + ((size_t)b * N + j0 + tid) * 32);
        float s = 0.0f;
#pragma unroll
        for (int q = 0; q < 8; q++) {
            const float4 v = p[q];
            s += (v.x + v.y) + (v.z + v.w);
        }
        s_is[tid] = 1.0f / s;
    }
    __syncthreads();

    const int jq = tid & 63, dr0 = tid >> 6;
    const float4 sv = ((const float4*)s_is)[jq];
#pragma unroll
    for (int it = 0; it < 8; it++) {
        const int d = d0 + it * 4 + dr0;
        const size_t o4 = (((size_t)b * D + d) * N + j0) / 4 + jq;
        const float4 hv = ((const float4*)g_hT)[o4];
        const float v0 = hv.x * sv.x, v1 = hv.y * sv.y, v2 = hv.z * sv.z, v3 = hv.w * sv.w;
        const __nv_bfloat16 h0 = __float2bfloat16_rn(v0);
        const __nv_bfloat16 h1 = __float2bfloat16_rn(v1);
        const __nv_bfloat16 h2 = __float2bfloat16_rn(v2);
        const __nv_bfloat16 h3 = __float2bfloat16_rn(v3);
        const __nv_bfloat16 l0 = __float2bfloat16_rn(v0 - __bfloat162float(h0));
        const __nv_bfloat16 l1 = __float2bfloat16_rn(v1 - __bfloat162float(h1));
        const __nv_bfloat16 l2 = __float2bfloat16_rn(v2 - __bfloat162float(h2));
        const __nv_bfloat16 l3 = __float2bfloat16_rn(v3 - __bfloat162float(h3));
        uint2 ph, pl;
        asm("mov.b32 %0, {%1, %2};" : "=r"(ph.x) : "h"(*(const uint16_t*)&h0), "h"(*(const uint16_t*)&h1));
        asm("mov.b32 %0, {%1, %2};" : "=r"(ph.y) : "h"(*(const uint16_t*)&h2), "h"(*(const uint16_t*)&h3));
        asm("mov.b32 %0, {%1, %2};" : "=r"(pl.x) : "h"(*(const uint16_t*)&l0), "h"(*(const uint16_t*)&l1));
        asm("mov.b32 %0, {%1, %2};" : "=r"(pl.y) : "h"(*(const uint16_t*)&l2), "h"(*(const uint16_t*)&l3));
        ((uint2*)g_sh)[o4] = ph;
        ((uint2*)g_sl)[o4] = pl;
    }
}

// ---------------------------------------------------------------------------
// hp+gate fused: 32 chunks x 3 fused split terms; depth-2 prefetch on 3 stages.
__device__ __forceinline__ void hp_issue(int c, int stage, uint32_t sbase,
                                         size_t arow, size_t brow, int tid) {
    const int koff = c * 64;
    const uint32_t s = sbase + (uint32_t)stage * STAGE_B;
    issue_tile(s,              g_Uh, arow, N, koff, tid);
    issue_tile(s + TILE_B,     g_Ul, arow, N, koff, tid);
    issue_tile(s + 2 * TILE_B, g_sh, brow, N, koff, tid);
    issue_tile(s + 3 * TILE_B, g_sl, brow, N, koff, tid);
    CP_COMMIT();
}

__global__ void __launch_bounds__(256) hp_k(
    const float* __restrict__ x, const float* __restrict__ gw,
    const float* __restrict__ gb, float* __restrict__ out) {
    extern __shared__ char sm[];
    const uint32_t sbase = smem_u32(sm);
    const int tid = threadIdx.x, wid = tid >> 5, lane = tid & 31;
    const int wr = wid >> 2, wc = wid & 3;
    const int b = blockIdx.y;
    const int i0 = blockIdx.x * 128;
    const size_t arow = (size_t)b * N + i0;
    const size_t brow = (size_t)b * D;

    float acc[4][4][4];
#pragma unroll
    for (int mi = 0; mi < 4; mi++)
#pragma unroll
        for (int ni = 0; ni < 4; ni++)
#pragma unroll
            for (int q = 0; q < 4; q++) acc[mi][ni][q] = 0.0f;

    hp_issue(0, 0, sbase, arow, brow, tid);
    hp_issue(1, 1, sbase, arow, brow, tid);
#pragma unroll 1
    for (int c = 0; c < 32; c++) {
        if (c < 31) CP_WAIT(1);
        else CP_WAIT(0);
        __syncthreads();
        if (c + 2 < 32) hp_issue(c + 2, (c + 2) % 3, sbase, arow, brow, tid);
        const uint32_t s = sbase + (uint32_t)(c % 3) * STAGE_B;
        mma_tri(s, s + TILE_B, s + 2 * TILE_B, s + 3 * TILE_B, wr, wc, lane, acc);
    }
    __syncthreads();

    float* sD = (float*)sm;
    acc_to_smem(sD, wr, wc, lane, acc, false);
    __syncthreads();

    const float4 g1 = ((const float4*)gw)[lane];
    const float4 g2 = ((const float4*)(gw + D))[lane];
    const float gbv = gb[0];
#pragma unroll 1
    for (int rr = wid; rr < 128; rr += 8) {
        const size_t row = (size_t)b * N + i0 + rr;
        const float4 xv = ((const float4*)(x + row * D))[lane];
        float4 hv;
        hv.x = fmaxf(sD[rr * 129 + lane * 4 + 0], 0.0f);
        hv.y = fmaxf(sD[rr * 129 + lane * 4 + 1], 0.0f);
        hv.z = fmaxf(sD[rr * 129 + lane * 4 + 2], 0.0f);
        hv.w = fmaxf(sD[rr * 129 + lane * 4 + 3], 0.0f);
        float p = xv.x * g1.x + xv.y * g1.y + xv.z * g1.z + xv.w * g1.w
                + hv.x * g2.x + hv.y * g2.y + hv.z * g2.z + hv.w * g2.w;
#pragma unroll
        for (int o = 16; o > 0; o >>= 1) p += __shfl_xor_sync(0xffffffffu, p, o);
        const float cf = 1.0f / (1.0f + __expf(-(p + gbv)));
        const float df = 1.0f - cf;
        float4 o4;
        o4.x = cf * xv.x + df * hv.x;
        o4.y = cf * xv.y + df * hv.y;
        o4.z = cf * xv.z + df * hv.z;
        o4.w = cf * xv.w + df * hv.w;
        ((float4*)(out + row * D))[lane] = o4;
    }
}

// ---------------------------------------------------------------------------
extern "C" void kernel_launch(void* const* d_in, const int* in_sizes, int n_in,
                              void* d_out, int out_size) {
    const float* x   = (const float*)d_in[0];
    const float* adj = (const float*)d_in[1];
    const float* W_w = (const float*)d_in[2];
    const float* W_b = (const float*)d_in[3];
    const float* A   = (const float*)d_in[4];
    const float* gw  = (const float*)d_in[5];
    const float* gb  = (const float*)d_in[6];
    float* out = (float*)d_out;

    static bool attr_done = false;
    if (!attr_done) {
        cudaFuncSetAttribute(esym_k, cudaFuncAttributeMaxDynamicSharedMemorySize, SMEM_MMA);
        cudaFuncSetAttribute(hp_k,   cudaFuncAttributeMaxDynamicSharedMemorySize, SMEM_MMA);
        attr_done = true;
    }

    prep_wm_k<<<dim3(4, 4), dim3(32, 8)>>>(W_w, A);
    fused_h_k<<<(B * N) / 32, 256>>>(x, W_b);
    esym_k<<<B * 136, 256, SMEM_MMA>>>(adj);
    scale_is_k<<<B * 32, 256>>>();
    hp_k<<<dim3(N / 128, B), 256, SMEM_MMA>>>(x, gw, gb, out);
}